// round 6
// baseline (speedup 1.0000x reference)
#include <cuda_runtime.h>
#include <cstdint>

#define B_IMG 4096

// slots: 0:x 1..5:w1..w5 6:wl 7..11:b1..b5 12:bl 13..17:act1..act5
__device__ unsigned g_maxbits[18];
__device__ __align__(16) float g_skip1[B_IMG * 64];
__device__ __align__(16) float g_act1 [B_IMG * 8192];   // [b][256 pix][32 ch]
__device__ __align__(16) float g_act2 [B_IMG * 4096];   // [b][64 pix][64 ch]
__device__ __align__(16) float g_act3 [B_IMG * 1024];   // [b][64 pix][16 ch]
__device__ __align__(16) float g_skip2[B_IMG * 1024];   // [b][16 pix][64 ch]
__device__ __align__(16) float g_act4 [B_IMG * 256];    // [b][16 pix][16 ch]
__device__ __align__(16) float g_act5 [B_IMG * 1024];   // [b][16 pix][64 ch]

__device__ __forceinline__ float ldmax(int i) { return __uint_as_float(g_maxbits[i]); }
__device__ __forceinline__ void amaxf(int i, float v) {
    atomicMax(&g_maxbits[i], __float_as_uint(v));
}
__device__ __forceinline__ float warpmax(float v) {
    #pragma unroll
    for (int o = 16; o > 0; o >>= 1) v = fmaxf(v, __shfl_xor_sync(0xffffffffu, v, o));
    return v;
}
__device__ __forceinline__ float quantv(float x, float s, float lo, float hi) {
    if (s <= 0.f) return 0.f;
    return fminf(fmaxf(rintf(x * s), lo), hi) / s;
}
__device__ __forceinline__ float mkscale(int slot, float maxv) {
    float m = ldmax(slot);
    return m > 0.f ? maxv / m : 0.f;
}

__global__ void k_reset() { if (threadIdx.x < 18) g_maxbits[threadIdx.x] = 0u; }

__global__ void __launch_bounds__(256) k_xmax(const float4* __restrict__ x) {
    const int n4 = B_IMG * 1024 / 4;
    float m = 0.f;
    for (int i = blockIdx.x * blockDim.x + threadIdx.x; i < n4; i += gridDim.x * blockDim.x) {
        float4 v = x[i];
        m = fmaxf(m, fmaxf(fmaxf(fabsf(v.x), fabsf(v.y)), fmaxf(fabsf(v.z), fabsf(v.w))));
    }
    m = warpmax(m);
    if ((threadIdx.x & 31) == 0) amaxf(0, m);
}

__global__ void __launch_bounds__(256) k_wmax(
    const float* w1, const float* w2, const float* w3, const float* w4, const float* w5,
    const float* wl, const float* b1, const float* b2, const float* b3, const float* b4,
    const float* b5, const float* bl)
{
    __shared__ float red[8];
    const float* ptrs[12] = {w1, w2, w3, w4, w5, wl, b1, b2, b3, b4, b5, bl};
    const int sizes[12]   = {288, 18432, 1024, 2304, 1024, 640, 32, 64, 16, 16, 64, 10};
    const float* p = ptrs[blockIdx.x];
    int n = sizes[blockIdx.x];
    float m = 0.f;
    for (int i = threadIdx.x; i < n; i += 256) m = fmaxf(m, fabsf(p[i]));
    m = warpmax(m);
    if ((threadIdx.x & 31) == 0) red[threadIdx.x >> 5] = m;
    __syncthreads();
    if (threadIdx.x == 0) {
        float mm = red[0];
        #pragma unroll
        for (int i = 1; i < 8; i++) mm = fmaxf(mm, red[i]);
        atomicMax(&g_maxbits[blockIdx.x + 1], __float_as_uint(mm));
    }
}

// Stage 1: quant(x) -> maxpool(5,4,2)=skip1 ; conv1(1->32,3x3,s2)+b -> clip -> act1
__global__ void __launch_bounds__(256) k_stage1(
    const float* __restrict__ x, const float* __restrict__ w1g, const float* __restrict__ b1g)
{
    __shared__ __align__(16) float xs[32 * 33];
    __shared__ __align__(16) float w1s[9 * 32];
    __shared__ __align__(16) float b1s[32];
    const int b = blockIdx.x, t = threadIdx.x;
    const float sx = mkscale(0, 127.f);

    float4 v = ((const float4*)(x + b * 1024))[t];
    {
        int h = t >> 3, w0 = (t & 7) * 4;
        xs[h * 33 + w0 + 0] = quantv(v.x, sx, -127.f, 127.f);
        xs[h * 33 + w0 + 1] = quantv(v.y, sx, -127.f, 127.f);
        xs[h * 33 + w0 + 2] = quantv(v.z, sx, -127.f, 127.f);
        xs[h * 33 + w0 + 3] = quantv(v.w, sx, -127.f, 127.f);
    }
    {
        float sw = mkscale(1, 127.f);
        for (int i = t; i < 288; i += 256) {           // FIX: strided (288 > blockDim)
            int oc = i / 9, tap = i % 9;
            w1s[tap * 32 + oc] = quantv(w1g[i], sw, -127.f, 127.f);
        }
    }
    if (t < 32) b1s[t] = quantv(b1g[t], mkscale(7, 32767.f), -32767.f, 32767.f);
    __syncthreads();

    if (t < 64) {  // maxpool 5/4/2 on quantized x
        int oh = t >> 3, ow = t & 7;
        float m = -3.4e38f;
        int h0 = max(0, 4 * oh - 2), h1 = min(31, 4 * oh + 2);
        int w0 = max(0, 4 * ow - 2), w1i = min(31, 4 * ow + 2);
        for (int ih = h0; ih <= h1; ih++)
            for (int iw = w0; iw <= w1i; iw++)
                m = fmaxf(m, xs[ih * 33 + iw]);
        g_skip1[b * 64 + t] = m;
    }

    int oh = t >> 4, ow = t & 15;
    float acc[32];
    #pragma unroll
    for (int o = 0; o < 32; o++) acc[o] = 0.f;
    for (int r = 0; r < 3; r++) {
        int ih = 2 * oh - 1 + r;
        if ((unsigned)ih >= 32u) continue;
        for (int s = 0; s < 3; s++) {
            int iw = 2 * ow - 1 + s;
            if ((unsigned)iw >= 32u) continue;
            float a = xs[ih * 33 + iw];
            const float* wrow = &w1s[(r * 3 + s) * 32];
            #pragma unroll
            for (int o4 = 0; o4 < 8; o4++) {
                float4 wv = ((const float4*)wrow)[o4];
                acc[o4*4+0] += a * wv.x; acc[o4*4+1] += a * wv.y;
                acc[o4*4+2] += a * wv.z; acc[o4*4+3] += a * wv.w;
            }
        }
    }
    float lm = 0.f;
    float* outp = g_act1 + (b * 256 + t) * 32;
    #pragma unroll
    for (int o4 = 0; o4 < 8; o4++) {
        float4 c;
        c.x = fminf(fmaxf(acc[o4*4+0] + b1s[o4*4+0], 0.f), 10.f);
        c.y = fminf(fmaxf(acc[o4*4+1] + b1s[o4*4+1], 0.f), 10.f);
        c.z = fminf(fmaxf(acc[o4*4+2] + b1s[o4*4+2], 0.f), 10.f);
        c.w = fminf(fmaxf(acc[o4*4+3] + b1s[o4*4+3], 0.f), 10.f);
        lm = fmaxf(lm, fmaxf(fmaxf(c.x, c.y), fmaxf(c.z, c.w)));
        ((float4*)outp)[o4] = c;
    }
    lm = warpmax(lm);
    if ((t & 31) == 0) amaxf(13, lm);
}

// Stage 2: conv2(32->64,3x3,s2) exact int8 dp4a ; + b2 + skip1 -> clip -> act2
__global__ void __launch_bounds__(128) k_stage2(
    const float* __restrict__ w2g, const float* __restrict__ b2g)
{
    __shared__ __align__(16) int ap[18 * 145];
    __shared__ __align__(16) int wp[9 * 8 * 64];
    const int b = blockIdx.x, t = threadIdx.x;
    const float m1 = ldmax(13);
    const float s1 = m1 > 0.f ? 127.f / m1 : 0.f;
    const float sw = mkscale(2, 127.f);

    for (int i = t; i < 18 * 145; i += 128) ap[i] = 0;
    if (t < 64) {
        int oc = t;
        for (int ic4 = 0; ic4 < 8; ic4++)
            for (int tap = 0; tap < 9; tap++) {
                int p = 0;
                #pragma unroll
                for (int j = 0; j < 4; j++) {
                    int c = __float2int_rn(w2g[oc * 288 + (ic4*4+j) * 9 + tap] * sw);
                    c = max(-127, min(127, c));
                    p |= (c & 255) << (8 * j);
                }
                wp[(tap * 8 + ic4) * 64 + oc] = p;
            }
    }
    __syncthreads();

    const float4* ag = (const float4*)(g_act1 + b * 8192);
    for (int i = 0; i < 16; i++) {
        int idx = t + 128 * i;
        float4 v = ag[idx];
        int ic4 = idx & 7, pix = idx >> 3;
        int ih = pix >> 4, iw = pix & 15;
        int c0 = max(0, min(127, __float2int_rn(v.x * s1)));
        int c1 = max(0, min(127, __float2int_rn(v.y * s1)));
        int c2 = max(0, min(127, __float2int_rn(v.z * s1)));
        int c3 = max(0, min(127, __float2int_rn(v.w * s1)));
        ap[(ih+1) * 145 + (iw+1) * 8 + ic4] = c0 | (c1<<8) | (c2<<16) | (c3<<24);
    }
    __syncthreads();

    const int posg = t & 15, ocg = t >> 4;       // 16 pixel-groups x 8 oc-groups
    const int oh = posg >> 1, ow0 = (posg & 1) * 4;
    int acc[4][8];
    #pragma unroll
    for (int j = 0; j < 4; j++)
        #pragma unroll
        for (int k = 0; k < 8; k++) acc[j][k] = 0;

    for (int r = 0; r < 3; r++)
        for (int s = 0; s < 3; s++) {
            const int base = (2*oh + r) * 145 + (2*ow0 + s) * 8;
            const int* wrow = &wp[(r*3+s) * 8 * 64 + ocg * 8];
            #pragma unroll
            for (int ic4 = 0; ic4 < 8; ic4++) {
                int a0 = ap[base + ic4], a1 = ap[base + 16 + ic4];
                int a2 = ap[base + 32 + ic4], a3 = ap[base + 48 + ic4];
                int4 wv0 = *(const int4*)(wrow + ic4 * 64);
                int4 wv1 = *(const int4*)(wrow + ic4 * 64 + 4);
                int wv[8] = {wv0.x, wv0.y, wv0.z, wv0.w, wv1.x, wv1.y, wv1.z, wv1.w};
                #pragma unroll
                for (int k = 0; k < 8; k++) {
                    acc[0][k] = __dp4a(a0, wv[k], acc[0][k]);
                    acc[1][k] = __dp4a(a1, wv[k], acc[1][k]);
                    acc[2][k] = __dp4a(a2, wv[k], acc[2][k]);
                    acc[3][k] = __dp4a(a3, wv[k], acc[3][k]);
                }
            }
        }

    const float inv = (s1 > 0.f && sw > 0.f) ? 1.f / (s1 * sw) : 0.f;
    const float sb = mkscale(8, 32767.f);
    float bq[8];
    #pragma unroll
    for (int k = 0; k < 8; k++) bq[k] = quantv(b2g[ocg*8+k], sb, -32767.f, 32767.f);

    float lm = 0.f;
    #pragma unroll
    for (int j = 0; j < 4; j++) {
        float sk = g_skip1[b * 64 + posg * 4 + j];
        float o[8];
        #pragma unroll
        for (int k = 0; k < 8; k++) {
            float y = (float)acc[j][k] * inv + bq[k] + sk;
            o[k] = fminf(fmaxf(y, 0.f), 10.f);
            lm = fmaxf(lm, o[k]);
        }
        float* dst = g_act2 + (b * 64 + posg * 4 + j) * 64 + ocg * 8;
        ((float4*)dst)[0] = make_float4(o[0], o[1], o[2], o[3]);
        ((float4*)dst)[1] = make_float4(o[4], o[5], o[6], o[7]);
    }
    lm = warpmax(lm);
    if ((t & 31) == 0) amaxf(14, lm);
}

// Stage 3: quant(act2) -> maxpool(3,2,1)=skip2 ; conv3(64->16,1x1) -> clip -> act3
__global__ void __launch_bounds__(256) k_stage3(
    const float* __restrict__ w3g, const float* __restrict__ b3g)
{
    __shared__ __align__(16) float c2q[64 * 65];
    __shared__ __align__(16) float w3s[64 * 16];
    __shared__ __align__(16) float b3s[16];
    const int b = blockIdx.x, t = threadIdx.x;
    const float m2 = ldmax(14);
    const float s2 = m2 > 0.f ? 127.f / m2 : 0.f;

    const float* a2 = g_act2 + b * 4096;
    for (int i = 0; i < 16; i++) {
        int idx = t + 256 * i;
        c2q[(idx >> 6) * 65 + (idx & 63)] = quantv(a2[idx], s2, 0.f, 127.f);
    }
    {
        float sw = mkscale(3, 127.f);
        for (int i = t; i < 1024; i += 256)
            w3s[(i & 63) * 16 + (i >> 6)] = quantv(w3g[i], sw, -127.f, 127.f);
    }
    if (t < 16) b3s[t] = quantv(b3g[t], mkscale(9, 32767.f), -32767.f, 32767.f);
    __syncthreads();

    {
        int pos = t >> 2, ocq = t & 3;
        float4 acc = make_float4(0.f, 0.f, 0.f, 0.f);
        for (int ic = 0; ic < 64; ic++) {
            float a = c2q[pos * 65 + ic];
            float4 wv = *(const float4*)&w3s[ic * 16 + ocq * 4];
            acc.x += a*wv.x; acc.y += a*wv.y; acc.z += a*wv.z; acc.w += a*wv.w;
        }
        float4 c;
        c.x = fminf(fmaxf(acc.x + b3s[ocq*4+0], 0.f), 10.f);
        c.y = fminf(fmaxf(acc.y + b3s[ocq*4+1], 0.f), 10.f);
        c.z = fminf(fmaxf(acc.z + b3s[ocq*4+2], 0.f), 10.f);
        c.w = fminf(fmaxf(acc.w + b3s[ocq*4+3], 0.f), 10.f);
        *(float4*)(g_act3 + (b * 64 + pos) * 16 + ocq * 4) = c;
        float lm = warpmax(fmaxf(fmaxf(c.x, c.y), fmaxf(c.z, c.w)));
        if ((t & 31) == 0) amaxf(15, lm);
    }

    for (int i = 0; i < 4; i++) {
        int idx = t + 256 * i;
        int opix = idx >> 6, ch = idx & 63;
        int oh = opix >> 2, ow = opix & 3;
        float m = -3.4e38f;
        int h0 = max(0, 2*oh-1), h1 = min(7, 2*oh+1);
        int w0 = max(0, 2*ow-1), w1i = min(7, 2*ow+1);
        for (int ih = h0; ih <= h1; ih++)
            for (int iw = w0; iw <= w1i; iw++)
                m = fmaxf(m, c2q[(ih * 8 + iw) * 65 + ch]);
        g_skip2[(b * 16 + opix) * 64 + ch] = m;
    }
}

// Stage 4: conv4(16->16,3x3,s2) -> clip -> act4 ; 4 images / block
__global__ void __launch_bounds__(256) k_stage4(
    const float* __restrict__ w4g, const float* __restrict__ b4g)
{
    __shared__ __align__(16) float a3q[4][64 * 17];
    __shared__ __align__(16) float w4s[144 * 16];
    __shared__ __align__(16) float b4s[16];
    const int t = threadIdx.x;
    const int li = t >> 6, sub = t & 63;
    const int img = blockIdx.x * 4 + li;
    const float m3 = ldmax(15);
    const float s3 = m3 > 0.f ? 127.f / m3 : 0.f;

    {
        float sw = mkscale(4, 127.f);
        for (int i = t; i < 2304; i += 256)
            w4s[(i % 144) * 16 + (i / 144)] = quantv(w4g[i], sw, -127.f, 127.f);
    }
    if (t < 16) b4s[t] = quantv(b4g[t], mkscale(10, 32767.f), -32767.f, 32767.f);
    const float* a3 = g_act3 + img * 1024;
    for (int i = sub; i < 1024; i += 64)
        a3q[li][(i >> 4) * 17 + (i & 15)] = quantv(a3[i], s3, 0.f, 127.f);
    __syncthreads();

    const int pix = sub >> 2, ocq = sub & 3;
    const int oh = pix >> 2, ow = pix & 3;
    float4 acc = make_float4(0.f, 0.f, 0.f, 0.f);
    for (int r = 0; r < 3; r++) {
        int ih = 2*oh - 1 + r;
        if ((unsigned)ih >= 8u) continue;
        for (int s = 0; s < 3; s++) {
            int iw = 2*ow - 1 + s;
            if ((unsigned)iw >= 8u) continue;
            int pin = ih * 8 + iw;
            #pragma unroll
            for (int ic = 0; ic < 16; ic++) {
                float a = a3q[li][pin * 17 + ic];
                float4 wv = *(const float4*)&w4s[(ic * 9 + r*3 + s) * 16 + ocq * 4];
                acc.x += a*wv.x; acc.y += a*wv.y; acc.z += a*wv.z; acc.w += a*wv.w;
            }
        }
    }
    float4 c;
    c.x = fminf(fmaxf(acc.x + b4s[ocq*4+0], 0.f), 10.f);
    c.y = fminf(fmaxf(acc.y + b4s[ocq*4+1], 0.f), 10.f);
    c.z = fminf(fmaxf(acc.z + b4s[ocq*4+2], 0.f), 10.f);
    c.w = fminf(fmaxf(acc.w + b4s[ocq*4+3], 0.f), 10.f);
    *(float4*)(g_act4 + img * 256 + pix * 16 + ocq * 4) = c;
    float lm = warpmax(fmaxf(fmaxf(c.x, c.y), fmaxf(c.z, c.w)));
    if ((t & 31) == 0) amaxf(16, lm);
}

// Stage 5: conv5(16->64,1x1) + b5 + skip2 -> clip -> act5 ; 2 images / block
__global__ void __launch_bounds__(256) k_stage5(
    const float* __restrict__ w5g, const float* __restrict__ b5g)
{
    __shared__ __align__(16) float a4q[2][16 * 17];
    __shared__ __align__(16) float w5s[16 * 64];
    const int t = threadIdx.x;
    const int li = t >> 7, st = t & 127;
    const int img = blockIdx.x * 2 + li;
    const float m4 = ldmax(16);
    const float s4 = m4 > 0.f ? 127.f / m4 : 0.f;

    {
        float sw = mkscale(5, 127.f);
        for (int i = t; i < 1024; i += 256)
            w5s[(i & 15) * 64 + (i >> 4)] = quantv(w5g[i], sw, -127.f, 127.f);
    }
    const float* a4 = g_act4 + img * 256;
    for (int i = st; i < 256; i += 128)
        a4q[li][(i >> 4) * 17 + (i & 15)] = quantv(a4[i], s4, 0.f, 127.f);
    const float sb = mkscale(11, 32767.f);
    const int pix = st >> 3, ocq = st & 7;
    float bq[8];
    #pragma unroll
    for (int k = 0; k < 8; k++) bq[k] = quantv(b5g[ocq*8+k], sb, -32767.f, 32767.f);
    __syncthreads();

    float acc[8];
    #pragma unroll
    for (int k = 0; k < 8; k++) acc[k] = 0.f;
    #pragma unroll
    for (int ic = 0; ic < 16; ic++) {
        float a = a4q[li][pix * 17 + ic];
        float4 w0 = *(const float4*)&w5s[ic * 64 + ocq * 8];
        float4 w1 = *(const float4*)&w5s[ic * 64 + ocq * 8 + 4];
        acc[0] += a*w0.x; acc[1] += a*w0.y; acc[2] += a*w0.z; acc[3] += a*w0.w;
        acc[4] += a*w1.x; acc[5] += a*w1.y; acc[6] += a*w1.z; acc[7] += a*w1.w;
    }
    const float* sk = g_skip2 + (img * 16 + pix) * 64 + ocq * 8;
    float o[8], lm = 0.f;
    #pragma unroll
    for (int k = 0; k < 8; k++) {
        float y = acc[k] + bq[k] + sk[k];
        o[k] = fminf(fmaxf(y, 0.f), 10.f);
        lm = fmaxf(lm, o[k]);
    }
    float* dst = g_act5 + (img * 16 + pix) * 64 + ocq * 8;
    ((float4*)dst)[0] = make_float4(o[0], o[1], o[2], o[3]);
    ((float4*)dst)[1] = make_float4(o[4], o[5], o[6], o[7]);
    lm = warpmax(lm);
    if ((t & 31) == 0) amaxf(17, lm);
}

// Final: quant(act5) -> mean(4x4) -> linear(64->10) with quantized wl, bl
__global__ void __launch_bounds__(64) k_final(
    const float* __restrict__ wl, const float* __restrict__ bl, float* __restrict__ out)
{
    __shared__ __align__(16) float sv[64];
    __shared__ __align__(16) float wls[640];
    const int b = blockIdx.x, t = threadIdx.x;
    const float m5 = ldmax(17);
    const float s5 = m5 > 0.f ? 127.f / m5 : 0.f;
    {
        float swl = mkscale(6, 127.f);
        for (int i = t; i < 640; i += 64) wls[i] = quantv(wl[i], swl, -127.f, 127.f);
    }
    const float* a5 = g_act5 + b * 1024;
    float acc = 0.f;
    #pragma unroll
    for (int p = 0; p < 16; p++) acc += quantv(a5[p * 64 + t], s5, 0.f, 127.f);
    sv[t] = acc * (1.f / 16.f);
    __syncthreads();
    if (t < 10) {
        float o = quantv(bl[t], mkscale(12, 32767.f), -32767.f, 32767.f);
        for (int c = 0; c < 64; c++) o += sv[c] * wls[t * 64 + c];
        out[b * 10 + t] = o;
    }
}

extern "C" void kernel_launch(void* const* d_in, const int* in_sizes, int n_in,
                              void* d_out, int out_size) {
    const float* x  = (const float*)d_in[0];
    const float* w1 = (const float*)d_in[1];  const float* b1 = (const float*)d_in[2];
    const float* w2 = (const float*)d_in[3];  const float* b2 = (const float*)d_in[4];
    const float* w3 = (const float*)d_in[5];  const float* b3 = (const float*)d_in[6];
    const float* w4 = (const float*)d_in[7];  const float* b4 = (const float*)d_in[8];
    const float* w5 = (const float*)d_in[9];  const float* b5 = (const float*)d_in[10];
    const float* wl = (const float*)d_in[11]; const float* bl = (const float*)d_in[12];

    k_reset<<<1, 32>>>();
    k_xmax<<<512, 256>>>((const float4*)x);
    k_wmax<<<12, 256>>>(w1, w2, w3, w4, w5, wl, b1, b2, b3, b4, b5, bl);
    k_stage1<<<B_IMG, 256>>>(x, w1, b1);
    k_stage2<<<B_IMG, 128>>>(w2, b2);
    k_stage3<<<B_IMG, 256>>>(w3, b3);
    k_stage4<<<B_IMG / 4, 256>>>(w4, b4);
    k_stage5<<<B_IMG / 2, 256>>>(w5, b5);
    k_final<<<B_IMG, 64>>>(wl, bl, (float*)d_out);
}

// round 9
// speedup vs baseline: 2.2116x; 2.2116x over previous
#include <cuda_runtime.h>
#include <cstdint>

#define B_IMG 4096

// slots: 0:x 1..5:w1..w5 6:wl 7..11:b1..b5 12:bl 13..17:act1..act5
__device__ unsigned g_maxbits[18];
__device__ __align__(16) float g_skip1[B_IMG * 64];
__device__ __align__(16) float g_act1 [B_IMG * 8192];   // [b][256 pix][32 ch]
__device__ __align__(16) float g_act2 [B_IMG * 4096];   // [b][64 pix][64 ch]
__device__ __align__(16) float g_act3 [B_IMG * 1024];   // [b][64 pix][16 ch]
__device__ __align__(16) int   g_skip2p[B_IMG * 256];   // [b][16 pix][16 ic4] packed codes
__device__ __align__(16) float g_act4 [B_IMG * 256];    // [b][16 pix][16 ch]
__device__ __align__(16) float g_act5 [B_IMG * 1024];   // [b][16 pix][64 ch]

// pre-quantized parameters (filled once per launch by k_wprep)
__device__ __align__(16) int   g_w2p[4608];   // [tap][ic4][oc=64] packed codes
__device__ __align__(16) int   g_w3p[256];    // [ic4=16][oc=16]
__device__ __align__(16) int   g_w4p[576];    // [tap=9][ic4=4][oc=16]
__device__ __align__(16) int   g_w5p[256];    // [ic4=4][oc=64]
__device__ __align__(16) float g_w1q[288];    // dequantized fp32
__device__ __align__(16) float g_wlq[640];
__device__ __align__(16) float g_b1q[32];
__device__ __align__(16) float g_b2q[64];
__device__ __align__(16) float g_b3q[16];
__device__ __align__(16) float g_b4q[16];
__device__ __align__(16) float g_b5q[64];
__device__ __align__(16) float g_blq[12];

__device__ __forceinline__ float ldmax(int i) { return __uint_as_float(g_maxbits[i]); }
__device__ __forceinline__ void amaxf(int i, float v) {
    atomicMax(&g_maxbits[i], __float_as_uint(v));
}
__device__ __forceinline__ float warpmax(float v) {
    #pragma unroll
    for (int o = 16; o > 0; o >>= 1) v = fmaxf(v, __shfl_xor_sync(0xffffffffu, v, o));
    return v;
}
__device__ __forceinline__ float mkscale(int slot, float maxv) {
    float m = ldmax(slot);
    return m > 0.f ? maxv / m : 0.f;
}
__device__ __forceinline__ int qcode(float x, float s, int lo, int hi) {
    return max(lo, min(hi, __float2int_rn(x * s)));
}
// one-time dequant with true division (matches reference exactly)
__device__ __forceinline__ float dequant1(float x, float s, float lo, float hi) {
    if (s <= 0.f) return 0.f;
    return fminf(fmaxf(rintf(x * s), lo), hi) / s;
}

__global__ void k_reset() { if (threadIdx.x < 18) g_maxbits[threadIdx.x] = 0u; }

// blocks 0..511: max|x| ; blocks 512..523: per-param max
__global__ void __launch_bounds__(256) k_absmax(
    const float4* __restrict__ x,
    const float* w1, const float* w2, const float* w3, const float* w4, const float* w5,
    const float* wl, const float* b1, const float* b2, const float* b3, const float* b4,
    const float* b5, const float* bl)
{
    if (blockIdx.x < 512) {
        const int n4 = B_IMG * 1024 / 4;
        float m = 0.f;
        for (int i = blockIdx.x * 256 + threadIdx.x; i < n4; i += 512 * 256) {
            float4 v = x[i];
            m = fmaxf(m, fmaxf(fmaxf(fabsf(v.x), fabsf(v.y)), fmaxf(fabsf(v.z), fabsf(v.w))));
        }
        m = warpmax(m);
        if ((threadIdx.x & 31) == 0) amaxf(0, m);
    } else {
        __shared__ float red[8];
        const float* ptrs[12] = {w1, w2, w3, w4, w5, wl, b1, b2, b3, b4, b5, bl};
        const int sizes[12]   = {288, 18432, 1024, 2304, 1024, 640, 32, 64, 16, 16, 64, 10};
        int blk = blockIdx.x - 512;
        const float* p = ptrs[blk];
        int n = sizes[blk];
        float m = 0.f;
        for (int i = threadIdx.x; i < n; i += 256) m = fmaxf(m, fabsf(p[i]));
        m = warpmax(m);
        if ((threadIdx.x & 31) == 0) red[threadIdx.x >> 5] = m;
        __syncthreads();
        if (threadIdx.x == 0) {
            float mm = red[0];
            #pragma unroll
            for (int i = 1; i < 8; i++) mm = fmaxf(mm, red[i]);
            atomicMax(&g_maxbits[blk + 1], __float_as_uint(mm));
        }
    }
}

// one-time parameter quantization/packing
__global__ void __launch_bounds__(256) k_wprep(
    const float* __restrict__ w1, const float* __restrict__ w2, const float* __restrict__ w3,
    const float* __restrict__ w4, const float* __restrict__ w5, const float* __restrict__ wl,
    const float* __restrict__ b1, const float* __restrict__ b2, const float* __restrict__ b3,
    const float* __restrict__ b4, const float* __restrict__ b5, const float* __restrict__ bl)
{
    const int t = threadIdx.x;
    if (blockIdx.x == 0) {
        const float sw = mkscale(2, 127.f);
        for (int i = t; i < 4608; i += 256) {
            int oc = i & 63, r = i >> 6, ic4 = r & 7, tap = r >> 3;
            int p = 0;
            #pragma unroll
            for (int j = 0; j < 4; j++)
                p |= (qcode(w2[oc * 288 + (ic4 * 4 + j) * 9 + tap], sw, -127, 127) & 255) << (8 * j);
            g_w2p[i] = p;
        }
    } else {
        {   // w3p: [ic4][oc=16]
            const float s = mkscale(3, 127.f);
            for (int i = t; i < 256; i += 256) {
                int ic4 = i >> 4, oc = i & 15, p = 0;
                #pragma unroll
                for (int j = 0; j < 4; j++)
                    p |= (qcode(w3[oc * 64 + ic4 * 4 + j], s, -127, 127) & 255) << (8 * j);
                g_w3p[i] = p;
            }
        }
        {   // w4p: [tap][ic4][oc=16]
            const float s = mkscale(4, 127.f);
            for (int i = t; i < 576; i += 256) {
                int oc = i & 15, ic4 = (i >> 4) & 3, tap = i >> 6, p = 0;
                #pragma unroll
                for (int j = 0; j < 4; j++)
                    p |= (qcode(w4[oc * 144 + (ic4 * 4 + j) * 9 + tap], s, -127, 127) & 255) << (8 * j);
                g_w4p[i] = p;
            }
        }
        {   // w5p: [ic4][oc=64]
            const float s = mkscale(5, 127.f);
            for (int i = t; i < 256; i += 256) {
                int ic4 = i >> 6, oc = i & 63, p = 0;
                #pragma unroll
                for (int j = 0; j < 4; j++)
                    p |= (qcode(w5[oc * 16 + ic4 * 4 + j], s, -127, 127) & 255) << (8 * j);
                g_w5p[i] = p;
            }
        }
        {   const float s = mkscale(1, 127.f);
            for (int i = t; i < 288; i += 256) g_w1q[i] = dequant1(w1[i], s, -127.f, 127.f); }
        {   const float s = mkscale(6, 127.f);
            for (int i = t; i < 640; i += 256) g_wlq[i] = dequant1(wl[i], s, -127.f, 127.f); }
        {   const float s = mkscale(7, 32767.f);
            if (t < 32) g_b1q[t] = dequant1(b1[t], s, -32767.f, 32767.f); }
        {   const float s = mkscale(8, 32767.f);
            if (t < 64) g_b2q[t] = dequant1(b2[t], s, -32767.f, 32767.f); }
        {   const float s = mkscale(9, 32767.f);
            if (t < 16) g_b3q[t] = dequant1(b3[t], s, -32767.f, 32767.f); }
        {   const float s = mkscale(10, 32767.f);
            if (t < 16) g_b4q[t] = dequant1(b4[t], s, -32767.f, 32767.f); }
        {   const float s = mkscale(11, 32767.f);
            if (t < 64) g_b5q[t] = dequant1(b5[t], s, -32767.f, 32767.f); }
        {   const float s = mkscale(12, 32767.f);
            if (t < 10) g_blq[t] = dequant1(bl[t], s, -32767.f, 32767.f); }
    }
}

// Stage 1: quant(x) -> maxpool(5,4,2)=skip1 ; conv1(1->32,3x3,s2)+b -> clip -> act1
__global__ void __launch_bounds__(256) k_stage1(const float* __restrict__ x)
{
    __shared__ __align__(16) float xs[32 * 33];
    __shared__ __align__(16) float w1s[9 * 32];
    __shared__ __align__(16) float b1s[32];
    const int b = blockIdx.x, t = threadIdx.x;
    const float sx = mkscale(0, 127.f);
    const float invx = sx > 0.f ? 1.f / sx : 0.f;

    float4 v = ((const float4*)(x + b * 1024))[t];
    {
        int h = t >> 3, w0 = (t & 7) * 4;
        xs[h * 33 + w0 + 0] = fminf(fmaxf(rintf(v.x * sx), -127.f), 127.f) * invx;
        xs[h * 33 + w0 + 1] = fminf(fmaxf(rintf(v.y * sx), -127.f), 127.f) * invx;
        xs[h * 33 + w0 + 2] = fminf(fmaxf(rintf(v.z * sx), -127.f), 127.f) * invx;
        xs[h * 33 + w0 + 3] = fminf(fmaxf(rintf(v.w * sx), -127.f), 127.f) * invx;
    }
    for (int i = t; i < 288; i += 256) {
        int oc = i / 9, tap = i % 9;
        w1s[tap * 32 + oc] = g_w1q[i];
    }
    if (t < 32) b1s[t] = g_b1q[t];
    __syncthreads();

    if (t < 64) {  // maxpool 5/4/2 on quantized x
        int oh = t >> 3, ow = t & 7;
        float m = -3.4e38f;
        int h0 = max(0, 4 * oh - 2), h1 = min(31, 4 * oh + 2);
        int w0 = max(0, 4 * ow - 2), w1i = min(31, 4 * ow + 2);
        for (int ih = h0; ih <= h1; ih++)
            for (int iw = w0; iw <= w1i; iw++)
                m = fmaxf(m, xs[ih * 33 + iw]);
        g_skip1[b * 64 + t] = m;
    }

    int oh = t >> 4, ow = t & 15;
    float acc[32];
    #pragma unroll
    for (int o = 0; o < 32; o++) acc[o] = 0.f;
    for (int r = 0; r < 3; r++) {
        int ih = 2 * oh - 1 + r;
        if ((unsigned)ih >= 32u) continue;
        for (int s = 0; s < 3; s++) {
            int iw = 2 * ow - 1 + s;
            if ((unsigned)iw >= 32u) continue;
            float a = xs[ih * 33 + iw];
            const float* wrow = &w1s[(r * 3 + s) * 32];
            #pragma unroll
            for (int o4 = 0; o4 < 8; o4++) {
                float4 wv = ((const float4*)wrow)[o4];
                acc[o4*4+0] += a * wv.x; acc[o4*4+1] += a * wv.y;
                acc[o4*4+2] += a * wv.z; acc[o4*4+3] += a * wv.w;
            }
        }
    }
    float lm = 0.f;
    float* outp = g_act1 + (b * 256 + t) * 32;
    #pragma unroll
    for (int o4 = 0; o4 < 8; o4++) {
        float4 c;
        c.x = fminf(fmaxf(acc[o4*4+0] + b1s[o4*4+0], 0.f), 10.f);
        c.y = fminf(fmaxf(acc[o4*4+1] + b1s[o4*4+1], 0.f), 10.f);
        c.z = fminf(fmaxf(acc[o4*4+2] + b1s[o4*4+2], 0.f), 10.f);
        c.w = fminf(fmaxf(acc[o4*4+3] + b1s[o4*4+3], 0.f), 10.f);
        lm = fmaxf(lm, fmaxf(fmaxf(c.x, c.y), fmaxf(c.z, c.w)));
        ((float4*)outp)[o4] = c;
    }
    lm = warpmax(lm);
    if ((t & 31) == 0) amaxf(13, lm);
}

// Stage 2: conv2(32->64,3x3,s2) int8 dp4a ; + b2 + skip1 -> clip -> act2. 2 images/block.
__global__ void __launch_bounds__(256) k_stage2()
{
    __shared__ __align__(16) int ap[2][18 * 145];
    __shared__ __align__(16) int wp[4608];
    const int t = threadIdx.x;
    const int li = t >> 7, st = t & 127;
    const int b = blockIdx.x * 2 + li;
    const float m1 = ldmax(13);
    const float s1 = m1 > 0.f ? 127.f / m1 : 0.f;

    for (int i = t; i < 1152; i += 256) ((int4*)wp)[i] = ((const int4*)g_w2p)[i];
    for (int i = st; i < 18 * 145; i += 128) ap[li][i] = 0;
    __syncthreads();   // ap zero must land before halo-interior fill below (diff threads)

    const float4* ag = (const float4*)(g_act1 + b * 8192);
    #pragma unroll
    for (int i = 0; i < 16; i++) {
        int idx = st + 128 * i;
        float4 v = ag[idx];
        int ic4 = idx & 7, pix = idx >> 3;
        int ih = pix >> 4, iw = pix & 15;
        int c0 = min(127, __float2int_rn(v.x * s1));
        int c1 = min(127, __float2int_rn(v.y * s1));
        int c2 = min(127, __float2int_rn(v.z * s1));
        int c3 = min(127, __float2int_rn(v.w * s1));
        ap[li][(ih+1) * 145 + (iw+1) * 8 + ic4] = c0 | (c1<<8) | (c2<<16) | (c3<<24);
    }
    __syncthreads();

    const int posg = st & 15, ocg = st >> 4;       // 16 pixel-groups x 8 oc-groups
    const int oh = posg >> 1, ow0 = (posg & 1) * 4;
    int acc[4][8];
    #pragma unroll
    for (int j = 0; j < 4; j++)
        #pragma unroll
        for (int k = 0; k < 8; k++) acc[j][k] = 0;

    for (int r = 0; r < 3; r++)
        for (int s = 0; s < 3; s++) {
            const int base = (2*oh + r) * 145 + (2*ow0 + s) * 8;
            const int* wrow = &wp[(r*3+s) * 8 * 64 + ocg * 8];
            #pragma unroll
            for (int ic4 = 0; ic4 < 8; ic4++) {
                int a0 = ap[li][base + ic4], a1 = ap[li][base + 16 + ic4];
                int a2 = ap[li][base + 32 + ic4], a3 = ap[li][base + 48 + ic4];
                int4 wv0 = *(const int4*)(wrow + ic4 * 64);
                int4 wv1 = *(const int4*)(wrow + ic4 * 64 + 4);
                int wv[8] = {wv0.x, wv0.y, wv0.z, wv0.w, wv1.x, wv1.y, wv1.z, wv1.w};
                #pragma unroll
                for (int k = 0; k < 8; k++) {
                    acc[0][k] = __dp4a(a0, wv[k], acc[0][k]);
                    acc[1][k] = __dp4a(a1, wv[k], acc[1][k]);
                    acc[2][k] = __dp4a(a2, wv[k], acc[2][k]);
                    acc[3][k] = __dp4a(a3, wv[k], acc[3][k]);
                }
            }
        }

    const float sw = mkscale(2, 127.f);
    const float inv = (s1 > 0.f && sw > 0.f) ? 1.f / (s1 * sw) : 0.f;
    float lm = 0.f;
    #pragma unroll
    for (int j = 0; j < 4; j++) {
        float sk = g_skip1[b * 64 + posg * 4 + j];
        float o[8];
        #pragma unroll
        for (int k = 0; k < 8; k++) {
            float y = (float)acc[j][k] * inv + g_b2q[ocg*8+k] + sk;
            o[k] = fminf(fmaxf(y, 0.f), 10.f);
            lm = fmaxf(lm, o[k]);
        }
        float* dst = g_act2 + (b * 64 + posg * 4 + j) * 64 + ocg * 8;
        ((float4*)dst)[0] = make_float4(o[0], o[1], o[2], o[3]);
        ((float4*)dst)[1] = make_float4(o[4], o[5], o[6], o[7]);
    }
    lm = warpmax(lm);
    if ((t & 31) == 0) amaxf(14, lm);
}

// Stage 3: quant(act2) codes -> maxpool(3,2,1)=skip2 codes ; conv3(64->16,1x1) dp4a
__global__ void __launch_bounds__(256) k_stage3()
{
    __shared__ __align__(16) int cp[64 * 17];   // [pix][ic4] packed codes
    __shared__ __align__(16) int w3s[256];      // [ic4][oc]
    __shared__ __align__(16) float b3s[16];
    const int b = blockIdx.x, t = threadIdx.x;
    const float m2 = ldmax(14);
    const float s2 = m2 > 0.f ? 127.f / m2 : 0.f;

    if (t < 64) ((int4*)w3s)[t] = ((const int4*)g_w3p)[t];
    if (t < 16) b3s[t] = g_b3q[t];

    const float4* a2 = (const float4*)(g_act2 + b * 4096);
    #pragma unroll
    for (int i = 0; i < 4; i++) {
        int idx4 = t + 256 * i;
        float4 v = a2[idx4];
        int pix = idx4 >> 4, ic4 = idx4 & 15;
        int c0 = min(127, __float2int_rn(v.x * s2));
        int c1 = min(127, __float2int_rn(v.y * s2));
        int c2 = min(127, __float2int_rn(v.z * s2));
        int c3 = min(127, __float2int_rn(v.w * s2));
        cp[pix * 17 + ic4] = c0 | (c1<<8) | (c2<<16) | (c3<<24);
    }
    __syncthreads();

    {   // conv3: thread = (pos, 4 oc)
        int pos = t >> 2, ocq = t & 3;
        int4 acc = make_int4(0, 0, 0, 0);
        #pragma unroll
        for (int ic4 = 0; ic4 < 16; ic4++) {
            int a = cp[pos * 17 + ic4];
            int4 w = ((const int4*)w3s)[ic4 * 4 + ocq];
            acc.x = __dp4a(a, w.x, acc.x); acc.y = __dp4a(a, w.y, acc.y);
            acc.z = __dp4a(a, w.z, acc.z); acc.w = __dp4a(a, w.w, acc.w);
        }
        const float sw3 = mkscale(3, 127.f);
        const float inv3 = (s2 > 0.f && sw3 > 0.f) ? 1.f / (s2 * sw3) : 0.f;
        float4 c;
        c.x = fminf(fmaxf((float)acc.x * inv3 + b3s[ocq*4+0], 0.f), 10.f);
        c.y = fminf(fmaxf((float)acc.y * inv3 + b3s[ocq*4+1], 0.f), 10.f);
        c.z = fminf(fmaxf((float)acc.z * inv3 + b3s[ocq*4+2], 0.f), 10.f);
        c.w = fminf(fmaxf((float)acc.w * inv3 + b3s[ocq*4+3], 0.f), 10.f);
        *(float4*)(g_act3 + (b * 64 + pos) * 16 + ocq * 4) = c;
        float lm = warpmax(fmaxf(fmaxf(c.x, c.y), fmaxf(c.z, c.w)));
        if ((t & 31) == 0) amaxf(15, lm);
    }

    {   // maxpool(3,2,1) in code space (codes >= 0, byte-wise max)
        int opix = t >> 4, ic4 = t & 15;
        int oh = opix >> 2, ow = opix & 3;
        int m = 0;
        int h0 = max(0, 2*oh-1), h1 = min(7, 2*oh+1);
        int w0 = max(0, 2*ow-1), w1i = min(7, 2*ow+1);
        for (int ih = h0; ih <= h1; ih++)
            for (int iw = w0; iw <= w1i; iw++)
                m = __vmaxs4(m, cp[(ih * 8 + iw) * 17 + ic4]);
        g_skip2p[(b * 16 + opix) * 16 + ic4] = m;
    }
}

// Stage 4: conv4(16->16,3x3,s2) dp4a ; 4 images / block
__global__ void __launch_bounds__(256) k_stage4()
{
    __shared__ __align__(16) int a3p[4][64 * 5];   // [pin][ic4] padded
    __shared__ __align__(16) int w4s[576];         // [tap][ic4][oc]
    __shared__ __align__(16) float b4s[16];
    const int t = threadIdx.x;
    const int li = t >> 6, st = t & 63;
    const int img = blockIdx.x * 4 + li;
    const float m3 = ldmax(15);
    const float s3 = m3 > 0.f ? 127.f / m3 : 0.f;

    for (int i = t; i < 576; i += 256) w4s[i] = g_w4p[i];
    if (t < 16) b4s[t] = g_b4q[t];

    const float4* a3 = (const float4*)(g_act3 + img * 1024);
    #pragma unroll
    for (int i = 0; i < 4; i++) {
        int idx4 = st + 64 * i;
        float4 v = a3[idx4];
        int pin = idx4 >> 2, ic4 = idx4 & 3;
        int c0 = min(127, __float2int_rn(v.x * s3));
        int c1 = min(127, __float2int_rn(v.y * s3));
        int c2 = min(127, __float2int_rn(v.z * s3));
        int c3 = min(127, __float2int_rn(v.w * s3));
        a3p[li][pin * 5 + ic4] = c0 | (c1<<8) | (c2<<16) | (c3<<24);
    }
    __syncthreads();

    const int pix = st >> 2, ocq = st & 3;
    const int oh = pix >> 2, ow = pix & 3;
    int4 acc = make_int4(0, 0, 0, 0);
    for (int r = 0; r < 3; r++) {
        int ih = 2*oh - 1 + r;
        if ((unsigned)ih >= 8u) continue;
        for (int s = 0; s < 3; s++) {
            int iw = 2*ow - 1 + s;
            if ((unsigned)iw >= 8u) continue;
            int pin = ih * 8 + iw, tap = r * 3 + s;
            #pragma unroll
            for (int ic4 = 0; ic4 < 4; ic4++) {
                int a = a3p[li][pin * 5 + ic4];
                int4 w = ((const int4*)w4s)[tap * 16 + ic4 * 4 + ocq];
                acc.x = __dp4a(a, w.x, acc.x); acc.y = __dp4a(a, w.y, acc.y);
                acc.z = __dp4a(a, w.z, acc.z); acc.w = __dp4a(a, w.w, acc.w);
            }
        }
    }
    const float sw4 = mkscale(4, 127.f);
    const float inv4 = (s3 > 0.f && sw4 > 0.f) ? 1.f / (s3 * sw4) : 0.f;
    float4 c;
    c.x = fminf(fmaxf((float)acc.x * inv4 + b4s[ocq*4+0], 0.f), 10.f);
    c.y = fminf(fmaxf((float)acc.y * inv4 + b4s[ocq*4+1], 0.f), 10.f);
    c.z = fminf(fmaxf((float)acc.z * inv4 + b4s[ocq*4+2], 0.f), 10.f);
    c.w = fminf(fmaxf((float)acc.w * inv4 + b4s[ocq*4+3], 0.f), 10.f);
    *(float4*)(g_act4 + img * 256 + pix * 16 + ocq * 4) = c;
    float lm = warpmax(fmaxf(fmaxf(c.x, c.y), fmaxf(c.z, c.w)));
    if ((t & 31) == 0) amaxf(16, lm);
}

// Stage 5: conv5(16->64,1x1) dp4a + b5 + skip2 -> clip -> act5 ; 2 images / block
__global__ void __launch_bounds__(256) k_stage5()
{
    __shared__ __align__(16) int a4p[2][16 * 5];
    __shared__ __align__(16) int w5s[256];   // [ic4][oc=64]
    __shared__ __align__(16) float b5s[64];
    const int t = threadIdx.x;
    const int li = t >> 7, st = t & 127;
    const int img = blockIdx.x * 2 + li;
    const float m4 = ldmax(16);
    const float s4 = m4 > 0.f ? 127.f / m4 : 0.f;

    if (t < 64) ((int4*)w5s)[t] = ((const int4*)g_w5p)[t];
    if (t >= 64 && t < 128) b5s[t - 64] = g_b5q[t - 64];

    const float4* a4 = (const float4*)(g_act4 + img * 256);
    if (st < 64) {
        float4 v = a4[st];
        int pin = st >> 2, ic4 = st & 3;
        int c0 = min(127, __float2int_rn(v.x * s4));
        int c1 = min(127, __float2int_rn(v.y * s4));
        int c2 = min(127, __float2int_rn(v.z * s4));
        int c3 = min(127, __float2int_rn(v.w * s4));
        a4p[li][pin * 5 + ic4] = c0 | (c1<<8) | (c2<<16) | (c3<<24);
    }
    __syncthreads();

    const int pix = st >> 3, ocg = st & 7;
    int acc[8];
    #pragma unroll
    for (int k = 0; k < 8; k++) acc[k] = 0;
    #pragma unroll
    for (int ic4 = 0; ic4 < 4; ic4++) {
        int a = a4p[li][pix * 5 + ic4];
        int4 w0 = ((const int4*)w5s)[ic4 * 16 + ocg * 2];
        int4 w1 = ((const int4*)w5s)[ic4 * 16 + ocg * 2 + 1];
        acc[0] = __dp4a(a, w0.x, acc[0]); acc[1] = __dp4a(a, w0.y, acc[1]);
        acc[2] = __dp4a(a, w0.z, acc[2]); acc[3] = __dp4a(a, w0.w, acc[3]);
        acc[4] = __dp4a(a, w1.x, acc[4]); acc[5] = __dp4a(a, w1.y, acc[5]);
        acc[6] = __dp4a(a, w1.z, acc[6]); acc[7] = __dp4a(a, w1.w, acc[7]);
    }
    const float sw5 = mkscale(5, 127.f);
    const float invw = (s4 > 0.f && sw5 > 0.f) ? 1.f / (s4 * sw5) : 0.f;
    const float m2 = ldmax(14);
    const float s2 = m2 > 0.f ? 127.f / m2 : 0.f;
    const float inv2 = s2 > 0.f ? 1.f / s2 : 0.f;

    const int* skp = g_skip2p + (img * 16 + pix) * 16 + ocg * 2;
    int sk0 = skp[0], sk1 = skp[1];
    float o[8], lm = 0.f;
    #pragma unroll
    for (int k = 0; k < 8; k++) {
        int code = (k < 4 ? (sk0 >> (8 * k)) : (sk1 >> (8 * (k - 4)))) & 255;
        float y = (float)acc[k] * invw + b5s[ocg*8+k] + (float)code * inv2;
        o[k] = fminf(fmaxf(y, 0.f), 10.f);
        lm = fmaxf(lm, o[k]);
    }
    float* dst = g_act5 + (img * 16 + pix) * 64 + ocg * 8;
    ((float4*)dst)[0] = make_float4(o[0], o[1], o[2], o[3]);
    ((float4*)dst)[1] = make_float4(o[4], o[5], o[6], o[7]);
    lm = warpmax(lm);
    if ((t & 31) == 0) amaxf(17, lm);
}

// Final: quant(act5) -> mean(4x4) -> linear(64->10)
__global__ void __launch_bounds__(64) k_final(float* __restrict__ out)
{
    __shared__ __align__(16) float sv[64];
    __shared__ __align__(16) float wls[640];
    const int b = blockIdx.x, t = threadIdx.x;
    const float m5 = ldmax(17);
    const float s5 = m5 > 0.f ? 127.f / m5 : 0.f;
    const float inv5 = s5 > 0.f ? 1.f / s5 : 0.f;
    for (int i = t; i < 640; i += 64) wls[i] = g_wlq[i];
    const float* a5 = g_act5 + b * 1024;
    int acc = 0;
    #pragma unroll
    for (int p = 0; p < 16; p++)
        acc += min(127, __float2int_rn(a5[p * 64 + t] * s5));
    sv[t] = (float)acc * inv5 * (1.f / 16.f);
    __syncthreads();
    if (t < 10) {
        float o = g_blq[t];
        for (int c = 0; c < 64; c++) o += sv[c] * wls[t * 64 + c];
        out[b * 10 + t] = o;
    }
}

extern "C" void kernel_launch(void* const* d_in, const int* in_sizes, int n_in,
                              void* d_out, int out_size) {
    const float* x  = (const float*)d_in[0];
    const float* w1 = (const float*)d_in[1];  const float* b1 = (const float*)d_in[2];
    const float* w2 = (const float*)d_in[3];  const float* b2 = (const float*)d_in[4];
    const float* w3 = (const float*)d_in[5];  const float* b3 = (const float*)d_in[6];
    const float* w4 = (const float*)d_in[7];  const float* b4 = (const float*)d_in[8];
    const float* w5 = (const float*)d_in[9];  const float* b5 = (const float*)d_in[10];
    const float* wl = (const float*)d_in[11]; const float* bl = (const float*)d_in[12];

    k_reset<<<1, 32>>>();
    k_absmax<<<524, 256>>>((const float4*)x, w1, w2, w3, w4, w5, wl,
                           b1, b2, b3, b4, b5, bl);
    k_wprep<<<2, 256>>>(w1, w2, w3, w4, w5, wl, b1, b2, b3, b4, b5, bl);
    k_stage1<<<B_IMG, 256>>>(x);
    k_stage2<<<B_IMG / 2, 256>>>();
    k_stage3<<<B_IMG, 256>>>();
    k_stage4<<<B_IMG / 4, 256>>>();
    k_stage5<<<B_IMG / 2, 256>>>();
    k_final<<<B_IMG, 64>>>((float*)d_out);
}

// round 10
// speedup vs baseline: 2.4289x; 1.0983x over previous
#include <cuda_runtime.h>
#include <cstdint>

#define B_IMG 4096

// slots: 0:x 1..5:w1..w5 6:wl 7..11:b1..b5 12:bl 13..17:act1..act5
__device__ unsigned g_maxbits[18];
__device__ __align__(16) float g_skip1[B_IMG * 64];
__device__ __align__(16) float g_act1 [B_IMG * 8192];   // [b][256 pix][32 ch]
__device__ __align__(16) float g_act2 [B_IMG * 4096];   // [b][64 pix][64 ch]
__device__ __align__(16) float g_act3 [B_IMG * 1024];   // [b][64 pix][16 ch]
__device__ __align__(16) int   g_skip2p[B_IMG * 256];   // [b][16 pix][16 ic4] packed codes
__device__ __align__(16) float g_act4 [B_IMG * 256];    // [b][16 pix][16 ch]
__device__ __align__(16) float g_act5 [B_IMG * 1024];   // [b][16 pix][64 ch]

// pre-quantized parameters (filled once per launch by k_wprep)
__device__ __align__(16) int   g_w2p[4608];   // [oc=64][tap*8+ic4=72] packed codes
__device__ __align__(16) int   g_w1p[96];     // [r=3][oc=32] bytes (w0,w1,w2,0)
__device__ __align__(16) int   g_w3p[256];    // [ic4=16][oc=16]
__device__ __align__(16) int   g_w4p[576];    // [tap=9][ic4=4][oc=16]
__device__ __align__(16) int   g_w5p[256];    // [ic4=4][oc=64]
__device__ __align__(16) float g_wlq[640];
__device__ __align__(16) float g_b1q[32];
__device__ __align__(16) float g_b2q[64];
__device__ __align__(16) float g_b3q[16];
__device__ __align__(16) float g_b4q[16];
__device__ __align__(16) float g_b5q[64];
__device__ __align__(16) float g_blq[12];

__device__ __forceinline__ float ldmax(int i) { return __uint_as_float(g_maxbits[i]); }
__device__ __forceinline__ void amaxf(int i, float v) {
    atomicMax(&g_maxbits[i], __float_as_uint(v));
}
__device__ __forceinline__ float warpmax(float v) {
    #pragma unroll
    for (int o = 16; o > 0; o >>= 1) v = fmaxf(v, __shfl_xor_sync(0xffffffffu, v, o));
    return v;
}
__device__ __forceinline__ float mkscale(int slot, float maxv) {
    float m = ldmax(slot);
    return m > 0.f ? maxv / m : 0.f;
}
__device__ __forceinline__ int qcode(float x, float s, int lo, int hi) {
    return max(lo, min(hi, __float2int_rn(x * s)));
}
__device__ __forceinline__ float dequant1(float x, float s, float lo, float hi) {
    if (s <= 0.f) return 0.f;
    return fminf(fmaxf(rintf(x * s), lo), hi) / s;
}
// int8 tensor-core mma: D(16x8,s32) += A(16x32,s8) * B(32x8,s8)
__device__ __forceinline__ void mma_s8(int* c, int a0, int a1, int a2, int a3,
                                       int b0, int b1) {
    asm volatile(
        "mma.sync.aligned.m16n8k32.row.col.s32.s8.s8.s32 "
        "{%0,%1,%2,%3}, {%4,%5,%6,%7}, {%8,%9}, {%0,%1,%2,%3};"
        : "+r"(c[0]), "+r"(c[1]), "+r"(c[2]), "+r"(c[3])
        : "r"(a0), "r"(a1), "r"(a2), "r"(a3), "r"(b0), "r"(b1));
}

__global__ void k_reset() { if (threadIdx.x < 18) g_maxbits[threadIdx.x] = 0u; }

// blocks 0..511: max|x| ; blocks 512..523: per-param max
__global__ void __launch_bounds__(256) k_absmax(
    const float4* __restrict__ x,
    const float* w1, const float* w2, const float* w3, const float* w4, const float* w5,
    const float* wl, const float* b1, const float* b2, const float* b3, const float* b4,
    const float* b5, const float* bl)
{
    if (blockIdx.x < 512) {
        const int n4 = B_IMG * 1024 / 4;
        float m = 0.f;
        for (int i = blockIdx.x * 256 + threadIdx.x; i < n4; i += 512 * 256) {
            float4 v = x[i];
            m = fmaxf(m, fmaxf(fmaxf(fabsf(v.x), fabsf(v.y)), fmaxf(fabsf(v.z), fabsf(v.w))));
        }
        m = warpmax(m);
        if ((threadIdx.x & 31) == 0) amaxf(0, m);
    } else {
        __shared__ float red[8];
        const float* ptrs[12] = {w1, w2, w3, w4, w5, wl, b1, b2, b3, b4, b5, bl};
        const int sizes[12]   = {288, 18432, 1024, 2304, 1024, 640, 32, 64, 16, 16, 64, 10};
        int blk = blockIdx.x - 512;
        const float* p = ptrs[blk];
        int n = sizes[blk];
        float m = 0.f;
        for (int i = threadIdx.x; i < n; i += 256) m = fmaxf(m, fabsf(p[i]));
        m = warpmax(m);
        if ((threadIdx.x & 31) == 0) red[threadIdx.x >> 5] = m;
        __syncthreads();
        if (threadIdx.x == 0) {
            float mm = red[0];
            #pragma unroll
            for (int i = 1; i < 8; i++) mm = fmaxf(mm, red[i]);
            atomicMax(&g_maxbits[blk + 1], __float_as_uint(mm));
        }
    }
}

// one-time parameter quantization/packing
__global__ void __launch_bounds__(256) k_wprep(
    const float* __restrict__ w1, const float* __restrict__ w2, const float* __restrict__ w3,
    const float* __restrict__ w4, const float* __restrict__ w5, const float* __restrict__ wl,
    const float* __restrict__ b1, const float* __restrict__ b2, const float* __restrict__ b3,
    const float* __restrict__ b4, const float* __restrict__ b5, const float* __restrict__ bl)
{
    const int t = threadIdx.x;
    if (blockIdx.x == 0) {
        const float sw = mkscale(2, 127.f);
        for (int i = t; i < 4608; i += 256) {
            int oc = i / 72, k = i - oc * 72, tap = k >> 3, ic4 = k & 7;
            int p = 0;
            #pragma unroll
            for (int j = 0; j < 4; j++)
                p |= (qcode(w2[oc * 288 + (ic4 * 4 + j) * 9 + tap], sw, -127, 127) & 255) << (8 * j);
            g_w2p[i] = p;
        }
    } else {
        {   // w1p: [r][oc], bytes = (w[oc][r][0..2], 0)
            const float s = mkscale(1, 127.f);
            if (t < 96) {
                int r = t >> 5, oc = t & 31, p = 0;
                #pragma unroll
                for (int j = 0; j < 3; j++)
                    p |= (qcode(w1[oc * 9 + r * 3 + j], s, -127, 127) & 255) << (8 * j);
                g_w1p[t] = p;
            }
        }
        {   // w3p: [ic4][oc=16]
            const float s = mkscale(3, 127.f);
            for (int i = t; i < 256; i += 256) {
                int ic4 = i >> 4, oc = i & 15, p = 0;
                #pragma unroll
                for (int j = 0; j < 4; j++)
                    p |= (qcode(w3[oc * 64 + ic4 * 4 + j], s, -127, 127) & 255) << (8 * j);
                g_w3p[i] = p;
            }
        }
        {   // w4p: [tap][ic4][oc=16]
            const float s = mkscale(4, 127.f);
            for (int i = t; i < 576; i += 256) {
                int oc = i & 15, ic4 = (i >> 4) & 3, tap = i >> 6, p = 0;
                #pragma unroll
                for (int j = 0; j < 4; j++)
                    p |= (qcode(w4[oc * 144 + (ic4 * 4 + j) * 9 + tap], s, -127, 127) & 255) << (8 * j);
                g_w4p[i] = p;
            }
        }
        {   // w5p: [ic4][oc=64]
            const float s = mkscale(5, 127.f);
            for (int i = t; i < 256; i += 256) {
                int ic4 = i >> 6, oc = i & 63, p = 0;
                #pragma unroll
                for (int j = 0; j < 4; j++)
                    p |= (qcode(w5[oc * 16 + ic4 * 4 + j], s, -127, 127) & 255) << (8 * j);
                g_w5p[i] = p;
            }
        }
        {   const float s = mkscale(6, 127.f);
            for (int i = t; i < 640; i += 256) g_wlq[i] = dequant1(wl[i], s, -127.f, 127.f); }
        {   const float s = mkscale(7, 32767.f);
            if (t < 32) g_b1q[t] = dequant1(b1[t], s, -32767.f, 32767.f); }
        {   const float s = mkscale(8, 32767.f);
            if (t < 64) g_b2q[t] = dequant1(b2[t], s, -32767.f, 32767.f); }
        {   const float s = mkscale(9, 32767.f);
            if (t < 16) g_b3q[t] = dequant1(b3[t], s, -32767.f, 32767.f); }
        {   const float s = mkscale(10, 32767.f);
            if (t < 16) g_b4q[t] = dequant1(b4[t], s, -32767.f, 32767.f); }
        {   const float s = mkscale(11, 32767.f);
            if (t < 64) g_b5q[t] = dequant1(b5[t], s, -32767.f, 32767.f); }
        {   const float s = mkscale(12, 32767.f);
            if (t < 10) g_blq[t] = dequant1(bl[t], s, -32767.f, 32767.f); }
    }
}

// Stage 1: quant(x) codes -> maxpool(5,4,2)=skip1 ; conv1 via dp4a on packed 3-tap rows
__global__ void __launch_bounds__(256) k_stage1(const float* __restrict__ x)
{
    __shared__ __align__(16) signed char xsb[34 * 40];  // [ih+1][iw+1], zero-padded
    __shared__ __align__(16) int w1s[96];
    __shared__ __align__(16) float b1s[32];
    const int b = blockIdx.x, t = threadIdx.x;
    const float sx = mkscale(0, 127.f);
    const float sw = mkscale(1, 127.f);
    const float inv  = (sx > 0.f && sw > 0.f) ? 1.f / (sx * sw) : 0.f;
    const float invx = sx > 0.f ? 1.f / sx : 0.f;

    for (int i = t; i < 340; i += 256) ((int*)xsb)[i] = 0;
    if (t < 96) w1s[t] = g_w1p[t];
    if (t < 32) b1s[t] = g_b1q[t];
    __syncthreads();

    {   // quantize 4 pixels per thread into the padded byte tile
        float4 v = ((const float4*)(x + b * 1024))[t];
        int h = t >> 3, w0 = (t & 7) * 4;
        int base = (h + 1) * 40 + w0 + 1;
        xsb[base + 0] = (signed char)qcode(v.x, sx, -127, 127);
        xsb[base + 1] = (signed char)qcode(v.y, sx, -127, 127);
        xsb[base + 2] = (signed char)qcode(v.z, sx, -127, 127);
        xsb[base + 3] = (signed char)qcode(v.w, sx, -127, 127);
    }
    __syncthreads();

    if (t < 64) {  // maxpool 5/4/2 in code space (clamped window; pads excluded)
        int oh = t >> 3, ow = t & 7;
        int m = -128;
        int h0 = max(0, 4 * oh - 2), h1 = min(31, 4 * oh + 2);
        int w0 = max(0, 4 * ow - 2), w1i = min(31, 4 * ow + 2);
        for (int ih = h0; ih <= h1; ih++)
            for (int iw = w0; iw <= w1i; iw++)
                m = max(m, (int)xsb[(ih + 1) * 40 + iw + 1]);
        g_skip1[b * 64 + t] = (float)m * invx;
    }

    const int oh = t >> 4, ow = t & 15;
    int acc[32];
    #pragma unroll
    for (int o = 0; o < 32; o++) acc[o] = 0;
    const int* xw = (const int*)xsb;
    #pragma unroll
    for (int r = 0; r < 3; r++) {
        int rowb = (2 * oh + r) * 40 + 2 * ow;  // padded byte addr of taps (iw-1..)
        int wi = rowb >> 2, off = rowb & 3;
        int a = __byte_perm(xw[wi], xw[wi + 1], 0x3210 + off * 0x1111);
        const int4* wr = (const int4*)&w1s[r * 32];
        #pragma unroll
        for (int o4 = 0; o4 < 8; o4++) {
            int4 wv = wr[o4];
            acc[o4*4+0] = __dp4a(a, wv.x, acc[o4*4+0]);
            acc[o4*4+1] = __dp4a(a, wv.y, acc[o4*4+1]);
            acc[o4*4+2] = __dp4a(a, wv.z, acc[o4*4+2]);
            acc[o4*4+3] = __dp4a(a, wv.w, acc[o4*4+3]);
        }
    }
    float lm = 0.f;
    float* outp = g_act1 + (b * 256 + t) * 32;
    #pragma unroll
    for (int o4 = 0; o4 < 8; o4++) {
        float4 c;
        c.x = fminf(fmaxf((float)acc[o4*4+0] * inv + b1s[o4*4+0], 0.f), 10.f);
        c.y = fminf(fmaxf((float)acc[o4*4+1] * inv + b1s[o4*4+1], 0.f), 10.f);
        c.z = fminf(fmaxf((float)acc[o4*4+2] * inv + b1s[o4*4+2], 0.f), 10.f);
        c.w = fminf(fmaxf((float)acc[o4*4+3] * inv + b1s[o4*4+3], 0.f), 10.f);
        lm = fmaxf(lm, fmaxf(fmaxf(c.x, c.y), fmaxf(c.z, c.w)));
        ((float4*)outp)[o4] = c;
    }
    lm = warpmax(lm);
    if ((t & 31) == 0) amaxf(13, lm);
}

// Stage 2: conv2(32->64,3x3,s2) via int8 mma.sync tensor cores. 2 images/block.
__global__ void __launch_bounds__(256) k_stage2()
{
    __shared__ __align__(16) int ap[2][18 * 145];   // halo'd codes [ih+1][(iw+1)*8+ic4]
    __shared__ __align__(16) int ws[64 * 76];       // [oc][tap*8+ic4], stride 76
    const int t = threadIdx.x;
    const int li = t >> 7, st = t & 127;
    const int b0img = blockIdx.x * 2;
    const float m1 = ldmax(13);
    const float s1 = m1 > 0.f ? 127.f / m1 : 0.f;

    for (int i = t; i < 4608; i += 256) {
        int oc = i / 72, k = i - oc * 72;
        ws[oc * 76 + k] = g_w2p[i];
    }
    for (int i = st; i < 18 * 145; i += 128) ap[li][i] = 0;
    __syncthreads();

    const float4* ag = (const float4*)(g_act1 + (b0img + li) * 8192);
    #pragma unroll
    for (int i = 0; i < 16; i++) {
        int idx = st + 128 * i;
        float4 v = ag[idx];
        int ic4 = idx & 7, pix = idx >> 3;
        int ih = pix >> 4, iw = pix & 15;
        int c0 = min(127, __float2int_rn(v.x * s1));
        int c1 = min(127, __float2int_rn(v.y * s1));
        int c2 = min(127, __float2int_rn(v.z * s1));
        int c3 = min(127, __float2int_rn(v.w * s1));
        ap[li][(ih+1) * 145 + (iw+1) * 8 + ic4] = c0 | (c1<<8) | (c2<<16) | (c3<<24);
    }
    __syncthreads();

    // warp w: image li2 = w>>2, M-tile mt = w&3 (pixels mt*16 .. mt*16+15)
    const int w = t >> 5, lane = t & 31;
    const int li2 = w >> 2, mt = w & 3;
    const int b = b0img + li2;
    const int r = lane >> 2, c4 = lane & 3;
    const int pix = mt * 16 + r;            // fragment rows: pix and pix+8
    const int oh = pix >> 3, ow = pix & 7;

    int acc[8][4];
    #pragma unroll
    for (int nt = 0; nt < 8; nt++)
        #pragma unroll
        for (int k = 0; k < 4; k++) acc[nt][k] = 0;

    #pragma unroll
    for (int kc = 0; kc < 9; kc++) {        // K-chunk == conv tap
        const int tr = kc / 3, tc = kc - tr * 3;
        const int abase = (2 * oh + tr) * 145 + (2 * ow + tc) * 8;
        int a0 = ap[li2][abase + c4];
        int a1 = ap[li2][abase + 290 + c4];          // pix+8 => oh+1 => +2*145
        int a2 = ap[li2][abase + c4 + 4];
        int a3 = ap[li2][abase + 290 + c4 + 4];
        #pragma unroll
        for (int nt = 0; nt < 8; nt++) {
            int wb = (nt * 8 + r) * 76 + kc * 8;
            mma_s8(acc[nt], a0, a1, a2, a3, ws[wb + c4], ws[wb + c4 + 4]);
        }
    }

    const float sww = mkscale(2, 127.f);
    const float inv = (s1 > 0.f && sww > 0.f) ? 1.f / (s1 * sww) : 0.f;
    const float sk0 = g_skip1[b * 64 + pix];
    const float sk1 = g_skip1[b * 64 + pix + 8];
    float lm = 0.f;
    #pragma unroll
    for (int nt = 0; nt < 8; nt++) {
        int oc = nt * 8 + 2 * c4;
        float y0 = fminf(fmaxf((float)acc[nt][0] * inv + g_b2q[oc]     + sk0, 0.f), 10.f);
        float y1 = fminf(fmaxf((float)acc[nt][1] * inv + g_b2q[oc + 1] + sk0, 0.f), 10.f);
        float y2 = fminf(fmaxf((float)acc[nt][2] * inv + g_b2q[oc]     + sk1, 0.f), 10.f);
        float y3 = fminf(fmaxf((float)acc[nt][3] * inv + g_b2q[oc + 1] + sk1, 0.f), 10.f);
        lm = fmaxf(lm, fmaxf(fmaxf(y0, y1), fmaxf(y2, y3)));
        *(float2*)(g_act2 + (b * 64 + pix)     * 64 + oc) = make_float2(y0, y1);
        *(float2*)(g_act2 + (b * 64 + pix + 8) * 64 + oc) = make_float2(y2, y3);
    }
    lm = warpmax(lm);
    if (lane == 0) amaxf(14, lm);
}

// Stage 3: quant(act2) codes -> maxpool(3,2,1)=skip2 codes ; conv3(64->16,1x1) dp4a
__global__ void __launch_bounds__(256) k_stage3()
{
    __shared__ __align__(16) int cp[64 * 17];   // [pix][ic4] packed codes
    __shared__ __align__(16) int w3s[256];      // [ic4][oc]
    __shared__ __align__(16) float b3s[16];
    const int b = blockIdx.x, t = threadIdx.x;
    const float m2 = ldmax(14);
    const float s2 = m2 > 0.f ? 127.f / m2 : 0.f;

    if (t < 64) ((int4*)w3s)[t] = ((const int4*)g_w3p)[t];
    if (t < 16) b3s[t] = g_b3q[t];

    const float4* a2 = (const float4*)(g_act2 + b * 4096);
    #pragma unroll
    for (int i = 0; i < 4; i++) {
        int idx4 = t + 256 * i;
        float4 v = a2[idx4];
        int pix = idx4 >> 4, ic4 = idx4 & 15;
        int c0 = min(127, __float2int_rn(v.x * s2));
        int c1 = min(127, __float2int_rn(v.y * s2));
        int c2 = min(127, __float2int_rn(v.z * s2));
        int c3 = min(127, __float2int_rn(v.w * s2));
        cp[pix * 17 + ic4] = c0 | (c1<<8) | (c2<<16) | (c3<<24);
    }
    __syncthreads();

    {   // conv3: thread = (pos, 4 oc)
        int pos = t >> 2, ocq = t & 3;
        int4 acc = make_int4(0, 0, 0, 0);
        #pragma unroll
        for (int ic4 = 0; ic4 < 16; ic4++) {
            int a = cp[pos * 17 + ic4];
            int4 w = ((const int4*)w3s)[ic4 * 4 + ocq];
            acc.x = __dp4a(a, w.x, acc.x); acc.y = __dp4a(a, w.y, acc.y);
            acc.z = __dp4a(a, w.z, acc.z); acc.w = __dp4a(a, w.w, acc.w);
        }
        const float sw3 = mkscale(3, 127.f);
        const float inv3 = (s2 > 0.f && sw3 > 0.f) ? 1.f / (s2 * sw3) : 0.f;
        float4 c;
        c.x = fminf(fmaxf((float)acc.x * inv3 + b3s[ocq*4+0], 0.f), 10.f);
        c.y = fminf(fmaxf((float)acc.y * inv3 + b3s[ocq*4+1], 0.f), 10.f);
        c.z = fminf(fmaxf((float)acc.z * inv3 + b3s[ocq*4+2], 0.f), 10.f);
        c.w = fminf(fmaxf((float)acc.w * inv3 + b3s[ocq*4+3], 0.f), 10.f);
        *(float4*)(g_act3 + (b * 64 + pos) * 16 + ocq * 4) = c;
        float lm = warpmax(fmaxf(fmaxf(c.x, c.y), fmaxf(c.z, c.w)));
        if ((t & 31) == 0) amaxf(15, lm);
    }

    {   // maxpool(3,2,1) in code space
        int opix = t >> 4, ic4 = t & 15;
        int oh = opix >> 2, ow = opix & 3;
        int m = 0;
        int h0 = max(0, 2*oh-1), h1 = min(7, 2*oh+1);
        int w0 = max(0, 2*ow-1), w1i = min(7, 2*ow+1);
        for (int ih = h0; ih <= h1; ih++)
            for (int iw = w0; iw <= w1i; iw++)
                m = __vmaxs4(m, cp[(ih * 8 + iw) * 17 + ic4]);
        g_skip2p[(b * 16 + opix) * 16 + ic4] = m;
    }
}

// Stage 4: conv4(16->16,3x3,s2) dp4a ; 4 images / block
__global__ void __launch_bounds__(256) k_stage4()
{
    __shared__ __align__(16) int a3p[4][64 * 5];
    __shared__ __align__(16) int w4s[576];
    __shared__ __align__(16) float b4s[16];
    const int t = threadIdx.x;
    const int li = t >> 6, st = t & 63;
    const int img = blockIdx.x * 4 + li;
    const float m3 = ldmax(15);
    const float s3 = m3 > 0.f ? 127.f / m3 : 0.f;

    for (int i = t; i < 576; i += 256) w4s[i] = g_w4p[i];
    if (t < 16) b4s[t] = g_b4q[t];

    const float4* a3 = (const float4*)(g_act3 + img * 1024);
    #pragma unroll
    for (int i = 0; i < 4; i++) {
        int idx4 = st + 64 * i;
        float4 v = a3[idx4];
        int pin = idx4 >> 2, ic4 = idx4 & 3;
        int c0 = min(127, __float2int_rn(v.x * s3));
        int c1 = min(127, __float2int_rn(v.y * s3));
        int c2 = min(127, __float2int_rn(v.z * s3));
        int c3 = min(127, __float2int_rn(v.w * s3));
        a3p[li][pin * 5 + ic4] = c0 | (c1<<8) | (c2<<16) | (c3<<24);
    }
    __syncthreads();

    const int pix = st >> 2, ocq = st & 3;
    const int oh = pix >> 2, ow = pix & 3;
    int4 acc = make_int4(0, 0, 0, 0);
    for (int r = 0; r < 3; r++) {
        int ih = 2*oh - 1 + r;
        if ((unsigned)ih >= 8u) continue;
        for (int s = 0; s < 3; s++) {
            int iw = 2*ow - 1 + s;
            if ((unsigned)iw >= 8u) continue;
            int pin = ih * 8 + iw, tap = r * 3 + s;
            #pragma unroll
            for (int ic4 = 0; ic4 < 4; ic4++) {
                int a = a3p[li][pin * 5 + ic4];
                int4 w = ((const int4*)w4s)[tap * 16 + ic4 * 4 + ocq];
                acc.x = __dp4a(a, w.x, acc.x); acc.y = __dp4a(a, w.y, acc.y);
                acc.z = __dp4a(a, w.z, acc.z); acc.w = __dp4a(a, w.w, acc.w);
            }
        }
    }
    const float sw4 = mkscale(4, 127.f);
    const float inv4 = (s3 > 0.f && sw4 > 0.f) ? 1.f / (s3 * sw4) : 0.f;
    float4 c;
    c.x = fminf(fmaxf((float)acc.x * inv4 + b4s[ocq*4+0], 0.f), 10.f);
    c.y = fminf(fmaxf((float)acc.y * inv4 + b4s[ocq*4+1], 0.f), 10.f);
    c.z = fminf(fmaxf((float)acc.z * inv4 + b4s[ocq*4+2], 0.f), 10.f);
    c.w = fminf(fmaxf((float)acc.w * inv4 + b4s[ocq*4+3], 0.f), 10.f);
    *(float4*)(g_act4 + img * 256 + pix * 16 + ocq * 4) = c;
    float lm = warpmax(fmaxf(fmaxf(c.x, c.y), fmaxf(c.z, c.w)));
    if ((t & 31) == 0) amaxf(16, lm);
}

// Stage 5: conv5(16->64,1x1) dp4a + b5 + skip2 -> clip -> act5 ; 2 images / block
__global__ void __launch_bounds__(256) k_stage5()
{
    __shared__ __align__(16) int a4p[2][16 * 5];
    __shared__ __align__(16) int w5s[256];
    __shared__ __align__(16) float b5s[64];
    const int t = threadIdx.x;
    const int li = t >> 7, st = t & 127;
    const int img = blockIdx.x * 2 + li;
    const float m4 = ldmax(16);
    const float s4 = m4 > 0.f ? 127.f / m4 : 0.f;

    if (t < 64) ((int4*)w5s)[t] = ((const int4*)g_w5p)[t];
    if (t >= 64 && t < 128) b5s[t - 64] = g_b5q[t - 64];

    const float4* a4 = (const float4*)(g_act4 + img * 256);
    if (st < 64) {
        float4 v = a4[st];
        int pin = st >> 2, ic4 = st & 3;
        int c0 = min(127, __float2int_rn(v.x * s4));
        int c1 = min(127, __float2int_rn(v.y * s4));
        int c2 = min(127, __float2int_rn(v.z * s4));
        int c3 = min(127, __float2int_rn(v.w * s4));
        a4p[li][pin * 5 + ic4] = c0 | (c1<<8) | (c2<<16) | (c3<<24);
    }
    __syncthreads();

    const int pix = st >> 3, ocg = st & 7;
    int acc[8];
    #pragma unroll
    for (int k = 0; k < 8; k++) acc[k] = 0;
    #pragma unroll
    for (int ic4 = 0; ic4 < 4; ic4++) {
        int a = a4p[li][pix * 5 + ic4];
        int4 w0 = ((const int4*)w5s)[ic4 * 16 + ocg * 2];
        int4 w1 = ((const int4*)w5s)[ic4 * 16 + ocg * 2 + 1];
        acc[0] = __dp4a(a, w0.x, acc[0]); acc[1] = __dp4a(a, w0.y, acc[1]);
        acc[2] = __dp4a(a, w0.z, acc[2]); acc[3] = __dp4a(a, w0.w, acc[3]);
        acc[4] = __dp4a(a, w1.x, acc[4]); acc[5] = __dp4a(a, w1.y, acc[5]);
        acc[6] = __dp4a(a, w1.z, acc[6]); acc[7] = __dp4a(a, w1.w, acc[7]);
    }
    const float sw5 = mkscale(5, 127.f);
    const float invw = (s4 > 0.f && sw5 > 0.f) ? 1.f / (s4 * sw5) : 0.f;
    const float m2 = ldmax(14);
    const float s2 = m2 > 0.f ? 127.f / m2 : 0.f;
    const float inv2 = s2 > 0.f ? 1.f / s2 : 0.f;

    const int* skp = g_skip2p + (img * 16 + pix) * 16 + ocg * 2;
    int sk0 = skp[0], sk1 = skp[1];
    float o[8], lm = 0.f;
    #pragma unroll
    for (int k = 0; k < 8; k++) {
        int code = (k < 4 ? (sk0 >> (8 * k)) : (sk1 >> (8 * (k - 4)))) & 255;
        float y = (float)acc[k] * invw + b5s[ocg*8+k] + (float)code * inv2;
        o[k] = fminf(fmaxf(y, 0.f), 10.f);
        lm = fmaxf(lm, o[k]);
    }
    float* dst = g_act5 + (img * 16 + pix) * 64 + ocg * 8;
    ((float4*)dst)[0] = make_float4(o[0], o[1], o[2], o[3]);
    ((float4*)dst)[1] = make_float4(o[4], o[5], o[6], o[7]);
    lm = warpmax(lm);
    if ((t & 31) == 0) amaxf(17, lm);
}

// Final: quant(act5) -> mean(4x4) -> linear(64->10)
__global__ void __launch_bounds__(64) k_final(float* __restrict__ out)
{
    __shared__ __align__(16) float sv[64];
    __shared__ __align__(16) float wls[640];
    const int b = blockIdx.x, t = threadIdx.x;
    const float m5 = ldmax(17);
    const float s5 = m5 > 0.f ? 127.f / m5 : 0.f;
    const float inv5 = s5 > 0.f ? 1.f / s5 : 0.f;
    for (int i = t; i < 640; i += 64) wls[i] = g_wlq[i];
    const float* a5 = g_act5 + b * 1024;
    int acc = 0;
    #pragma unroll
    for (int p = 0; p < 16; p++)
        acc += min(127, __float2int_rn(a5[p * 64 + t] * s5));
    sv[t] = (float)acc * inv5 * (1.f / 16.f);
    __syncthreads();
    if (t < 10) {
        float o = g_blq[t];
        for (int c = 0; c < 64; c++) o += sv[c] * wls[t * 64 + c];
        out[b * 10 + t] = o;
    }
}

extern "C" void kernel_launch(void* const* d_in, const int* in_sizes, int n_in,
                              void* d_out, int out_size) {
    const float* x  = (const float*)d_in[0];
    const float* w1 = (const float*)d_in[1];  const float* b1 = (const float*)d_in[2];
    const float* w2 = (const float*)d_in[3];  const float* b2 = (const float*)d_in[4];
    const float* w3 = (const float*)d_in[5];  const float* b3 = (const float*)d_in[6];
    const float* w4 = (const float*)d_in[7];  const float* b4 = (const float*)d_in[8];
    const float* w5 = (const float*)d_in[9];  const float* b5 = (const float*)d_in[10];
    const float* wl = (const float*)d_in[11]; const float* bl = (const float*)d_in[12];

    k_reset<<<1, 32>>>();
    k_absmax<<<524, 256>>>((const float4*)x, w1, w2, w3, w4, w5, wl,
                           b1, b2, b3, b4, b5, bl);
    k_wprep<<<2, 256>>>(w1, w2, w3, w4, w5, wl, b1, b2, b3, b4, b5, bl);
    k_stage1<<<B_IMG, 256>>>(x);
    k_stage2<<<B_IMG / 2, 256>>>();
    k_stage3<<<B_IMG, 256>>>();
    k_stage4<<<B_IMG / 4, 256>>>();
    k_stage5<<<B_IMG / 2, 256>>>();
    k_final<<<B_IMG, 64>>>((float*)d_out);
}

// round 11
// speedup vs baseline: 2.9695x; 1.2226x over previous
#include <cuda_runtime.h>
#include <cstdint>

#define B_IMG 4096

// slots: 0:x 1..5:w1..w5 6:wl 7..11:b1..b5 12:bl 13..17:act1..act5
__device__ unsigned g_maxbits[18];
__device__ __align__(16) float g_skip1[B_IMG * 64];
__device__ __align__(16) float g_act1 [B_IMG * 8192];   // [b][256 pix][32 ch]
__device__ __align__(16) float g_act2 [B_IMG * 4096];   // [b][64 pix][64 ch]
__device__ __align__(16) float g_act3 [B_IMG * 1024];   // [b][64 pix][16 ch]
__device__ __align__(16) int   g_skip2p[B_IMG * 256];   // [b][16 pix][16 ic4] packed codes
__device__ __align__(16) float g_act4 [B_IMG * 256];    // [b][16 pix][16 ch]
__device__ __align__(16) float g_act5 [B_IMG * 1024];   // [b][16 pix][64 ch]

// pre-quantized parameters (filled once per launch by k_wprep)
__device__ __align__(16) int   g_w2p[4608];   // [oc=64][tap*8+ic4=72] packed codes
__device__ __align__(16) int   g_w1p[96];     // [r=3][oc=32] bytes (w0,w1,w2,0)
__device__ __align__(16) int   g_w3p[256];    // [ic4=16][oc=16]
__device__ __align__(16) int   g_w4p[576];    // [tap=9][ic4=4][oc=16]
__device__ __align__(16) int   g_w5p[256];    // [ic4=4][oc=64]
__device__ __align__(16) float g_wlq[640];
__device__ __align__(16) float g_b1q[32];
__device__ __align__(16) float g_b2q[64];
__device__ __align__(16) float g_b3q[16];
__device__ __align__(16) float g_b4q[16];
__device__ __align__(16) float g_b5q[64];
__device__ __align__(16) float g_blq[12];

__device__ __forceinline__ float ldmax(int i) { return __uint_as_float(g_maxbits[i]); }
__device__ __forceinline__ void amaxf(int i, float v) {
    atomicMax(&g_maxbits[i], __float_as_uint(v));
}
__device__ __forceinline__ float warpmax(float v) {
    #pragma unroll
    for (int o = 16; o > 0; o >>= 1) v = fmaxf(v, __shfl_xor_sync(0xffffffffu, v, o));
    return v;
}
// block-level max -> ONE atomic per block (avoids single-address RED serialization)
template<int NW>
__device__ __forceinline__ void blockamax(int slot, float lm, float* redm,
                                          int t) {
    lm = warpmax(lm);
    if ((t & 31) == 0) redm[t >> 5] = lm;
    __syncthreads();
    if (t == 0) {
        float mm = redm[0];
        #pragma unroll
        for (int i = 1; i < NW; i++) mm = fmaxf(mm, redm[i]);
        amaxf(slot, mm);
    }
}
__device__ __forceinline__ float mkscale(int slot, float maxv) {
    float m = ldmax(slot);
    return m > 0.f ? maxv / m : 0.f;
}
__device__ __forceinline__ int qcode(float x, float s, int lo, int hi) {
    return max(lo, min(hi, __float2int_rn(x * s)));
}
__device__ __forceinline__ float dequant1(float x, float s, float lo, float hi) {
    if (s <= 0.f) return 0.f;
    return fminf(fmaxf(rintf(x * s), lo), hi) / s;
}
// int8 tensor-core mma: D(16x8,s32) += A(16x32,s8) * B(32x8,s8)
__device__ __forceinline__ void mma_s8(int* c, int a0, int a1, int a2, int a3,
                                       int b0, int b1) {
    asm volatile(
        "mma.sync.aligned.m16n8k32.row.col.s32.s8.s8.s32 "
        "{%0,%1,%2,%3}, {%4,%5,%6,%7}, {%8,%9}, {%0,%1,%2,%3};"
        : "+r"(c[0]), "+r"(c[1]), "+r"(c[2]), "+r"(c[3])
        : "r"(a0), "r"(a1), "r"(a2), "r"(a3), "r"(b0), "r"(b1));
}

__global__ void k_reset() { if (threadIdx.x < 18) g_maxbits[threadIdx.x] = 0u; }

// blocks 0..511: max|x| ; blocks 512..523: per-param max
__global__ void __launch_bounds__(256) k_absmax(
    const float4* __restrict__ x,
    const float* w1, const float* w2, const float* w3, const float* w4, const float* w5,
    const float* wl, const float* b1, const float* b2, const float* b3, const float* b4,
    const float* b5, const float* bl)
{
    __shared__ float redm[8];
    if (blockIdx.x < 512) {
        const int n4 = B_IMG * 1024 / 4;
        float m = 0.f;
        for (int i = blockIdx.x * 256 + threadIdx.x; i < n4; i += 512 * 256) {
            float4 v = x[i];
            m = fmaxf(m, fmaxf(fmaxf(fabsf(v.x), fabsf(v.y)), fmaxf(fabsf(v.z), fabsf(v.w))));
        }
        blockamax<8>(0, m, redm, threadIdx.x);
    } else {
        const float* ptrs[12] = {w1, w2, w3, w4, w5, wl, b1, b2, b3, b4, b5, bl};
        const int sizes[12]   = {288, 18432, 1024, 2304, 1024, 640, 32, 64, 16, 16, 64, 10};
        int blk = blockIdx.x - 512;
        const float* p = ptrs[blk];
        int n = sizes[blk];
        float m = 0.f;
        for (int i = threadIdx.x; i < n; i += 256) m = fmaxf(m, fabsf(p[i]));
        blockamax<8>(blk + 1, m, redm, threadIdx.x);
    }
}

// one-time parameter quantization/packing
__global__ void __launch_bounds__(256) k_wprep(
    const float* __restrict__ w1, const float* __restrict__ w2, const float* __restrict__ w3,
    const float* __restrict__ w4, const float* __restrict__ w5, const float* __restrict__ wl,
    const float* __restrict__ b1, const float* __restrict__ b2, const float* __restrict__ b3,
    const float* __restrict__ b4, const float* __restrict__ b5, const float* __restrict__ bl)
{
    const int t = threadIdx.x;
    if (blockIdx.x == 0) {
        const float sw = mkscale(2, 127.f);
        for (int i = t; i < 4608; i += 256) {
            int oc = i / 72, k = i - oc * 72, tap = k >> 3, ic4 = k & 7;
            int p = 0;
            #pragma unroll
            for (int j = 0; j < 4; j++)
                p |= (qcode(w2[oc * 288 + (ic4 * 4 + j) * 9 + tap], sw, -127, 127) & 255) << (8 * j);
            g_w2p[i] = p;
        }
    } else {
        {   // w1p: [r][oc], bytes = (w[oc][r][0..2], 0)
            const float s = mkscale(1, 127.f);
            if (t < 96) {
                int r = t >> 5, oc = t & 31, p = 0;
                #pragma unroll
                for (int j = 0; j < 3; j++)
                    p |= (qcode(w1[oc * 9 + r * 3 + j], s, -127, 127) & 255) << (8 * j);
                g_w1p[t] = p;
            }
        }
        {   // w3p: [ic4][oc=16]
            const float s = mkscale(3, 127.f);
            for (int i = t; i < 256; i += 256) {
                int ic4 = i >> 4, oc = i & 15, p = 0;
                #pragma unroll
                for (int j = 0; j < 4; j++)
                    p |= (qcode(w3[oc * 64 + ic4 * 4 + j], s, -127, 127) & 255) << (8 * j);
                g_w3p[i] = p;
            }
        }
        {   // w4p: [tap][ic4][oc=16]
            const float s = mkscale(4, 127.f);
            for (int i = t; i < 576; i += 256) {
                int oc = i & 15, ic4 = (i >> 4) & 3, tap = i >> 6, p = 0;
                #pragma unroll
                for (int j = 0; j < 4; j++)
                    p |= (qcode(w4[oc * 144 + (ic4 * 4 + j) * 9 + tap], s, -127, 127) & 255) << (8 * j);
                g_w4p[i] = p;
            }
        }
        {   // w5p: [ic4][oc=64]
            const float s = mkscale(5, 127.f);
            for (int i = t; i < 256; i += 256) {
                int ic4 = i >> 6, oc = i & 63, p = 0;
                #pragma unroll
                for (int j = 0; j < 4; j++)
                    p |= (qcode(w5[oc * 16 + ic4 * 4 + j], s, -127, 127) & 255) << (8 * j);
                g_w5p[i] = p;
            }
        }
        {   const float s = mkscale(6, 127.f);
            for (int i = t; i < 640; i += 256) g_wlq[i] = dequant1(wl[i], s, -127.f, 127.f); }
        {   const float s = mkscale(7, 32767.f);
            if (t < 32) g_b1q[t] = dequant1(b1[t], s, -32767.f, 32767.f); }
        {   const float s = mkscale(8, 32767.f);
            if (t < 64) g_b2q[t] = dequant1(b2[t], s, -32767.f, 32767.f); }
        {   const float s = mkscale(9, 32767.f);
            if (t < 16) g_b3q[t] = dequant1(b3[t], s, -32767.f, 32767.f); }
        {   const float s = mkscale(10, 32767.f);
            if (t < 16) g_b4q[t] = dequant1(b4[t], s, -32767.f, 32767.f); }
        {   const float s = mkscale(11, 32767.f);
            if (t < 64) g_b5q[t] = dequant1(b5[t], s, -32767.f, 32767.f); }
        {   const float s = mkscale(12, 32767.f);
            if (t < 10) g_blq[t] = dequant1(bl[t], s, -32767.f, 32767.f); }
    }
}

// Stage 1: quant(x) codes -> maxpool(5,4,2)=skip1 ; conv1 via dp4a on packed 3-tap rows
__global__ void __launch_bounds__(256) k_stage1(const float* __restrict__ x)
{
    __shared__ __align__(16) signed char xsb[34 * 40];  // [ih+1][iw+1], zero-padded
    __shared__ __align__(16) int w1s[96];
    __shared__ __align__(16) float b1s[32];
    __shared__ float redm[8];
    const int b = blockIdx.x, t = threadIdx.x;
    const float sx = mkscale(0, 127.f);
    const float sw = mkscale(1, 127.f);
    const float inv  = (sx > 0.f && sw > 0.f) ? 1.f / (sx * sw) : 0.f;
    const float invx = sx > 0.f ? 1.f / sx : 0.f;

    for (int i = t; i < 340; i += 256) ((int*)xsb)[i] = 0;
    if (t < 96) w1s[t] = g_w1p[t];
    if (t < 32) b1s[t] = g_b1q[t];
    __syncthreads();

    {   // quantize 4 pixels per thread into the padded byte tile
        float4 v = ((const float4*)(x + b * 1024))[t];
        int h = t >> 3, w0 = (t & 7) * 4;
        int base = (h + 1) * 40 + w0 + 1;
        xsb[base + 0] = (signed char)qcode(v.x, sx, -127, 127);
        xsb[base + 1] = (signed char)qcode(v.y, sx, -127, 127);
        xsb[base + 2] = (signed char)qcode(v.z, sx, -127, 127);
        xsb[base + 3] = (signed char)qcode(v.w, sx, -127, 127);
    }
    __syncthreads();

    if (t < 64) {  // maxpool 5/4/2 in code space (clamped window; pads excluded)
        int oh = t >> 3, ow = t & 7;
        int m = -128;
        int h0 = max(0, 4 * oh - 2), h1 = min(31, 4 * oh + 2);
        int w0 = max(0, 4 * ow - 2), w1i = min(31, 4 * ow + 2);
        for (int ih = h0; ih <= h1; ih++)
            for (int iw = w0; iw <= w1i; iw++)
                m = max(m, (int)xsb[(ih + 1) * 40 + iw + 1]);
        g_skip1[b * 64 + t] = (float)m * invx;
    }

    const int oh = t >> 4, ow = t & 15;
    int acc[32];
    #pragma unroll
    for (int o = 0; o < 32; o++) acc[o] = 0;
    const int* xw = (const int*)xsb;
    #pragma unroll
    for (int r = 0; r < 3; r++) {
        int rowb = (2 * oh + r) * 40 + 2 * ow;  // padded byte addr of taps (iw-1..)
        int wi = rowb >> 2, off = rowb & 3;
        int a = __byte_perm(xw[wi], xw[wi + 1], 0x3210 + off * 0x1111);
        const int4* wr = (const int4*)&w1s[r * 32];
        #pragma unroll
        for (int o4 = 0; o4 < 8; o4++) {
            int4 wv = wr[o4];
            acc[o4*4+0] = __dp4a(a, wv.x, acc[o4*4+0]);
            acc[o4*4+1] = __dp4a(a, wv.y, acc[o4*4+1]);
            acc[o4*4+2] = __dp4a(a, wv.z, acc[o4*4+2]);
            acc[o4*4+3] = __dp4a(a, wv.w, acc[o4*4+3]);
        }
    }
    float lm = 0.f;
    float* outp = g_act1 + (b * 256 + t) * 32;
    #pragma unroll
    for (int o4 = 0; o4 < 8; o4++) {
        float4 c;
        c.x = fminf(fmaxf((float)acc[o4*4+0] * inv + b1s[o4*4+0], 0.f), 10.f);
        c.y = fminf(fmaxf((float)acc[o4*4+1] * inv + b1s[o4*4+1], 0.f), 10.f);
        c.z = fminf(fmaxf((float)acc[o4*4+2] * inv + b1s[o4*4+2], 0.f), 10.f);
        c.w = fminf(fmaxf((float)acc[o4*4+3] * inv + b1s[o4*4+3], 0.f), 10.f);
        lm = fmaxf(lm, fmaxf(fmaxf(c.x, c.y), fmaxf(c.z, c.w)));
        ((float4*)outp)[o4] = c;
    }
    __syncthreads();
    blockamax<8>(13, lm, redm, t);
}

// Stage 2: conv2(32->64,3x3,s2) via int8 mma.sync tensor cores. 2 images/block.
__global__ void __launch_bounds__(256) k_stage2()
{
    __shared__ __align__(16) int ap[2][18 * 145];   // halo'd codes [ih+1][(iw+1)*8+ic4]
    __shared__ __align__(16) int ws[64 * 76];       // [oc][tap*8+ic4], stride 76
    __shared__ float redm[8];
    const int t = threadIdx.x;
    const int li = t >> 7, st = t & 127;
    const int b0img = blockIdx.x * 2;
    const float m1 = ldmax(13);
    const float s1 = m1 > 0.f ? 127.f / m1 : 0.f;

    for (int i = t; i < 4608; i += 256) {
        int oc = i / 72, k = i - oc * 72;
        ws[oc * 76 + k] = g_w2p[i];
    }
    for (int i = st; i < 18 * 145; i += 128) ap[li][i] = 0;
    __syncthreads();

    const float4* ag = (const float4*)(g_act1 + (b0img + li) * 8192);
    #pragma unroll
    for (int i = 0; i < 16; i++) {
        int idx = st + 128 * i;
        float4 v = ag[idx];
        int ic4 = idx & 7, pix = idx >> 3;
        int ih = pix >> 4, iw = pix & 15;
        int c0 = min(127, __float2int_rn(v.x * s1));
        int c1 = min(127, __float2int_rn(v.y * s1));
        int c2 = min(127, __float2int_rn(v.z * s1));
        int c3 = min(127, __float2int_rn(v.w * s1));
        ap[li][(ih+1) * 145 + (iw+1) * 8 + ic4] = c0 | (c1<<8) | (c2<<16) | (c3<<24);
    }
    __syncthreads();

    // warp w: image li2 = w>>2, M-tile mt = w&3 (pixels mt*16 .. mt*16+15)
    const int w = t >> 5, lane = t & 31;
    const int li2 = w >> 2, mt = w & 3;
    const int b = b0img + li2;
    const int r = lane >> 2, c4 = lane & 3;
    const int pix = mt * 16 + r;            // fragment rows: pix and pix+8
    const int oh = pix >> 3, ow = pix & 7;

    int acc[8][4];
    #pragma unroll
    for (int nt = 0; nt < 8; nt++)
        #pragma unroll
        for (int k = 0; k < 4; k++) acc[nt][k] = 0;

    #pragma unroll
    for (int kc = 0; kc < 9; kc++) {        // K-chunk == conv tap
        const int tr = kc / 3, tc = kc - tr * 3;
        const int abase = (2 * oh + tr) * 145 + (2 * ow + tc) * 8;
        int a0 = ap[li2][abase + c4];
        int a1 = ap[li2][abase + 290 + c4];          // pix+8 => oh+1 => +2*145
        int a2 = ap[li2][abase + c4 + 4];
        int a3 = ap[li2][abase + 290 + c4 + 4];
        #pragma unroll
        for (int nt = 0; nt < 8; nt++) {
            int wb = (nt * 8 + r) * 76 + kc * 8;
            mma_s8(acc[nt], a0, a1, a2, a3, ws[wb + c4], ws[wb + c4 + 4]);
        }
    }

    const float sww = mkscale(2, 127.f);
    const float inv = (s1 > 0.f && sww > 0.f) ? 1.f / (s1 * sww) : 0.f;
    const float sk0 = g_skip1[b * 64 + pix];
    const float sk1 = g_skip1[b * 64 + pix + 8];
    float lm = 0.f;
    #pragma unroll
    for (int nt = 0; nt < 8; nt++) {
        int oc = nt * 8 + 2 * c4;
        float y0 = fminf(fmaxf((float)acc[nt][0] * inv + g_b2q[oc]     + sk0, 0.f), 10.f);
        float y1 = fminf(fmaxf((float)acc[nt][1] * inv + g_b2q[oc + 1] + sk0, 0.f), 10.f);
        float y2 = fminf(fmaxf((float)acc[nt][2] * inv + g_b2q[oc]     + sk1, 0.f), 10.f);
        float y3 = fminf(fmaxf((float)acc[nt][3] * inv + g_b2q[oc + 1] + sk1, 0.f), 10.f);
        lm = fmaxf(lm, fmaxf(fmaxf(y0, y1), fmaxf(y2, y3)));
        *(float2*)(g_act2 + (b * 64 + pix)     * 64 + oc) = make_float2(y0, y1);
        *(float2*)(g_act2 + (b * 64 + pix + 8) * 64 + oc) = make_float2(y2, y3);
    }
    blockamax<8>(14, lm, redm, t);
}

// Stage 3: quant(act2) codes -> maxpool(3,2,1)=skip2 codes ; conv3(64->16,1x1) dp4a
__global__ void __launch_bounds__(256) k_stage3()
{
    __shared__ __align__(16) int cp[64 * 17];   // [pix][ic4] packed codes
    __shared__ __align__(16) int w3s[256];      // [ic4][oc]
    __shared__ __align__(16) float b3s[16];
    __shared__ float redm[8];
    const int b = blockIdx.x, t = threadIdx.x;
    const float m2 = ldmax(14);
    const float s2 = m2 > 0.f ? 127.f / m2 : 0.f;

    if (t < 64) ((int4*)w3s)[t] = ((const int4*)g_w3p)[t];
    if (t < 16) b3s[t] = g_b3q[t];

    const float4* a2 = (const float4*)(g_act2 + b * 4096);
    #pragma unroll
    for (int i = 0; i < 4; i++) {
        int idx4 = t + 256 * i;
        float4 v = a2[idx4];
        int pix = idx4 >> 4, ic4 = idx4 & 15;
        int c0 = min(127, __float2int_rn(v.x * s2));
        int c1 = min(127, __float2int_rn(v.y * s2));
        int c2 = min(127, __float2int_rn(v.z * s2));
        int c3 = min(127, __float2int_rn(v.w * s2));
        cp[pix * 17 + ic4] = c0 | (c1<<8) | (c2<<16) | (c3<<24);
    }
    __syncthreads();

    float lm;
    {   // conv3: thread = (pos, 4 oc)
        int pos = t >> 2, ocq = t & 3;
        int4 acc = make_int4(0, 0, 0, 0);
        #pragma unroll
        for (int ic4 = 0; ic4 < 16; ic4++) {
            int a = cp[pos * 17 + ic4];
            int4 w = ((const int4*)w3s)[ic4 * 4 + ocq];
            acc.x = __dp4a(a, w.x, acc.x); acc.y = __dp4a(a, w.y, acc.y);
            acc.z = __dp4a(a, w.z, acc.z); acc.w = __dp4a(a, w.w, acc.w);
        }
        const float sw3 = mkscale(3, 127.f);
        const float inv3 = (s2 > 0.f && sw3 > 0.f) ? 1.f / (s2 * sw3) : 0.f;
        float4 c;
        c.x = fminf(fmaxf((float)acc.x * inv3 + b3s[ocq*4+0], 0.f), 10.f);
        c.y = fminf(fmaxf((float)acc.y * inv3 + b3s[ocq*4+1], 0.f), 10.f);
        c.z = fminf(fmaxf((float)acc.z * inv3 + b3s[ocq*4+2], 0.f), 10.f);
        c.w = fminf(fmaxf((float)acc.w * inv3 + b3s[ocq*4+3], 0.f), 10.f);
        *(float4*)(g_act3 + (b * 64 + pos) * 16 + ocq * 4) = c;
        lm = fmaxf(fmaxf(c.x, c.y), fmaxf(c.z, c.w));
    }

    {   // maxpool(3,2,1) in code space
        int opix = t >> 4, ic4 = t & 15;
        int oh = opix >> 2, ow = opix & 3;
        int m = 0;
        int h0 = max(0, 2*oh-1), h1 = min(7, 2*oh+1);
        int w0 = max(0, 2*ow-1), w1i = min(7, 2*ow+1);
        for (int ih = h0; ih <= h1; ih++)
            for (int iw = w0; iw <= w1i; iw++)
                m = __vmaxs4(m, cp[(ih * 8 + iw) * 17 + ic4]);
        g_skip2p[(b * 16 + opix) * 16 + ic4] = m;
    }
    blockamax<8>(15, lm, redm, t);
}

// Stage 4: conv4(16->16,3x3,s2) dp4a ; 4 images / block
__global__ void __launch_bounds__(256) k_stage4()
{
    __shared__ __align__(16) int a3p[4][64 * 5];
    __shared__ __align__(16) int w4s[576];
    __shared__ __align__(16) float b4s[16];
    __shared__ float redm[8];
    const int t = threadIdx.x;
    const int li = t >> 6, st = t & 63;
    const int img = blockIdx.x * 4 + li;
    const float m3 = ldmax(15);
    const float s3 = m3 > 0.f ? 127.f / m3 : 0.f;

    for (int i = t; i < 576; i += 256) w4s[i] = g_w4p[i];
    if (t < 16) b4s[t] = g_b4q[t];

    const float4* a3 = (const float4*)(g_act3 + img * 1024);
    #pragma unroll
    for (int i = 0; i < 4; i++) {
        int idx4 = st + 64 * i;
        float4 v = a3[idx4];
        int pin = idx4 >> 2, ic4 = idx4 & 3;
        int c0 = min(127, __float2int_rn(v.x * s3));
        int c1 = min(127, __float2int_rn(v.y * s3));
        int c2 = min(127, __float2int_rn(v.z * s3));
        int c3 = min(127, __float2int_rn(v.w * s3));
        a3p[li][pin * 5 + ic4] = c0 | (c1<<8) | (c2<<16) | (c3<<24);
    }
    __syncthreads();

    const int pix = st >> 2, ocq = st & 3;
    const int oh = pix >> 2, ow = pix & 3;
    int4 acc = make_int4(0, 0, 0, 0);
    for (int r = 0; r < 3; r++) {
        int ih = 2*oh - 1 + r;
        if ((unsigned)ih >= 8u) continue;
        for (int s = 0; s < 3; s++) {
            int iw = 2*ow - 1 + s;
            if ((unsigned)iw >= 8u) continue;
            int pin = ih * 8 + iw, tap = r * 3 + s;
            #pragma unroll
            for (int ic4 = 0; ic4 < 4; ic4++) {
                int a = a3p[li][pin * 5 + ic4];
                int4 w = ((const int4*)w4s)[tap * 16 + ic4 * 4 + ocq];
                acc.x = __dp4a(a, w.x, acc.x); acc.y = __dp4a(a, w.y, acc.y);
                acc.z = __dp4a(a, w.z, acc.z); acc.w = __dp4a(a, w.w, acc.w);
            }
        }
    }
    const float sw4 = mkscale(4, 127.f);
    const float inv4 = (s3 > 0.f && sw4 > 0.f) ? 1.f / (s3 * sw4) : 0.f;
    float4 c;
    c.x = fminf(fmaxf((float)acc.x * inv4 + b4s[ocq*4+0], 0.f), 10.f);
    c.y = fminf(fmaxf((float)acc.y * inv4 + b4s[ocq*4+1], 0.f), 10.f);
    c.z = fminf(fmaxf((float)acc.z * inv4 + b4s[ocq*4+2], 0.f), 10.f);
    c.w = fminf(fmaxf((float)acc.w * inv4 + b4s[ocq*4+3], 0.f), 10.f);
    *(float4*)(g_act4 + img * 256 + pix * 16 + ocq * 4) = c;
    float lm = fmaxf(fmaxf(c.x, c.y), fmaxf(c.z, c.w));
    blockamax<8>(16, lm, redm, t);
}

// Stage 5: conv5(16->64,1x1) dp4a + b5 + skip2 -> clip -> act5 ; 2 images / block
__global__ void __launch_bounds__(256) k_stage5()
{
    __shared__ __align__(16) int a4p[2][16 * 5];
    __shared__ __align__(16) int w5s[256];
    __shared__ __align__(16) float b5s[64];
    __shared__ float redm[8];
    const int t = threadIdx.x;
    const int li = t >> 7, st = t & 127;
    const int img = blockIdx.x * 2 + li;
    const float m4 = ldmax(16);
    const float s4 = m4 > 0.f ? 127.f / m4 : 0.f;

    if (t < 64) ((int4*)w5s)[t] = ((const int4*)g_w5p)[t];
    if (t >= 64 && t < 128) b5s[t - 64] = g_b5q[t - 64];

    const float4* a4 = (const float4*)(g_act4 + img * 256);
    if (st < 64) {
        float4 v = a4[st];
        int pin = st >> 2, ic4 = st & 3;
        int c0 = min(127, __float2int_rn(v.x * s4));
        int c1 = min(127, __float2int_rn(v.y * s4));
        int c2 = min(127, __float2int_rn(v.z * s4));
        int c3 = min(127, __float2int_rn(v.w * s4));
        a4p[li][pin * 5 + ic4] = c0 | (c1<<8) | (c2<<16) | (c3<<24);
    }
    __syncthreads();

    const int pix = st >> 3, ocg = st & 7;
    int acc[8];
    #pragma unroll
    for (int k = 0; k < 8; k++) acc[k] = 0;
    #pragma unroll
    for (int ic4 = 0; ic4 < 4; ic4++) {
        int a = a4p[li][pix * 5 + ic4];
        int4 w0 = ((const int4*)w5s)[ic4 * 16 + ocg * 2];
        int4 w1 = ((const int4*)w5s)[ic4 * 16 + ocg * 2 + 1];
        acc[0] = __dp4a(a, w0.x, acc[0]); acc[1] = __dp4a(a, w0.y, acc[1]);
        acc[2] = __dp4a(a, w0.z, acc[2]); acc[3] = __dp4a(a, w0.w, acc[3]);
        acc[4] = __dp4a(a, w1.x, acc[4]); acc[5] = __dp4a(a, w1.y, acc[5]);
        acc[6] = __dp4a(a, w1.z, acc[6]); acc[7] = __dp4a(a, w1.w, acc[7]);
    }
    const float sw5 = mkscale(5, 127.f);
    const float invw = (s4 > 0.f && sw5 > 0.f) ? 1.f / (s4 * sw5) : 0.f;
    const float m2 = ldmax(14);
    const float s2 = m2 > 0.f ? 127.f / m2 : 0.f;
    const float inv2 = s2 > 0.f ? 1.f / s2 : 0.f;

    const int* skp = g_skip2p + (img * 16 + pix) * 16 + ocg * 2;
    int sk0 = skp[0], sk1 = skp[1];
    float o[8], lm = 0.f;
    #pragma unroll
    for (int k = 0; k < 8; k++) {
        int code = (k < 4 ? (sk0 >> (8 * k)) : (sk1 >> (8 * (k - 4)))) & 255;
        float y = (float)acc[k] * invw + b5s[ocg*8+k] + (float)code * inv2;
        o[k] = fminf(fmaxf(y, 0.f), 10.f);
        lm = fmaxf(lm, o[k]);
    }
    float* dst = g_act5 + (img * 16 + pix) * 64 + ocg * 8;
    ((float4*)dst)[0] = make_float4(o[0], o[1], o[2], o[3]);
    ((float4*)dst)[1] = make_float4(o[4], o[5], o[6], o[7]);
    blockamax<8>(17, lm, redm, t);
}

// Final: quant(act5) -> mean(4x4) -> linear(64->10)
__global__ void __launch_bounds__(64) k_final(float* __restrict__ out)
{
    __shared__ __align__(16) float sv[64];
    __shared__ __align__(16) float wls[640];
    const int b = blockIdx.x, t = threadIdx.x;
    const float m5 = ldmax(17);
    const float s5 = m5 > 0.f ? 127.f / m5 : 0.f;
    const float inv5 = s5 > 0.f ? 1.f / s5 : 0.f;
    for (int i = t; i < 640; i += 64) wls[i] = g_wlq[i];
    const float* a5 = g_act5 + b * 1024;
    int acc = 0;
    #pragma unroll
    for (int p = 0; p < 16; p++)
        acc += min(127, __float2int_rn(a5[p * 64 + t] * s5));
    sv[t] = (float)acc * inv5 * (1.f / 16.f);
    __syncthreads();
    if (t < 10) {
        float o = g_blq[t];
        for (int c = 0; c < 64; c++) o += sv[c] * wls[t * 64 + c];
        out[b * 10 + t] = o;
    }
}

extern "C" void kernel_launch(void* const* d_in, const int* in_sizes, int n_in,
                              void* d_out, int out_size) {
    const float* x  = (const float*)d_in[0];
    const float* w1 = (const float*)d_in[1];  const float* b1 = (const float*)d_in[2];
    const float* w2 = (const float*)d_in[3];  const float* b2 = (const float*)d_in[4];
    const float* w3 = (const float*)d_in[5];  const float* b3 = (const float*)d_in[6];
    const float* w4 = (const float*)d_in[7];  const float* b4 = (const float*)d_in[8];
    const float* w5 = (const float*)d_in[9];  const float* b5 = (const float*)d_in[10];
    const float* wl = (const float*)d_in[11]; const float* bl = (const float*)d_in[12];

    k_reset<<<1, 32>>>();
    k_absmax<<<524, 256>>>((const float4*)x, w1, w2, w3, w4, w5, wl,
                           b1, b2, b3, b4, b5, bl);
    k_wprep<<<2, 256>>>(w1, w2, w3, w4, w5, wl, b1, b2, b3, b4, b5, bl);
    k_stage1<<<B_IMG, 256>>>(x);
    k_stage2<<<B_IMG / 2, 256>>>();
    k_stage3<<<B_IMG, 256>>>();
    k_stage4<<<B_IMG / 4, 256>>>();
    k_stage5<<<B_IMG / 2, 256>>>();
    k_final<<<B_IMG, 64>>>((float*)d_out);
}

// round 13
// speedup vs baseline: 3.2807x; 1.1048x over previous
#include <cuda_runtime.h>
#include <cstdint>

#define B_IMG 4096

// slots: 0:x 1..5:w1..w5 6:wl 7..11:b1..b5 12:bl 13..17:act1..act5
__device__ unsigned g_maxbits[18];
__device__ __align__(16) float g_skip1[B_IMG * 64];
__device__ __align__(16) float g_act1 [B_IMG * 8192];   // [b][256 pix][32 ch]
__device__ __align__(16) float g_act2 [B_IMG * 4096];   // [b][64 pix][64 ch]
__device__ __align__(16) float g_act3 [B_IMG * 1024];   // [b][64 pix][16 ch]
__device__ __align__(16) int   g_skip2p[B_IMG * 256];   // [b][16 pix][16 ic4] packed codes
__device__ __align__(16) float g_act4 [B_IMG * 256];    // [b][16 pix][16 ch]
__device__ __align__(16) float g_act5 [B_IMG * 1024];   // [b][16 pix][64 ch]

// pre-quantized parameters (filled once per launch by k_wprep)
__device__ __align__(16) int   g_w2p[4608];   // [oc=64][tap*8+ic4=72] packed codes
__device__ __align__(16) int   g_w1p[96];     // [r=3][oc=32] bytes (w0,w1,w2,0)
__device__ __align__(16) int   g_w3p[256];    // [ic4=16][oc=16]
__device__ __align__(16) int   g_w4p[576];    // [tap=9][ic4=4][oc=16]
__device__ __align__(16) int   g_w5p[256];    // [ic4=4][oc=64]
__device__ __align__(16) float g_wlq[640];
__device__ __align__(16) float g_b1q[32];
__device__ __align__(16) float g_b2q[64];
__device__ __align__(16) float g_b3q[16];
__device__ __align__(16) float g_b4q[16];
__device__ __align__(16) float g_b5q[64];
__device__ __align__(16) float g_blq[12];

__device__ __forceinline__ float ldmax(int i) { return __uint_as_float(g_maxbits[i]); }
__device__ __forceinline__ void amaxf(int i, float v) {
    atomicMax(&g_maxbits[i], __float_as_uint(v));
}
__device__ __forceinline__ float warpmax(float v) {
    #pragma unroll
    for (int o = 16; o > 0; o >>= 1) v = fmaxf(v, __shfl_xor_sync(0xffffffffu, v, o));
    return v;
}
// block-level max -> ONE atomic per block
template<int NW>
__device__ __forceinline__ void blockamax(int slot, float lm, float* redm, int t) {
    lm = warpmax(lm);
    if ((t & 31) == 0) redm[t >> 5] = lm;
    __syncthreads();
    if (t == 0) {
        float mm = redm[0];
        #pragma unroll
        for (int i = 1; i < NW; i++) mm = fmaxf(mm, redm[i]);
        amaxf(slot, mm);
    }
}
__device__ __forceinline__ float mkscale(int slot, float maxv) {
    float m = ldmax(slot);
    return m > 0.f ? maxv / m : 0.f;
}
__device__ __forceinline__ int qcode(float x, float s, int lo, int hi) {
    return max(lo, min(hi, __float2int_rn(x * s)));
}
__device__ __forceinline__ float dequant1(float x, float s, float lo, float hi) {
    if (s <= 0.f) return 0.f;
    return fminf(fmaxf(rintf(x * s), lo), hi) / s;
}
// int8 tensor-core mma: D(16x8,s32) += A(16x32,s8) * B(32x8,s8)
__device__ __forceinline__ void mma_s8(int* c, int a0, int a1, int a2, int a3,
                                       int b0, int b1) {
    asm volatile(
        "mma.sync.aligned.m16n8k32.row.col.s32.s8.s8.s32 "
        "{%0,%1,%2,%3}, {%4,%5,%6,%7}, {%8,%9}, {%0,%1,%2,%3};"
        : "+r"(c[0]), "+r"(c[1]), "+r"(c[2]), "+r"(c[3])
        : "r"(a0), "r"(a1), "r"(a2), "r"(a3), "r"(b0), "r"(b1));
}

__global__ void k_reset() { if (threadIdx.x < 18) g_maxbits[threadIdx.x] = 0u; }

// blocks 0..511: max|x| ; blocks 512..523: per-param max
__global__ void __launch_bounds__(256) k_absmax(
    const float4* __restrict__ x,
    const float* w1, const float* w2, const float* w3, const float* w4, const float* w5,
    const float* wl, const float* b1, const float* b2, const float* b3, const float* b4,
    const float* b5, const float* bl)
{
    __shared__ float redm[8];
    if (blockIdx.x < 512) {
        const int n4 = B_IMG * 1024 / 4;
        float m = 0.f;
        for (int i = blockIdx.x * 256 + threadIdx.x; i < n4; i += 512 * 256) {
            float4 v = x[i];
            m = fmaxf(m, fmaxf(fmaxf(fabsf(v.x), fabsf(v.y)), fmaxf(fabsf(v.z), fabsf(v.w))));
        }
        blockamax<8>(0, m, redm, threadIdx.x);
    } else {
        const float* ptrs[12] = {w1, w2, w3, w4, w5, wl, b1, b2, b3, b4, b5, bl};
        const int sizes[12]   = {288, 18432, 1024, 2304, 1024, 640, 32, 64, 16, 16, 64, 10};
        int blk = blockIdx.x - 512;
        const float* p = ptrs[blk];
        int n = sizes[blk];
        float m = 0.f;
        for (int i = threadIdx.x; i < n; i += 256) m = fmaxf(m, fabsf(p[i]));
        blockamax<8>(blk + 1, m, redm, threadIdx.x);
    }
}

// one-time parameter quantization/packing
__global__ void __launch_bounds__(256) k_wprep(
    const float* __restrict__ w1, const float* __restrict__ w2, const float* __restrict__ w3,
    const float* __restrict__ w4, const float* __restrict__ w5, const float* __restrict__ wl,
    const float* __restrict__ b1, const float* __restrict__ b2, const float* __restrict__ b3,
    const float* __restrict__ b4, const float* __restrict__ b5, const float* __restrict__ bl)
{
    const int t = threadIdx.x;
    if (blockIdx.x == 0) {
        const float sw = mkscale(2, 127.f);
        for (int i = t; i < 4608; i += 256) {
            int oc = i / 72, k = i - oc * 72, tap = k >> 3, ic4 = k & 7;
            int p = 0;
            #pragma unroll
            for (int j = 0; j < 4; j++)
                p |= (qcode(w2[oc * 288 + (ic4 * 4 + j) * 9 + tap], sw, -127, 127) & 255) << (8 * j);
            g_w2p[i] = p;
        }
    } else {
        {   // w1p: [r][oc], bytes = (w0,w1,w2,0)
            const float s = mkscale(1, 127.f);
            if (t < 96) {
                int r = t >> 5, oc = t & 31, p = 0;
                #pragma unroll
                for (int j = 0; j < 3; j++)
                    p |= (qcode(w1[oc * 9 + r * 3 + j], s, -127, 127) & 255) << (8 * j);
                g_w1p[t] = p;
            }
        }
        {   // w3p: [ic4][oc=16]
            const float s = mkscale(3, 127.f);
            for (int i = t; i < 256; i += 256) {
                int ic4 = i >> 4, oc = i & 15, p = 0;
                #pragma unroll
                for (int j = 0; j < 4; j++)
                    p |= (qcode(w3[oc * 64 + ic4 * 4 + j], s, -127, 127) & 255) << (8 * j);
                g_w3p[i] = p;
            }
        }
        {   // w4p: [tap][ic4][oc=16]
            const float s = mkscale(4, 127.f);
            for (int i = t; i < 576; i += 256) {
                int oc = i & 15, ic4 = (i >> 4) & 3, tap = i >> 6, p = 0;
                #pragma unroll
                for (int j = 0; j < 4; j++)
                    p |= (qcode(w4[oc * 144 + (ic4 * 4 + j) * 9 + tap], s, -127, 127) & 255) << (8 * j);
                g_w4p[i] = p;
            }
        }
        {   // w5p: [ic4][oc=64]
            const float s = mkscale(5, 127.f);
            for (int i = t; i < 256; i += 256) {
                int ic4 = i >> 6, oc = i & 63, p = 0;
                #pragma unroll
                for (int j = 0; j < 4; j++)
                    p |= (qcode(w5[oc * 16 + ic4 * 4 + j], s, -127, 127) & 255) << (8 * j);
                g_w5p[i] = p;
            }
        }
        {   const float s = mkscale(6, 127.f);
            for (int i = t; i < 640; i += 256) g_wlq[i] = dequant1(wl[i], s, -127.f, 127.f); }
        {   const float s = mkscale(7, 32767.f);
            if (t < 32) g_b1q[t] = dequant1(b1[t], s, -32767.f, 32767.f); }
        {   const float s = mkscale(8, 32767.f);
            if (t < 64) g_b2q[t] = dequant1(b2[t], s, -32767.f, 32767.f); }
        {   const float s = mkscale(9, 32767.f);
            if (t < 16) g_b3q[t] = dequant1(b3[t], s, -32767.f, 32767.f); }
        {   const float s = mkscale(10, 32767.f);
            if (t < 16) g_b4q[t] = dequant1(b4[t], s, -32767.f, 32767.f); }
        {   const float s = mkscale(11, 32767.f);
            if (t < 64) g_b5q[t] = dequant1(b5[t], s, -32767.f, 32767.f); }
        {   const float s = mkscale(12, 32767.f);
            if (t < 10) g_blq[t] = dequant1(bl[t], s, -32767.f, 32767.f); }
    }
}

// Stage 1: quant(x) -> maxpool(5,4,2)=skip1 ; conv1(1->32,3x3,s2) dp4a.
// Layout: row stride 40B = [4B left guard][32 data][4B right pad]; row 0 = top guard.
// Pixel (h,w) byte at (h+1)*40 + 4 + w. All guards zero.
__global__ void __launch_bounds__(256, 6) k_stage1(const float* __restrict__ x)
{
    __shared__ __align__(16) signed char xsb[33 * 40];
    __shared__ __align__(16) int w1s[96];
    __shared__ __align__(16) float b1s[32];
    __shared__ float redm[8];
    const int b = blockIdx.x, t = threadIdx.x;
    const float sx = mkscale(0, 127.f);
    const float sw = mkscale(1, 127.f);
    const float inv  = (sx > 0.f && sw > 0.f) ? 1.f / (sx * sw) : 0.f;
    const float invx = sx > 0.f ? 1.f / sx : 0.f;

    for (int i = t; i < 330; i += 256) ((int*)xsb)[i] = 0;
    if (t < 96) w1s[t] = g_w1p[t];
    if (t < 32) b1s[t] = g_b1q[t];
    __syncthreads();

    {   // quantize 4 pixels/thread, one aligned 4B store
        float4 v = ((const float4*)(x + b * 1024))[t];
        int h = t >> 3, w0 = (t & 7) * 4;
        int c0 = qcode(v.x, sx, -127, 127) & 255;
        int c1 = qcode(v.y, sx, -127, 127) & 255;
        int c2 = qcode(v.z, sx, -127, 127) & 255;
        int c3 = qcode(v.w, sx, -127, 127) & 255;
        *(int*)(xsb + (h + 1) * 40 + 4 + w0) = c0 | (c1 << 8) | (c2 << 16) | (c3 << 24);
    }
    __syncthreads();

    if (t < 64) {  // maxpool 5/4/2 in code space (clamped window)
        int oh = t >> 3, ow = t & 7;
        int m = -128;
        int h0 = max(0, 4 * oh - 2), h1 = min(31, 4 * oh + 2);
        int w0 = max(0, 4 * ow - 2), w1i = min(31, 4 * ow + 2);
        for (int ih = h0; ih <= h1; ih++)
            for (int iw = w0; iw <= w1i; iw++)
                m = max(m, (int)xsb[(ih + 1) * 40 + 4 + iw]);
        g_skip1[b * 64 + t] = (float)m * invx;
    }

    const int half = t & 1;
    const int pix0 = t >> 1;                 // 0..127; second task: +128
    const int* xw = (const int*)xsb;
    float lm = 0.f;
    #pragma unroll
    for (int it = 0; it < 2; it++) {
        const int pix = pix0 + it * 128;
        const int oh = pix >> 4, ow = pix & 15;
        int acc[16];
        #pragma unroll
        for (int o = 0; o < 16; o++) acc[o] = 0;
        #pragma unroll
        for (int r = 0; r < 3; r++) {
            // bytes needed: input cols (2ow-1 .. 2ow+2), row (2oh+r) [+1 shift built in]
            int rowb = (2 * oh + r) * 40 + 4 + 2 * ow - 1;   // >= 3, always in bounds
            int wi = rowb >> 2, off = rowb & 3;
            int a = __byte_perm(xw[wi], xw[wi + 1], 0x3210 + off * 0x1111);
            const int4* wr = (const int4*)&w1s[r * 32 + half * 16];
            #pragma unroll
            for (int o4 = 0; o4 < 4; o4++) {
                int4 wv = wr[o4];
                acc[o4*4+0] = __dp4a(a, wv.x, acc[o4*4+0]);
                acc[o4*4+1] = __dp4a(a, wv.y, acc[o4*4+1]);
                acc[o4*4+2] = __dp4a(a, wv.z, acc[o4*4+2]);
                acc[o4*4+3] = __dp4a(a, wv.w, acc[o4*4+3]);
            }
        }
        float* outp = g_act1 + (b * 256 + pix) * 32 + half * 16;
        #pragma unroll
        for (int o4 = 0; o4 < 4; o4++) {
            float4 c;
            c.x = fminf(fmaxf((float)acc[o4*4+0] * inv + b1s[half*16 + o4*4+0], 0.f), 10.f);
            c.y = fminf(fmaxf((float)acc[o4*4+1] * inv + b1s[half*16 + o4*4+1], 0.f), 10.f);
            c.z = fminf(fmaxf((float)acc[o4*4+2] * inv + b1s[half*16 + o4*4+2], 0.f), 10.f);
            c.w = fminf(fmaxf((float)acc[o4*4+3] * inv + b1s[half*16 + o4*4+3], 0.f), 10.f);
            lm = fmaxf(lm, fmaxf(fmaxf(c.x, c.y), fmaxf(c.z, c.w)));
            ((float4*)outp)[o4] = c;
        }
    }
    blockamax<8>(13, lm, redm, t);
}

// Stage 2: conv2(32->64,3x3,s2) int8 mma.sync. 2 images/block, 512 threads,
// warp = (img, M-tile, N-half): M16 x N32 per warp -> acc[4][4].
__global__ void __launch_bounds__(512) k_stage2()
{
    __shared__ __align__(16) int ap[2][18 * 145];   // halo'd codes [ih+1][(iw+1)*8+ic4]
    __shared__ __align__(16) int ws[64 * 76];       // [oc][tap*8+ic4], stride 76
    __shared__ float redm[16];
    const int t = threadIdx.x;
    const int b0img = blockIdx.x * 2;
    const float m1 = ldmax(13);
    const float s1 = m1 > 0.f ? 127.f / m1 : 0.f;

    for (int i = t; i < 4608; i += 512) {
        int oc = i / 72, k = i - oc * 72;
        ws[oc * 76 + k] = g_w2p[i];
    }
    for (int i = t; i < 2 * 2610; i += 512) ((int*)ap)[i] = 0;
    __syncthreads();

    {
        const int li = t >> 8, st = t & 255;
        const float4* ag = (const float4*)(g_act1 + (b0img + li) * 8192);
        #pragma unroll
        for (int i = 0; i < 8; i++) {
            int idx = st + 256 * i;
            float4 v = ag[idx];
            int ic4 = idx & 7, pix = idx >> 3;
            int ih = pix >> 4, iw = pix & 15;
            int c0 = min(127, __float2int_rn(v.x * s1));
            int c1 = min(127, __float2int_rn(v.y * s1));
            int c2 = min(127, __float2int_rn(v.z * s1));
            int c3 = min(127, __float2int_rn(v.w * s1));
            ap[li][(ih+1) * 145 + (iw+1) * 8 + ic4] = c0 | (c1<<8) | (c2<<16) | (c3<<24);
        }
    }
    __syncthreads();

    // 16 warps: li2 = w>>3 (image), mt = (w>>1)&3 (M-tile), nh = w&1 (N-half)
    const int w = t >> 5, lane = t & 31;
    const int li2 = w >> 3, mt = (w >> 1) & 3, nh = w & 1;
    const int b = b0img + li2;
    const int r = lane >> 2, c4 = lane & 3;
    const int pix = mt * 16 + r;            // fragment rows: pix and pix+8
    const int oh = pix >> 3, ow = pix & 7;

    int acc[4][4];
    #pragma unroll
    for (int j = 0; j < 4; j++)
        #pragma unroll
        for (int k = 0; k < 4; k++) acc[j][k] = 0;

    #pragma unroll
    for (int kc = 0; kc < 9; kc++) {        // K-chunk == conv tap
        const int tr = kc / 3, tc = kc - tr * 3;
        const int abase = (2 * oh + tr) * 145 + (2 * ow + tc) * 8;
        int a0 = ap[li2][abase + c4];
        int a1 = ap[li2][abase + 290 + c4];          // pix+8 => oh+1 => +2*145
        int a2 = ap[li2][abase + c4 + 4];
        int a3 = ap[li2][abase + 290 + c4 + 4];
        #pragma unroll
        for (int j = 0; j < 4; j++) {
            int ntg = nh * 4 + j;
            int wb = (ntg * 8 + r) * 76 + kc * 8;
            mma_s8(acc[j], a0, a1, a2, a3, ws[wb + c4], ws[wb + c4 + 4]);
        }
    }

    const float sww = mkscale(2, 127.f);
    const float inv = (s1 > 0.f && sww > 0.f) ? 1.f / (s1 * sww) : 0.f;
    const float sk0 = g_skip1[b * 64 + pix];
    const float sk1 = g_skip1[b * 64 + pix + 8];
    float lm = 0.f;
    #pragma unroll
    for (int j = 0; j < 4; j++) {
        int oc = (nh * 4 + j) * 8 + 2 * c4;
        float y0 = fminf(fmaxf((float)acc[j][0] * inv + g_b2q[oc]     + sk0, 0.f), 10.f);
        float y1 = fminf(fmaxf((float)acc[j][1] * inv + g_b2q[oc + 1] + sk0, 0.f), 10.f);
        float y2 = fminf(fmaxf((float)acc[j][2] * inv + g_b2q[oc]     + sk1, 0.f), 10.f);
        float y3 = fminf(fmaxf((float)acc[j][3] * inv + g_b2q[oc + 1] + sk1, 0.f), 10.f);
        lm = fmaxf(lm, fmaxf(fmaxf(y0, y1), fmaxf(y2, y3)));
        *(float2*)(g_act2 + (b * 64 + pix)     * 64 + oc) = make_float2(y0, y1);
        *(float2*)(g_act2 + (b * 64 + pix + 8) * 64 + oc) = make_float2(y2, y3);
    }
    blockamax<16>(14, lm, redm, t);
}

// Stage 3: quant(act2) codes -> maxpool(3,2,1)=skip2 codes ; conv3(64->16,1x1) dp4a
__global__ void __launch_bounds__(256) k_stage3()
{
    __shared__ __align__(16) int cp[64 * 17];   // [pix][ic4] packed codes
    __shared__ __align__(16) int w3s[256];      // [ic4][oc]
    __shared__ __align__(16) float b3s[16];
    __shared__ float redm[8];
    const int b = blockIdx.x, t = threadIdx.x;
    const float m2 = ldmax(14);
    const float s2 = m2 > 0.f ? 127.f / m2 : 0.f;

    if (t < 64) ((int4*)w3s)[t] = ((const int4*)g_w3p)[t];
    if (t < 16) b3s[t] = g_b3q[t];

    const float4* a2 = (const float4*)(g_act2 + b * 4096);
    #pragma unroll
    for (int i = 0; i < 4; i++) {
        int idx4 = t + 256 * i;
        float4 v = a2[idx4];
        int pix = idx4 >> 4, ic4 = idx4 & 15;
        int c0 = min(127, __float2int_rn(v.x * s2));
        int c1 = min(127, __float2int_rn(v.y * s2));
        int c2 = min(127, __float2int_rn(v.z * s2));
        int c3 = min(127, __float2int_rn(v.w * s2));
        cp[pix * 17 + ic4] = c0 | (c1<<8) | (c2<<16) | (c3<<24);
    }
    __syncthreads();

    float lm;
    {   // conv3: thread = (pos, 4 oc)
        int pos = t >> 2, ocq = t & 3;
        int4 acc = make_int4(0, 0, 0, 0);
        #pragma unroll
        for (int ic4 = 0; ic4 < 16; ic4++) {
            int a = cp[pos * 17 + ic4];
            int4 w = ((const int4*)w3s)[ic4 * 4 + ocq];
            acc.x = __dp4a(a, w.x, acc.x); acc.y = __dp4a(a, w.y, acc.y);
            acc.z = __dp4a(a, w.z, acc.z); acc.w = __dp4a(a, w.w, acc.w);
        }
        const float sw3 = mkscale(3, 127.f);
        const float inv3 = (s2 > 0.f && sw3 > 0.f) ? 1.f / (s2 * sw3) : 0.f;
        float4 c;
        c.x = fminf(fmaxf((float)acc.x * inv3 + b3s[ocq*4+0], 0.f), 10.f);
        c.y = fminf(fmaxf((float)acc.y * inv3 + b3s[ocq*4+1], 0.f), 10.f);
        c.z = fminf(fmaxf((float)acc.z * inv3 + b3s[ocq*4+2], 0.f), 10.f);
        c.w = fminf(fmaxf((float)acc.w * inv3 + b3s[ocq*4+3], 0.f), 10.f);
        *(float4*)(g_act3 + (b * 64 + pos) * 16 + ocq * 4) = c;
        lm = fmaxf(fmaxf(c.x, c.y), fmaxf(c.z, c.w));
    }

    {   // maxpool(3,2,1) in code space
        int opix = t >> 4, ic4 = t & 15;
        int oh = opix >> 2, ow = opix & 3;
        int m = 0;
        int h0 = max(0, 2*oh-1), h1 = min(7, 2*oh+1);
        int w0 = max(0, 2*ow-1), w1i = min(7, 2*ow+1);
        for (int ih = h0; ih <= h1; ih++)
            for (int iw = w0; iw <= w1i; iw++)
                m = __vmaxs4(m, cp[(ih * 8 + iw) * 17 + ic4]);
        g_skip2p[(b * 16 + opix) * 16 + ic4] = m;
    }
    blockamax<8>(15, lm, redm, t);
}

// Stage 4: conv4(16->16,3x3,s2) dp4a ; 4 images / block
__global__ void __launch_bounds__(256) k_stage4()
{
    __shared__ __align__(16) int a3p[4][64 * 5];
    __shared__ __align__(16) int w4s[576];
    __shared__ __align__(16) float b4s[16];
    __shared__ float redm[8];
    const int t = threadIdx.x;
    const int li = t >> 6, st = t & 63;
    const int img = blockIdx.x * 4 + li;
    const float m3 = ldmax(15);
    const float s3 = m3 > 0.f ? 127.f / m3 : 0.f;

    for (int i = t; i < 576; i += 256) w4s[i] = g_w4p[i];
    if (t < 16) b4s[t] = g_b4q[t];

    const float4* a3 = (const float4*)(g_act3 + img * 1024);
    #pragma unroll
    for (int i = 0; i < 4; i++) {
        int idx4 = st + 64 * i;
        float4 v = a3[idx4];
        int pin = idx4 >> 2, ic4 = idx4 & 3;
        int c0 = min(127, __float2int_rn(v.x * s3));
        int c1 = min(127, __float2int_rn(v.y * s3));
        int c2 = min(127, __float2int_rn(v.z * s3));
        int c3 = min(127, __float2int_rn(v.w * s3));
        a3p[li][pin * 5 + ic4] = c0 | (c1<<8) | (c2<<16) | (c3<<24);
    }
    __syncthreads();

    const int pix = st >> 2, ocq = st & 3;
    const int oh = pix >> 2, ow = pix & 3;
    int4 acc = make_int4(0, 0, 0, 0);
    for (int r = 0; r < 3; r++) {
        int ih = 2*oh - 1 + r;
        if ((unsigned)ih >= 8u) continue;
        for (int s = 0; s < 3; s++) {
            int iw = 2*ow - 1 + s;
            if ((unsigned)iw >= 8u) continue;
            int pin = ih * 8 + iw, tap = r * 3 + s;
            #pragma unroll
            for (int ic4 = 0; ic4 < 4; ic4++) {
                int a = a3p[li][pin * 5 + ic4];
                int4 w = ((const int4*)w4s)[tap * 16 + ic4 * 4 + ocq];
                acc.x = __dp4a(a, w.x, acc.x); acc.y = __dp4a(a, w.y, acc.y);
                acc.z = __dp4a(a, w.z, acc.z); acc.w = __dp4a(a, w.w, acc.w);
            }
        }
    }
    const float sw4 = mkscale(4, 127.f);
    const float inv4 = (s3 > 0.f && sw4 > 0.f) ? 1.f / (s3 * sw4) : 0.f;
    float4 c;
    c.x = fminf(fmaxf((float)acc.x * inv4 + b4s[ocq*4+0], 0.f), 10.f);
    c.y = fminf(fmaxf((float)acc.y * inv4 + b4s[ocq*4+1], 0.f), 10.f);
    c.z = fminf(fmaxf((float)acc.z * inv4 + b4s[ocq*4+2], 0.f), 10.f);
    c.w = fminf(fmaxf((float)acc.w * inv4 + b4s[ocq*4+3], 0.f), 10.f);
    *(float4*)(g_act4 + img * 256 + pix * 16 + ocq * 4) = c;
    float lm = fmaxf(fmaxf(c.x, c.y), fmaxf(c.z, c.w));
    blockamax<8>(16, lm, redm, t);
}

// Stage 5: conv5(16->64,1x1) dp4a + b5 + skip2 -> clip -> act5 ; 2 images / block
__global__ void __launch_bounds__(256) k_stage5()
{
    __shared__ __align__(16) int a4p[2][16 * 5];
    __shared__ __align__(16) int w5s[256];
    __shared__ __align__(16) float b5s[64];
    __shared__ float redm[8];
    const int t = threadIdx.x;
    const int li = t >> 7, st = t & 127;
    const int img = blockIdx.x * 2 + li;
    const float m4 = ldmax(16);
    const float s4 = m4 > 0.f ? 127.f / m4 : 0.f;

    if (t < 64) ((int4*)w5s)[t] = ((const int4*)g_w5p)[t];
    if (t >= 64 && t < 128) b5s[t - 64] = g_b5q[t - 64];

    const float4* a4 = (const float4*)(g_act4 + img * 256);
    if (st < 64) {
        float4 v = a4[st];
        int pin = st >> 2, ic4 = st & 3;
        int c0 = min(127, __float2int_rn(v.x * s4));
        int c1 = min(127, __float2int_rn(v.y * s4));
        int c2 = min(127, __float2int_rn(v.z * s4));
        int c3 = min(127, __float2int_rn(v.w * s4));
        a4p[li][pin * 5 + ic4] = c0 | (c1<<8) | (c2<<16) | (c3<<24);
    }
    __syncthreads();

    const int pix = st >> 3, ocg = st & 7;
    int acc[8];
    #pragma unroll
    for (int k = 0; k < 8; k++) acc[k] = 0;
    #pragma unroll
    for (int ic4 = 0; ic4 < 4; ic4++) {
        int a = a4p[li][pix * 5 + ic4];
        int4 w0 = ((const int4*)w5s)[ic4 * 16 + ocg * 2];
        int4 w1 = ((const int4*)w5s)[ic4 * 16 + ocg * 2 + 1];
        acc[0] = __dp4a(a, w0.x, acc[0]); acc[1] = __dp4a(a, w0.y, acc[1]);
        acc[2] = __dp4a(a, w0.z, acc[2]); acc[3] = __dp4a(a, w0.w, acc[3]);
        acc[4] = __dp4a(a, w1.x, acc[4]); acc[5] = __dp4a(a, w1.y, acc[5]);
        acc[6] = __dp4a(a, w1.z, acc[6]); acc[7] = __dp4a(a, w1.w, acc[7]);
    }
    const float sw5 = mkscale(5, 127.f);
    const float invw = (s4 > 0.f && sw5 > 0.f) ? 1.f / (s4 * sw5) : 0.f;
    const float m2 = ldmax(14);
    const float s2 = m2 > 0.f ? 127.f / m2 : 0.f;
    const float inv2 = s2 > 0.f ? 1.f / s2 : 0.f;

    const int* skp = g_skip2p + (img * 16 + pix) * 16 + ocg * 2;
    int sk0 = skp[0], sk1 = skp[1];
    float o[8], lm = 0.f;
    #pragma unroll
    for (int k = 0; k < 8; k++) {
        int code = (k < 4 ? (sk0 >> (8 * k)) : (sk1 >> (8 * (k - 4)))) & 255;
        float y = (float)acc[k] * invw + b5s[ocg*8+k] + (float)code * inv2;
        o[k] = fminf(fmaxf(y, 0.f), 10.f);
        lm = fmaxf(lm, o[k]);
    }
    float* dst = g_act5 + (img * 16 + pix) * 64 + ocg * 8;
    ((float4*)dst)[0] = make_float4(o[0], o[1], o[2], o[3]);
    ((float4*)dst)[1] = make_float4(o[4], o[5], o[6], o[7]);
    blockamax<8>(17, lm, redm, t);
}

// Final: quant(act5) -> mean(4x4) -> linear(64->10). 4 images / block.
__global__ void __launch_bounds__(256) k_final(float* __restrict__ out)
{
    __shared__ __align__(16) float sv[4][64];
    __shared__ __align__(16) float wls[640];
    const int t = threadIdx.x;
    const int li = t >> 6, sub = t & 63;
    const int img = blockIdx.x * 4 + li;
    const float m5 = ldmax(17);
    const float s5 = m5 > 0.f ? 127.f / m5 : 0.f;
    const float inv5 = s5 > 0.f ? 1.f / s5 : 0.f;
    for (int i = t; i < 640; i += 256) wls[i] = g_wlq[i];
    const float* a5 = g_act5 + img * 1024;
    int acc = 0;
    #pragma unroll
    for (int p = 0; p < 16; p++)
        acc += min(127, __float2int_rn(a5[p * 64 + sub] * s5));
    sv[li][sub] = (float)acc * inv5 * (1.f / 16.f);
    __syncthreads();
    if (t < 40) {
        int li3 = t / 10, o = t - li3 * 10;
        float r = g_blq[o];
        const float* svr = sv[li3];
        const float* wr = wls + o * 64;
        #pragma unroll 8
        for (int c = 0; c < 64; c++) r += svr[c] * wr[c];
        out[(blockIdx.x * 4 + li3) * 10 + o] = r;
    }
}

extern "C" void kernel_launch(void* const* d_in, const int* in_sizes, int n_in,
                              void* d_out, int out_size) {
    const float* x  = (const float*)d_in[0];
    const float* w1 = (const float*)d_in[1];  const float* b1 = (const float*)d_in[2];
    const float* w2 = (const float*)d_in[3];  const float* b2 = (const float*)d_in[4];
    const float* w3 = (const float*)d_in[5];  const float* b3 = (const float*)d_in[6];
    const float* w4 = (const float*)d_in[7];  const float* b4 = (const float*)d_in[8];
    const float* w5 = (const float*)d_in[9];  const float* b5 = (const float*)d_in[10];
    const float* wl = (const float*)d_in[11]; const float* bl = (const float*)d_in[12];

    k_reset<<<1, 32>>>();
    k_absmax<<<524, 256>>>((const float4*)x, w1, w2, w3, w4, w5, wl,
                           b1, b2, b3, b4, b5, bl);
    k_wprep<<<2, 256>>>(w1, w2, w3, w4, w5, wl, b1, b2, b3, b4, b5, bl);
    k_stage1<<<B_IMG, 256>>>(x);
    k_stage2<<<B_IMG / 2, 512>>>();
    k_stage3<<<B_IMG, 256>>>();
    k_stage4<<<B_IMG / 4, 256>>>();
    k_stage5<<<B_IMG / 2, 256>>>();
    k_final<<<B_IMG / 4, 256>>>((float*)d_out);
}

// round 14
// speedup vs baseline: 3.6362x; 1.1084x over previous
#include <cuda_runtime.h>
#include <cstdint>

#define B_IMG 4096

// slots: 0:x 1..5:w1..w5 6:wl 7..11:b1..b5 12:bl 13..17:act1..act5
__device__ unsigned g_maxbits[18];
__device__ __align__(16) float g_act2 [B_IMG * 4096];   // [b][64 pix][64 ch]
__device__ __align__(16) float g_act3 [B_IMG * 1024];   // [b][64 pix][16 ch]
__device__ __align__(16) int   g_skip2p[B_IMG * 256];   // [b][16 pix][16 ic4] packed codes
__device__ __align__(16) float g_act4 [B_IMG * 256];    // [b][16 pix][16 ch]
__device__ __align__(16) float g_act5 [B_IMG * 1024];   // [b][16 pix][64 ch]

// pre-quantized parameters (filled once per launch by k_wprep)
__device__ __align__(16) int   g_w2p[4608];   // [oc=64][tap*8+ic4=72] packed codes
__device__ __align__(16) int   g_w1p[96];     // [r=3][oc=32] bytes (w0,w1,w2,0)
__device__ __align__(16) int   g_w3p[256];    // [ic4=16][oc=16]
__device__ __align__(16) int   g_w4p[576];    // [tap=9][ic4=4][oc=16]
__device__ __align__(16) int   g_w5p[256];    // [ic4=4][oc=64]
__device__ __align__(16) float g_wlq[640];
__device__ __align__(16) float g_b1q[32];
__device__ __align__(16) float g_b2q[64];
__device__ __align__(16) float g_b3q[16];
__device__ __align__(16) float g_b4q[16];
__device__ __align__(16) float g_b5q[64];
__device__ __align__(16) float g_blq[12];

__device__ __forceinline__ float ldmax(int i) { return __uint_as_float(g_maxbits[i]); }
__device__ __forceinline__ void amaxf(int i, float v) {
    atomicMax(&g_maxbits[i], __float_as_uint(v));
}
__device__ __forceinline__ float warpmax(float v) {
    #pragma unroll
    for (int o = 16; o > 0; o >>= 1) v = fmaxf(v, __shfl_xor_sync(0xffffffffu, v, o));
    return v;
}
// block-level max -> ONE atomic per block
template<int NW>
__device__ __forceinline__ void blockamax(int slot, float lm, float* redm, int t) {
    lm = warpmax(lm);
    if ((t & 31) == 0) redm[t >> 5] = lm;
    __syncthreads();
    if (t == 0) {
        float mm = redm[0];
        #pragma unroll
        for (int i = 1; i < NW; i++) mm = fmaxf(mm, redm[i]);
        amaxf(slot, mm);
    }
}
__device__ __forceinline__ float mkscale(int slot, float maxv) {
    float m = ldmax(slot);
    return m > 0.f ? maxv / m : 0.f;
}
__device__ __forceinline__ int qcode(float x, float s, int lo, int hi) {
    return max(lo, min(hi, __float2int_rn(x * s)));
}
__device__ __forceinline__ float dequant1(float x, float s, float lo, float hi) {
    if (s <= 0.f) return 0.f;
    return fminf(fmaxf(rintf(x * s), lo), hi) / s;
}
// int8 tensor-core mma: D(16x8,s32) += A(16x32,s8) * B(32x8,s8)
__device__ __forceinline__ void mma_s8(int* c, int a0, int a1, int a2, int a3,
                                       int b0, int b1) {
    asm volatile(
        "mma.sync.aligned.m16n8k32.row.col.s32.s8.s8.s32 "
        "{%0,%1,%2,%3}, {%4,%5,%6,%7}, {%8,%9}, {%0,%1,%2,%3};"
        : "+r"(c[0]), "+r"(c[1]), "+r"(c[2]), "+r"(c[3])
        : "r"(a0), "r"(a1), "r"(a2), "r"(a3), "r"(b0), "r"(b1));
}

__global__ void k_reset() { if (threadIdx.x < 18) g_maxbits[threadIdx.x] = 0u; }

// blocks 0..511: max|x| ; blocks 512..523: per-param max
__global__ void __launch_bounds__(256) k_absmax(
    const float4* __restrict__ x,
    const float* w1, const float* w2, const float* w3, const float* w4, const float* w5,
    const float* wl, const float* b1, const float* b2, const float* b3, const float* b4,
    const float* b5, const float* bl)
{
    __shared__ float redm[8];
    if (blockIdx.x < 512) {
        const int n4 = B_IMG * 1024 / 4;
        float m = 0.f;
        for (int i = blockIdx.x * 256 + threadIdx.x; i < n4; i += 512 * 256) {
            float4 v = x[i];
            m = fmaxf(m, fmaxf(fmaxf(fabsf(v.x), fabsf(v.y)), fmaxf(fabsf(v.z), fabsf(v.w))));
        }
        blockamax<8>(0, m, redm, threadIdx.x);
    } else {
        const float* ptrs[12] = {w1, w2, w3, w4, w5, wl, b1, b2, b3, b4, b5, bl};
        const int sizes[12]   = {288, 18432, 1024, 2304, 1024, 640, 32, 64, 16, 16, 64, 10};
        int blk = blockIdx.x - 512;
        const float* p = ptrs[blk];
        int n = sizes[blk];
        float m = 0.f;
        for (int i = threadIdx.x; i < n; i += 256) m = fmaxf(m, fabsf(p[i]));
        blockamax<8>(blk + 1, m, redm, threadIdx.x);
    }
}

// one-time parameter quantization/packing
__global__ void __launch_bounds__(256) k_wprep(
    const float* __restrict__ w1, const float* __restrict__ w2, const float* __restrict__ w3,
    const float* __restrict__ w4, const float* __restrict__ w5, const float* __restrict__ wl,
    const float* __restrict__ b1, const float* __restrict__ b2, const float* __restrict__ b3,
    const float* __restrict__ b4, const float* __restrict__ b5, const float* __restrict__ bl)
{
    const int t = threadIdx.x;
    if (blockIdx.x == 0) {
        const float sw = mkscale(2, 127.f);
        for (int i = t; i < 4608; i += 256) {
            int oc = i / 72, k = i - oc * 72, tap = k >> 3, ic4 = k & 7;
            int p = 0;
            #pragma unroll
            for (int j = 0; j < 4; j++)
                p |= (qcode(w2[oc * 288 + (ic4 * 4 + j) * 9 + tap], sw, -127, 127) & 255) << (8 * j);
            g_w2p[i] = p;
        }
    } else {
        {   // w1p: [r][oc], bytes = (w0,w1,w2,0)
            const float s = mkscale(1, 127.f);
            if (t < 96) {
                int r = t >> 5, oc = t & 31, p = 0;
                #pragma unroll
                for (int j = 0; j < 3; j++)
                    p |= (qcode(w1[oc * 9 + r * 3 + j], s, -127, 127) & 255) << (8 * j);
                g_w1p[t] = p;
            }
        }
        {   // w3p: [ic4][oc=16]
            const float s = mkscale(3, 127.f);
            for (int i = t; i < 256; i += 256) {
                int ic4 = i >> 4, oc = i & 15, p = 0;
                #pragma unroll
                for (int j = 0; j < 4; j++)
                    p |= (qcode(w3[oc * 64 + ic4 * 4 + j], s, -127, 127) & 255) << (8 * j);
                g_w3p[i] = p;
            }
        }
        {   // w4p: [tap][ic4][oc=16]
            const float s = mkscale(4, 127.f);
            for (int i = t; i < 576; i += 256) {
                int oc = i & 15, ic4 = (i >> 4) & 3, tap = i >> 6, p = 0;
                #pragma unroll
                for (int j = 0; j < 4; j++)
                    p |= (qcode(w4[oc * 144 + (ic4 * 4 + j) * 9 + tap], s, -127, 127) & 255) << (8 * j);
                g_w4p[i] = p;
            }
        }
        {   // w5p: [ic4][oc=64]
            const float s = mkscale(5, 127.f);
            for (int i = t; i < 256; i += 256) {
                int ic4 = i >> 6, oc = i & 63, p = 0;
                #pragma unroll
                for (int j = 0; j < 4; j++)
                    p |= (qcode(w5[oc * 16 + ic4 * 4 + j], s, -127, 127) & 255) << (8 * j);
                g_w5p[i] = p;
            }
        }
        {   const float s = mkscale(6, 127.f);
            for (int i = t; i < 640; i += 256) g_wlq[i] = dequant1(wl[i], s, -127.f, 127.f); }
        {   const float s = mkscale(7, 32767.f);
            if (t < 32) g_b1q[t] = dequant1(b1[t], s, -32767.f, 32767.f); }
        {   const float s = mkscale(8, 32767.f);
            if (t < 64) g_b2q[t] = dequant1(b2[t], s, -32767.f, 32767.f); }
        {   const float s = mkscale(9, 32767.f);
            if (t < 16) g_b3q[t] = dequant1(b3[t], s, -32767.f, 32767.f); }
        {   const float s = mkscale(10, 32767.f);
            if (t < 16) g_b4q[t] = dequant1(b4[t], s, -32767.f, 32767.f); }
        {   const float s = mkscale(11, 32767.f);
            if (t < 64) g_b5q[t] = dequant1(b5[t], s, -32767.f, 32767.f); }
        {   const float s = mkscale(12, 32767.f);
            if (t < 10) g_blq[t] = dequant1(bl[t], s, -32767.f, 32767.f); }
    }
}

// k_max1: conv1 recompute pass producing ONLY max(act1) -> slot 13. No stores.
// Quantizes w1/b1 in-block (identical formulas to k_wprep -> identical codes).
__global__ void __launch_bounds__(256, 6) k_max1(
    const float* __restrict__ x, const float* __restrict__ w1g, const float* __restrict__ b1g)
{
    __shared__ __align__(16) signed char xsb[33 * 40];
    __shared__ __align__(16) int w1s[96];
    __shared__ __align__(16) float b1s[32];
    __shared__ float redm[8];
    const int b = blockIdx.x, t = threadIdx.x;
    const float sx = mkscale(0, 127.f);
    const float sw = mkscale(1, 127.f);
    const float inv = (sx > 0.f && sw > 0.f) ? 1.f / (sx * sw) : 0.f;

    for (int i = t; i < 330; i += 256) ((int*)xsb)[i] = 0;
    if (t < 96) {
        int r = t >> 5, oc = t & 31, p = 0;
        #pragma unroll
        for (int j = 0; j < 3; j++)
            p |= (qcode(w1g[oc * 9 + r * 3 + j], sw, -127, 127) & 255) << (8 * j);
        w1s[t] = p;
    }
    if (t < 32) b1s[t] = dequant1(b1g[t], mkscale(7, 32767.f), -32767.f, 32767.f);
    __syncthreads();

    {
        float4 v = ((const float4*)(x + b * 1024))[t];
        int h = t >> 3, w0 = (t & 7) * 4;
        int c0 = qcode(v.x, sx, -127, 127) & 255;
        int c1 = qcode(v.y, sx, -127, 127) & 255;
        int c2 = qcode(v.z, sx, -127, 127) & 255;
        int c3 = qcode(v.w, sx, -127, 127) & 255;
        *(int*)(xsb + (h + 1) * 40 + 4 + w0) = c0 | (c1 << 8) | (c2 << 16) | (c3 << 24);
    }
    __syncthreads();

    const int half = t & 1;
    const int pix0 = t >> 1;
    const int* xw = (const int*)xsb;
    float lm = 0.f;
    #pragma unroll
    for (int it = 0; it < 2; it++) {
        const int pix = pix0 + it * 128;
        const int oh = pix >> 4, ow = pix & 15;
        int acc[16];
        #pragma unroll
        for (int o = 0; o < 16; o++) acc[o] = 0;
        #pragma unroll
        for (int r = 0; r < 3; r++) {
            int rowb = (2 * oh + r) * 40 + 4 + 2 * ow - 1;
            int wi = rowb >> 2, off = rowb & 3;
            int a = __byte_perm(xw[wi], xw[wi + 1], 0x3210 + off * 0x1111);
            const int4* wr = (const int4*)&w1s[r * 32 + half * 16];
            #pragma unroll
            for (int o4 = 0; o4 < 4; o4++) {
                int4 wv = wr[o4];
                acc[o4*4+0] = __dp4a(a, wv.x, acc[o4*4+0]);
                acc[o4*4+1] = __dp4a(a, wv.y, acc[o4*4+1]);
                acc[o4*4+2] = __dp4a(a, wv.z, acc[o4*4+2]);
                acc[o4*4+3] = __dp4a(a, wv.w, acc[o4*4+3]);
            }
        }
        #pragma unroll
        for (int o = 0; o < 16; o++) {
            float c = fminf(fmaxf((float)acc[o] * inv + b1s[half*16 + o], 0.f), 10.f);
            lm = fmaxf(lm, c);
        }
    }
    blockamax<8>(13, lm, redm, t);
}

// Fused stage1+2: conv1 -> quantize act1 codes directly into smem halo tile,
// skip1 pooled in smem, then conv2 via int8 mma.sync. act1 never hits DRAM.
// 2 images/block, 512 threads.
__global__ void __launch_bounds__(512) k_stage12(const float* __restrict__ x)
{
    __shared__ __align__(16) int xsbi[2][336];      // byte tile per image (33*40 B)
    __shared__ __align__(16) int ap[2][18 * 145];   // act1 codes, halo'd
    __shared__ __align__(16) int ws[64 * 76];       // conv2 weights [oc][tap*8+ic4]
    __shared__ __align__(16) int w1s[96];
    __shared__ __align__(16) float b1s[32];
    __shared__ __align__(16) float skip1s[2][64];
    __shared__ float redm[16];
    const int t = threadIdx.x;
    const int b0img = blockIdx.x * 2;
    const float sx = mkscale(0, 127.f);
    const float sw1 = mkscale(1, 127.f);
    const float inv1 = (sx > 0.f && sw1 > 0.f) ? 1.f / (sx * sw1) : 0.f;
    const float invx = sx > 0.f ? 1.f / sx : 0.f;
    const float m1 = ldmax(13);
    const float s1 = m1 > 0.f ? 127.f / m1 : 0.f;

    for (int i = t; i < 4608; i += 512) {
        int oc = i / 72, k = i - oc * 72;
        ws[oc * 76 + k] = g_w2p[i];
    }
    for (int i = t; i < 2 * 2610; i += 512) ((int*)ap)[i] = 0;
    for (int i = t; i < 672; i += 512) ((int*)xsbi)[i] = 0;
    if (t < 96) w1s[t] = g_w1p[t];
    if (t >= 128 && t < 160) b1s[t - 128] = g_b1q[t - 128];
    __syncthreads();

    {   // quantize x into both byte tiles
        const int li = t >> 8, st = t & 255;
        float4 v = ((const float4*)(x + (b0img + li) * 1024))[st];
        int h = st >> 3, w0 = (st & 7) * 4;
        int c0 = qcode(v.x, sx, -127, 127) & 255;
        int c1 = qcode(v.y, sx, -127, 127) & 255;
        int c2 = qcode(v.z, sx, -127, 127) & 255;
        int c3 = qcode(v.w, sx, -127, 127) & 255;
        *(int*)((signed char*)xsbi[li] + (h + 1) * 40 + 4 + w0) =
            c0 | (c1 << 8) | (c2 << 16) | (c3 << 24);
    }
    __syncthreads();

    if (t < 128) {  // skip1: maxpool(5,4,2) of x codes
        int li = t >> 6, pos = t & 63;
        int oh = pos >> 3, ow = pos & 7;
        const signed char* xb = (const signed char*)xsbi[li];
        int m = -128;
        int h0 = max(0, 4 * oh - 2), h1 = min(31, 4 * oh + 2);
        int w0 = max(0, 4 * ow - 2), w1i = min(31, 4 * ow + 2);
        for (int ih = h0; ih <= h1; ih++)
            for (int iw = w0; iw <= w1i; iw++)
                m = max(m, (int)xb[(ih + 1) * 40 + 4 + iw]);
        skip1s[li][pos] = (float)m * invx;
    }

    {   // conv1 + quantize -> ap. task = (li, pix, half) over two half-iterations
        const int li = t >> 8, pix = t & 255;
        const int oh = pix >> 4, ow = pix & 15;
        const int* xw = (const int*)xsbi[li];
        #pragma unroll
        for (int half = 0; half < 2; half++) {
            int acc[16];
            #pragma unroll
            for (int o = 0; o < 16; o++) acc[o] = 0;
            #pragma unroll
            for (int r = 0; r < 3; r++) {
                int rowb = (2 * oh + r) * 40 + 4 + 2 * ow - 1;
                int wi = rowb >> 2, off = rowb & 3;
                int a = __byte_perm(xw[wi], xw[wi + 1], 0x3210 + off * 0x1111);
                const int4* wr = (const int4*)&w1s[r * 32 + half * 16];
                #pragma unroll
                for (int o4 = 0; o4 < 4; o4++) {
                    int4 wv = wr[o4];
                    acc[o4*4+0] = __dp4a(a, wv.x, acc[o4*4+0]);
                    acc[o4*4+1] = __dp4a(a, wv.y, acc[o4*4+1]);
                    acc[o4*4+2] = __dp4a(a, wv.z, acc[o4*4+2]);
                    acc[o4*4+3] = __dp4a(a, wv.w, acc[o4*4+3]);
                }
            }
            #pragma unroll
            for (int j = 0; j < 4; j++) {
                int cc[4];
                #pragma unroll
                for (int k = 0; k < 4; k++) {
                    float c = fminf(fmaxf((float)acc[j*4+k] * inv1 + b1s[half*16 + j*4+k], 0.f), 10.f);
                    cc[k] = min(127, __float2int_rn(c * s1));
                }
                ap[li][(oh + 1) * 145 + (ow + 1) * 8 + half * 4 + j] =
                    cc[0] | (cc[1] << 8) | (cc[2] << 16) | (cc[3] << 24);
            }
        }
    }
    __syncthreads();

    // conv2 mma phase: 16 warps, li2 = w>>3, mt = (w>>1)&3, nh = w&1
    const int w = t >> 5, lane = t & 31;
    const int li2 = w >> 3, mt = (w >> 1) & 3, nh = w & 1;
    const int b = b0img + li2;
    const int r = lane >> 2, c4 = lane & 3;
    const int pix = mt * 16 + r;
    const int oh = pix >> 3, ow = pix & 7;

    int acc[4][4];
    #pragma unroll
    for (int j = 0; j < 4; j++)
        #pragma unroll
        for (int k = 0; k < 4; k++) acc[j][k] = 0;

    #pragma unroll
    for (int kc = 0; kc < 9; kc++) {
        const int tr = kc / 3, tc = kc - tr * 3;
        const int abase = (2 * oh + tr) * 145 + (2 * ow + tc) * 8;
        int a0 = ap[li2][abase + c4];
        int a1 = ap[li2][abase + 290 + c4];
        int a2 = ap[li2][abase + c4 + 4];
        int a3 = ap[li2][abase + 290 + c4 + 4];
        #pragma unroll
        for (int j = 0; j < 4; j++) {
            int ntg = nh * 4 + j;
            int wb = (ntg * 8 + r) * 76 + kc * 8;
            mma_s8(acc[j], a0, a1, a2, a3, ws[wb + c4], ws[wb + c4 + 4]);
        }
    }

    const float sww = mkscale(2, 127.f);
    const float inv = (s1 > 0.f && sww > 0.f) ? 1.f / (s1 * sww) : 0.f;
    const float sk0 = skip1s[li2][pix];
    const float sk1 = skip1s[li2][pix + 8];
    float lm = 0.f;
    #pragma unroll
    for (int j = 0; j < 4; j++) {
        int oc = (nh * 4 + j) * 8 + 2 * c4;
        float y0 = fminf(fmaxf((float)acc[j][0] * inv + g_b2q[oc]     + sk0, 0.f), 10.f);
        float y1 = fminf(fmaxf((float)acc[j][1] * inv + g_b2q[oc + 1] + sk0, 0.f), 10.f);
        float y2 = fminf(fmaxf((float)acc[j][2] * inv + g_b2q[oc]     + sk1, 0.f), 10.f);
        float y3 = fminf(fmaxf((float)acc[j][3] * inv + g_b2q[oc + 1] + sk1, 0.f), 10.f);
        lm = fmaxf(lm, fmaxf(fmaxf(y0, y1), fmaxf(y2, y3)));
        *(float2*)(g_act2 + (b * 64 + pix)     * 64 + oc) = make_float2(y0, y1);
        *(float2*)(g_act2 + (b * 64 + pix + 8) * 64 + oc) = make_float2(y2, y3);
    }
    blockamax<16>(14, lm, redm, t);
}

// Stage 3: quant(act2) codes -> maxpool(3,2,1)=skip2 codes ; conv3(64->16,1x1) dp4a
__global__ void __launch_bounds__(256) k_stage3()
{
    __shared__ __align__(16) int cp[64 * 17];
    __shared__ __align__(16) int w3s[256];
    __shared__ __align__(16) float b3s[16];
    __shared__ float redm[8];
    const int b = blockIdx.x, t = threadIdx.x;
    const float m2 = ldmax(14);
    const float s2 = m2 > 0.f ? 127.f / m2 : 0.f;

    if (t < 64) ((int4*)w3s)[t] = ((const int4*)g_w3p)[t];
    if (t < 16) b3s[t] = g_b3q[t];

    const float4* a2 = (const float4*)(g_act2 + b * 4096);
    #pragma unroll
    for (int i = 0; i < 4; i++) {
        int idx4 = t + 256 * i;
        float4 v = a2[idx4];
        int pix = idx4 >> 4, ic4 = idx4 & 15;
        int c0 = min(127, __float2int_rn(v.x * s2));
        int c1 = min(127, __float2int_rn(v.y * s2));
        int c2 = min(127, __float2int_rn(v.z * s2));
        int c3 = min(127, __float2int_rn(v.w * s2));
        cp[pix * 17 + ic4] = c0 | (c1<<8) | (c2<<16) | (c3<<24);
    }
    __syncthreads();

    float lm;
    {
        int pos = t >> 2, ocq = t & 3;
        int4 acc = make_int4(0, 0, 0, 0);
        #pragma unroll
        for (int ic4 = 0; ic4 < 16; ic4++) {
            int a = cp[pos * 17 + ic4];
            int4 w = ((const int4*)w3s)[ic4 * 4 + ocq];
            acc.x = __dp4a(a, w.x, acc.x); acc.y = __dp4a(a, w.y, acc.y);
            acc.z = __dp4a(a, w.z, acc.z); acc.w = __dp4a(a, w.w, acc.w);
        }
        const float sw3 = mkscale(3, 127.f);
        const float inv3 = (s2 > 0.f && sw3 > 0.f) ? 1.f / (s2 * sw3) : 0.f;
        float4 c;
        c.x = fminf(fmaxf((float)acc.x * inv3 + b3s[ocq*4+0], 0.f), 10.f);
        c.y = fminf(fmaxf((float)acc.y * inv3 + b3s[ocq*4+1], 0.f), 10.f);
        c.z = fminf(fmaxf((float)acc.z * inv3 + b3s[ocq*4+2], 0.f), 10.f);
        c.w = fminf(fmaxf((float)acc.w * inv3 + b3s[ocq*4+3], 0.f), 10.f);
        *(float4*)(g_act3 + (b * 64 + pos) * 16 + ocq * 4) = c;
        lm = fmaxf(fmaxf(c.x, c.y), fmaxf(c.z, c.w));
    }

    {
        int opix = t >> 4, ic4 = t & 15;
        int oh = opix >> 2, ow = opix & 3;
        int m = 0;
        int h0 = max(0, 2*oh-1), h1 = min(7, 2*oh+1);
        int w0 = max(0, 2*ow-1), w1i = min(7, 2*ow+1);
        for (int ih = h0; ih <= h1; ih++)
            for (int iw = w0; iw <= w1i; iw++)
                m = __vmaxs4(m, cp[(ih * 8 + iw) * 17 + ic4]);
        g_skip2p[(b * 16 + opix) * 16 + ic4] = m;
    }
    blockamax<8>(15, lm, redm, t);
}

// Stage 4: conv4(16->16,3x3,s2) dp4a ; 4 images / block
__global__ void __launch_bounds__(256) k_stage4()
{
    __shared__ __align__(16) int a3p[4][64 * 5];
    __shared__ __align__(16) int w4s[576];
    __shared__ __align__(16) float b4s[16];
    __shared__ float redm[8];
    const int t = threadIdx.x;
    const int li = t >> 6, st = t & 63;
    const int img = blockIdx.x * 4 + li;
    const float m3 = ldmax(15);
    const float s3 = m3 > 0.f ? 127.f / m3 : 0.f;

    for (int i = t; i < 576; i += 256) w4s[i] = g_w4p[i];
    if (t < 16) b4s[t] = g_b4q[t];

    const float4* a3 = (const float4*)(g_act3 + img * 1024);
    #pragma unroll
    for (int i = 0; i < 4; i++) {
        int idx4 = st + 64 * i;
        float4 v = a3[idx4];
        int pin = idx4 >> 2, ic4 = idx4 & 3;
        int c0 = min(127, __float2int_rn(v.x * s3));
        int c1 = min(127, __float2int_rn(v.y * s3));
        int c2 = min(127, __float2int_rn(v.z * s3));
        int c3 = min(127, __float2int_rn(v.w * s3));
        a3p[li][pin * 5 + ic4] = c0 | (c1<<8) | (c2<<16) | (c3<<24);
    }
    __syncthreads();

    const int pix = st >> 2, ocq = st & 3;
    const int oh = pix >> 2, ow = pix & 3;
    int4 acc = make_int4(0, 0, 0, 0);
    for (int r = 0; r < 3; r++) {
        int ih = 2*oh - 1 + r;
        if ((unsigned)ih >= 8u) continue;
        for (int s = 0; s < 3; s++) {
            int iw = 2*ow - 1 + s;
            if ((unsigned)iw >= 8u) continue;
            int pin = ih * 8 + iw, tap = r * 3 + s;
            #pragma unroll
            for (int ic4 = 0; ic4 < 4; ic4++) {
                int a = a3p[li][pin * 5 + ic4];
                int4 w = ((const int4*)w4s)[tap * 16 + ic4 * 4 + ocq];
                acc.x = __dp4a(a, w.x, acc.x); acc.y = __dp4a(a, w.y, acc.y);
                acc.z = __dp4a(a, w.z, acc.z); acc.w = __dp4a(a, w.w, acc.w);
            }
        }
    }
    const float sw4 = mkscale(4, 127.f);
    const float inv4 = (s3 > 0.f && sw4 > 0.f) ? 1.f / (s3 * sw4) : 0.f;
    float4 c;
    c.x = fminf(fmaxf((float)acc.x * inv4 + b4s[ocq*4+0], 0.f), 10.f);
    c.y = fminf(fmaxf((float)acc.y * inv4 + b4s[ocq*4+1], 0.f), 10.f);
    c.z = fminf(fmaxf((float)acc.z * inv4 + b4s[ocq*4+2], 0.f), 10.f);
    c.w = fminf(fmaxf((float)acc.w * inv4 + b4s[ocq*4+3], 0.f), 10.f);
    *(float4*)(g_act4 + img * 256 + pix * 16 + ocq * 4) = c;
    float lm = fmaxf(fmaxf(c.x, c.y), fmaxf(c.z, c.w));
    blockamax<8>(16, lm, redm, t);
}

// Stage 5: conv5(16->64,1x1) dp4a + b5 + skip2 -> clip -> act5 ; 2 images / block
__global__ void __launch_bounds__(256) k_stage5()
{
    __shared__ __align__(16) int a4p[2][16 * 5];
    __shared__ __align__(16) int w5s[256];
    __shared__ __align__(16) float b5s[64];
    __shared__ float redm[8];
    const int t = threadIdx.x;
    const int li = t >> 7, st = t & 127;
    const int img = blockIdx.x * 2 + li;
    const float m4 = ldmax(16);
    const float s4 = m4 > 0.f ? 127.f / m4 : 0.f;

    if (t < 64) ((int4*)w5s)[t] = ((const int4*)g_w5p)[t];
    if (t >= 64 && t < 128) b5s[t - 64] = g_b5q[t - 64];

    const float4* a4 = (const float4*)(g_act4 + img * 256);
    if (st < 64) {
        float4 v = a4[st];
        int pin = st >> 2, ic4 = st & 3;
        int c0 = min(127, __float2int_rn(v.x * s4));
        int c1 = min(127, __float2int_rn(v.y * s4));
        int c2 = min(127, __float2int_rn(v.z * s4));
        int c3 = min(127, __float2int_rn(v.w * s4));
        a4p[li][pin * 5 + ic4] = c0 | (c1<<8) | (c2<<16) | (c3<<24);
    }
    __syncthreads();

    const int pix = st >> 3, ocg = st & 7;
    int acc[8];
    #pragma unroll
    for (int k = 0; k < 8; k++) acc[k] = 0;
    #pragma unroll
    for (int ic4 = 0; ic4 < 4; ic4++) {
        int a = a4p[li][pix * 5 + ic4];
        int4 w0 = ((const int4*)w5s)[ic4 * 16 + ocg * 2];
        int4 w1 = ((const int4*)w5s)[ic4 * 16 + ocg * 2 + 1];
        acc[0] = __dp4a(a, w0.x, acc[0]); acc[1] = __dp4a(a, w0.y, acc[1]);
        acc[2] = __dp4a(a, w0.z, acc[2]); acc[3] = __dp4a(a, w0.w, acc[3]);
        acc[4] = __dp4a(a, w1.x, acc[4]); acc[5] = __dp4a(a, w1.y, acc[5]);
        acc[6] = __dp4a(a, w1.z, acc[6]); acc[7] = __dp4a(a, w1.w, acc[7]);
    }
    const float sw5 = mkscale(5, 127.f);
    const float invw = (s4 > 0.f && sw5 > 0.f) ? 1.f / (s4 * sw5) : 0.f;
    const float m2 = ldmax(14);
    const float s2 = m2 > 0.f ? 127.f / m2 : 0.f;
    const float inv2 = s2 > 0.f ? 1.f / s2 : 0.f;

    const int* skp = g_skip2p + (img * 16 + pix) * 16 + ocg * 2;
    int sk0 = skp[0], sk1 = skp[1];
    float o[8], lm = 0.f;
    #pragma unroll
    for (int k = 0; k < 8; k++) {
        int code = (k < 4 ? (sk0 >> (8 * k)) : (sk1 >> (8 * (k - 4)))) & 255;
        float y = (float)acc[k] * invw + b5s[ocg*8+k] + (float)code * inv2;
        o[k] = fminf(fmaxf(y, 0.f), 10.f);
        lm = fmaxf(lm, o[k]);
    }
    float* dst = g_act5 + (img * 16 + pix) * 64 + ocg * 8;
    ((float4*)dst)[0] = make_float4(o[0], o[1], o[2], o[3]);
    ((float4*)dst)[1] = make_float4(o[4], o[5], o[6], o[7]);
    blockamax<8>(17, lm, redm, t);
}

// Final: quant(act5) -> mean(4x4) -> linear(64->10). 4 images / block.
__global__ void __launch_bounds__(256) k_final(float* __restrict__ out)
{
    __shared__ __align__(16) float sv[4][64];
    __shared__ __align__(16) float wls[640];
    const int t = threadIdx.x;
    const int li = t >> 6, sub = t & 63;
    const int img = blockIdx.x * 4 + li;
    const float m5 = ldmax(17);
    const float s5 = m5 > 0.f ? 127.f / m5 : 0.f;
    const float inv5 = s5 > 0.f ? 1.f / s5 : 0.f;
    for (int i = t; i < 640; i += 256) wls[i] = g_wlq[i];
    const float* a5 = g_act5 + img * 1024;
    int acc = 0;
    #pragma unroll
    for (int p = 0; p < 16; p++)
        acc += min(127, __float2int_rn(a5[p * 64 + sub] * s5));
    sv[li][sub] = (float)acc * inv5 * (1.f / 16.f);
    __syncthreads();
    if (t < 40) {
        int li3 = t / 10, o = t - li3 * 10;
        float r = g_blq[o];
        const float* svr = sv[li3];
        const float* wr = wls + o * 64;
        #pragma unroll 8
        for (int c = 0; c < 64; c++) r += svr[c] * wr[c];
        out[(blockIdx.x * 4 + li3) * 10 + o] = r;
    }
}

extern "C" void kernel_launch(void* const* d_in, const int* in_sizes, int n_in,
                              void* d_out, int out_size) {
    const float* x  = (const float*)d_in[0];
    const float* w1 = (const float*)d_in[1];  const float* b1 = (const float*)d_in[2];
    const float* w2 = (const float*)d_in[3];  const float* b2 = (const float*)d_in[4];
    const float* w3 = (const float*)d_in[5];  const float* b3 = (const float*)d_in[6];
    const float* w4 = (const float*)d_in[7];  const float* b4 = (const float*)d_in[8];
    const float* w5 = (const float*)d_in[9];  const float* b5 = (const float*)d_in[10];
    const float* wl = (const float*)d_in[11]; const float* bl = (const float*)d_in[12];

    k_reset<<<1, 32>>>();
    k_absmax<<<524, 256>>>((const float4*)x, w1, w2, w3, w4, w5, wl,
                           b1, b2, b3, b4, b5, bl);
    k_wprep<<<2, 256>>>(w1, w2, w3, w4, w5, wl, b1, b2, b3, b4, b5, bl);
    k_max1<<<B_IMG, 256>>>(x, w1, b1);
    k_stage12<<<B_IMG / 2, 512>>>(x);
    k_stage3<<<B_IMG, 256>>>();
    k_stage4<<<B_IMG / 4, 256>>>();
    k_stage5<<<B_IMG / 2, 256>>>();
    k_final<<<B_IMG / 4, 256>>>((float*)d_out);
}

// round 15
// speedup vs baseline: 3.7405x; 1.0287x over previous
#include <cuda_runtime.h>
#include <cstdint>

#define B_IMG 4096

// slots: 0:x 1..5:w1..w5 6:wl 7..11:b1..b5 12:bl 13..17:act1..act5
__device__ unsigned g_maxbits[18];
__device__ __align__(16) float g_act2 [B_IMG * 4096];   // [b][64 pix][64 ch]
__device__ __align__(16) float g_act3 [B_IMG * 1024];   // [b][64 pix][16 ch]
__device__ __align__(16) int   g_skip2p[B_IMG * 256];   // [b][16 pix][16 ic4] packed codes
__device__ __align__(16) float g_act4 [B_IMG * 256];    // [b][16 pix][16 ch]
__device__ __align__(16) float g_act5 [B_IMG * 1024];   // [b][16 pix][64 ch]

// pre-quantized parameters (filled once per launch by k_wprep)
__device__ __align__(16) int   g_w2p[4608];   // [oc=64][tap*8+ic4=72] packed codes
__device__ __align__(16) int   g_w1p[96];     // [r=3][oc=32] bytes (w0,w1,w2,0)
__device__ __align__(16) int   g_w3p[256];    // [ic4=16][oc=16]
__device__ __align__(16) int   g_w4p[576];    // [tap=9][ic4=4][oc=16]
__device__ __align__(16) int   g_w5p[256];    // [ic4=4][oc=64]
__device__ __align__(16) float g_wlq[640];
__device__ __align__(16) float g_b1q[32];
__device__ __align__(16) float g_b2q[64];
__device__ __align__(16) float g_b3q[16];
__device__ __align__(16) float g_b4q[16];
__device__ __align__(16) float g_b5q[64];
__device__ __align__(16) float g_blq[12];

__device__ __forceinline__ float ldmax(int i) { return __uint_as_float(g_maxbits[i]); }
__device__ __forceinline__ void amaxf(int i, float v) {
    atomicMax(&g_maxbits[i], __float_as_uint(v));
}
__device__ __forceinline__ float warpmax(float v) {
    #pragma unroll
    for (int o = 16; o > 0; o >>= 1) v = fmaxf(v, __shfl_xor_sync(0xffffffffu, v, o));
    return v;
}
// block-level max -> ONE atomic per block
template<int NW>
__device__ __forceinline__ void blockamax(int slot, float lm, float* redm, int t) {
    lm = warpmax(lm);
    if ((t & 31) == 0) redm[t >> 5] = lm;
    __syncthreads();
    if (t == 0) {
        float mm = redm[0];
        #pragma unroll
        for (int i = 1; i < NW; i++) mm = fmaxf(mm, redm[i]);
        amaxf(slot, mm);
    }
}
__device__ __forceinline__ float mkscale(int slot, float maxv) {
    float m = ldmax(slot);
    return m > 0.f ? maxv / m : 0.f;
}
__device__ __forceinline__ int qcode(float x, float s, int lo, int hi) {
    return max(lo, min(hi, __float2int_rn(x * s)));
}
__device__ __forceinline__ float dequant1(float x, float s, float lo, float hi) {
    if (s <= 0.f) return 0.f;
    return fminf(fmaxf(rintf(x * s), lo), hi) / s;
}
// int8 tensor-core mma: D(16x8,s32) += A(16x32,s8) * B(32x8,s8)
__device__ __forceinline__ void mma_s8(int* c, int a0, int a1, int a2, int a3,
                                       int b0, int b1) {
    asm volatile(
        "mma.sync.aligned.m16n8k32.row.col.s32.s8.s8.s32 "
        "{%0,%1,%2,%3}, {%4,%5,%6,%7}, {%8,%9}, {%0,%1,%2,%3};"
        : "+r"(c[0]), "+r"(c[1]), "+r"(c[2]), "+r"(c[3])
        : "r"(a0), "r"(a1), "r"(a2), "r"(a3), "r"(b0), "r"(b1));
}

__global__ void k_reset() { if (threadIdx.x < 18) g_maxbits[threadIdx.x] = 0u; }

// blocks 0..511: max|x| ; blocks 512..523: per-param max
__global__ void __launch_bounds__(256) k_absmax(
    const float4* __restrict__ x,
    const float* w1, const float* w2, const float* w3, const float* w4, const float* w5,
    const float* wl, const float* b1, const float* b2, const float* b3, const float* b4,
    const float* b5, const float* bl)
{
    __shared__ float redm[8];
    if (blockIdx.x < 512) {
        const int n4 = B_IMG * 1024 / 4;
        float m = 0.f;
        for (int i = blockIdx.x * 256 + threadIdx.x; i < n4; i += 512 * 256) {
            float4 v = x[i];
            m = fmaxf(m, fmaxf(fmaxf(fabsf(v.x), fabsf(v.y)), fmaxf(fabsf(v.z), fabsf(v.w))));
        }
        blockamax<8>(0, m, redm, threadIdx.x);
    } else {
        const float* ptrs[12] = {w1, w2, w3, w4, w5, wl, b1, b2, b3, b4, b5, bl};
        const int sizes[12]   = {288, 18432, 1024, 2304, 1024, 640, 32, 64, 16, 16, 64, 10};
        int blk = blockIdx.x - 512;
        const float* p = ptrs[blk];
        int n = sizes[blk];
        float m = 0.f;
        for (int i = threadIdx.x; i < n; i += 256) m = fmaxf(m, fabsf(p[i]));
        blockamax<8>(blk + 1, m, redm, threadIdx.x);
    }
}

// one-time parameter quantization/packing
__global__ void __launch_bounds__(256) k_wprep(
    const float* __restrict__ w1, const float* __restrict__ w2, const float* __restrict__ w3,
    const float* __restrict__ w4, const float* __restrict__ w5, const float* __restrict__ wl,
    const float* __restrict__ b1, const float* __restrict__ b2, const float* __restrict__ b3,
    const float* __restrict__ b4, const float* __restrict__ b5, const float* __restrict__ bl)
{
    const int t = threadIdx.x;
    if (blockIdx.x == 0) {
        const float sw = mkscale(2, 127.f);
        for (int i = t; i < 4608; i += 256) {
            int oc = i / 72, k = i - oc * 72, tap = k >> 3, ic4 = k & 7;
            int p = 0;
            #pragma unroll
            for (int j = 0; j < 4; j++)
                p |= (qcode(w2[oc * 288 + (ic4 * 4 + j) * 9 + tap], sw, -127, 127) & 255) << (8 * j);
            g_w2p[i] = p;
        }
    } else {
        {   // w1p: [r][oc], bytes = (w0,w1,w2,0)
            const float s = mkscale(1, 127.f);
            if (t < 96) {
                int r = t >> 5, oc = t & 31, p = 0;
                #pragma unroll
                for (int j = 0; j < 3; j++)
                    p |= (qcode(w1[oc * 9 + r * 3 + j], s, -127, 127) & 255) << (8 * j);
                g_w1p[t] = p;
            }
        }
        {   // w3p: [ic4][oc=16]
            const float s = mkscale(3, 127.f);
            for (int i = t; i < 256; i += 256) {
                int ic4 = i >> 4, oc = i & 15, p = 0;
                #pragma unroll
                for (int j = 0; j < 4; j++)
                    p |= (qcode(w3[oc * 64 + ic4 * 4 + j], s, -127, 127) & 255) << (8 * j);
                g_w3p[i] = p;
            }
        }
        {   // w4p: [tap][ic4][oc=16]
            const float s = mkscale(4, 127.f);
            for (int i = t; i < 576; i += 256) {
                int oc = i & 15, ic4 = (i >> 4) & 3, tap = i >> 6, p = 0;
                #pragma unroll
                for (int j = 0; j < 4; j++)
                    p |= (qcode(w4[oc * 144 + (ic4 * 4 + j) * 9 + tap], s, -127, 127) & 255) << (8 * j);
                g_w4p[i] = p;
            }
        }
        {   // w5p: [ic4][oc=64]
            const float s = mkscale(5, 127.f);
            for (int i = t; i < 256; i += 256) {
                int ic4 = i >> 6, oc = i & 63, p = 0;
                #pragma unroll
                for (int j = 0; j < 4; j++)
                    p |= (qcode(w5[oc * 16 + ic4 * 4 + j], s, -127, 127) & 255) << (8 * j);
                g_w5p[i] = p;
            }
        }
        {   const float s = mkscale(6, 127.f);
            for (int i = t; i < 640; i += 256) g_wlq[i] = dequant1(wl[i], s, -127.f, 127.f); }
        {   const float s = mkscale(7, 32767.f);
            if (t < 32) g_b1q[t] = dequant1(b1[t], s, -32767.f, 32767.f); }
        {   const float s = mkscale(8, 32767.f);
            if (t < 64) g_b2q[t] = dequant1(b2[t], s, -32767.f, 32767.f); }
        {   const float s = mkscale(9, 32767.f);
            if (t < 16) g_b3q[t] = dequant1(b3[t], s, -32767.f, 32767.f); }
        {   const float s = mkscale(10, 32767.f);
            if (t < 16) g_b4q[t] = dequant1(b4[t], s, -32767.f, 32767.f); }
        {   const float s = mkscale(11, 32767.f);
            if (t < 64) g_b5q[t] = dequant1(b5[t], s, -32767.f, 32767.f); }
        {   const float s = mkscale(12, 32767.f);
            if (t < 10) g_blq[t] = dequant1(bl[t], s, -32767.f, 32767.f); }
    }
}

// k_max1: conv1 recompute producing ONLY max(act1) -> slot 13.
// Integer per-channel max first (affine+clip monotone in acc), float convert once.
__global__ void __launch_bounds__(256, 6) k_max1(
    const float* __restrict__ x, const float* __restrict__ w1g, const float* __restrict__ b1g)
{
    __shared__ __align__(16) signed char xsb[33 * 40];
    __shared__ __align__(16) int w1s[96];
    __shared__ __align__(16) float b1s[32];
    __shared__ float redm[8];
    const int b = blockIdx.x, t = threadIdx.x;
    const float sx = mkscale(0, 127.f);
    const float sw = mkscale(1, 127.f);
    const float inv = (sx > 0.f && sw > 0.f) ? 1.f / (sx * sw) : 0.f;

    for (int i = t; i < 330; i += 256) ((int*)xsb)[i] = 0;
    if (t < 96) {
        int r = t >> 5, oc = t & 31, p = 0;
        #pragma unroll
        for (int j = 0; j < 3; j++)
            p |= (qcode(w1g[oc * 9 + r * 3 + j], sw, -127, 127) & 255) << (8 * j);
        w1s[t] = p;
    }
    if (t < 32) b1s[t] = dequant1(b1g[t], mkscale(7, 32767.f), -32767.f, 32767.f);
    __syncthreads();

    {
        float4 v = ((const float4*)(x + b * 1024))[t];
        int h = t >> 3, w0 = (t & 7) * 4;
        int c0 = qcode(v.x, sx, -127, 127) & 255;
        int c1 = qcode(v.y, sx, -127, 127) & 255;
        int c2 = qcode(v.z, sx, -127, 127) & 255;
        int c3 = qcode(v.w, sx, -127, 127) & 255;
        *(int*)(xsb + (h + 1) * 40 + 4 + w0) = c0 | (c1 << 8) | (c2 << 16) | (c3 << 24);
    }
    __syncthreads();

    const int half = t & 1;
    const int pix0 = t >> 1;
    const int* xw = (const int*)xsb;
    int macc[16];
    #pragma unroll
    for (int o = 0; o < 16; o++) macc[o] = INT_MIN;
    #pragma unroll
    for (int it = 0; it < 2; it++) {
        const int pix = pix0 + it * 128;
        const int oh = pix >> 4, ow = pix & 15;
        int acc[16];
        #pragma unroll
        for (int o = 0; o < 16; o++) acc[o] = 0;
        #pragma unroll
        for (int r = 0; r < 3; r++) {
            int rowb = (2 * oh + r) * 40 + 4 + 2 * ow - 1;
            int wi = rowb >> 2, off = rowb & 3;
            int a = __byte_perm(xw[wi], xw[wi + 1], 0x3210 + off * 0x1111);
            const int4* wr = (const int4*)&w1s[r * 32 + half * 16];
            #pragma unroll
            for (int o4 = 0; o4 < 4; o4++) {
                int4 wv = wr[o4];
                acc[o4*4+0] = __dp4a(a, wv.x, acc[o4*4+0]);
                acc[o4*4+1] = __dp4a(a, wv.y, acc[o4*4+1]);
                acc[o4*4+2] = __dp4a(a, wv.z, acc[o4*4+2]);
                acc[o4*4+3] = __dp4a(a, wv.w, acc[o4*4+3]);
            }
        }
        #pragma unroll
        for (int o = 0; o < 16; o++) macc[o] = max(macc[o], acc[o]);
    }
    float lm = 0.f;
    #pragma unroll
    for (int o = 0; o < 16; o++) {
        float c = fminf(fmaxf((float)macc[o] * inv + b1s[half*16 + o], 0.f), 10.f);
        lm = fmaxf(lm, c);
    }
    blockamax<8>(13, lm, redm, t);
}

// Fused stage1+2: conv1 -> act1 codes in smem halo tile -> conv2 int8 mma.
// conv1 epilogue uses fused affine: code = clamp(rint(acc*ks + b*s1), 0, 127).
__global__ void __launch_bounds__(512) k_stage12(const float* __restrict__ x)
{
    __shared__ __align__(16) int xsbi[2][336];      // byte tile per image (33*40 B)
    __shared__ __align__(16) int ap[2][18 * 145];   // act1 codes, halo'd
    __shared__ __align__(16) int ws[64 * 76];       // conv2 weights [oc][tap*8+ic4]
    __shared__ __align__(16) int w1s[96];
    __shared__ __align__(16) float bs1s[32];        // b1q * s1
    __shared__ __align__(16) float skip1s[2][64];
    __shared__ float redm[16];
    const int t = threadIdx.x;
    const int b0img = blockIdx.x * 2;
    const float sx = mkscale(0, 127.f);
    const float sw1 = mkscale(1, 127.f);
    const float invx = sx > 0.f ? 1.f / sx : 0.f;
    const float m1 = ldmax(13);
    const float s1 = m1 > 0.f ? 127.f / m1 : 0.f;
    const float ks = (sx > 0.f && sw1 > 0.f) ? s1 / (sx * sw1) : 0.f;

    for (int i = t; i < 4608; i += 512) {
        int oc = i / 72, k = i - oc * 72;
        ws[oc * 76 + k] = g_w2p[i];
    }
    for (int i = t; i < 2 * 2610; i += 512) ((int*)ap)[i] = 0;
    for (int i = t; i < 672; i += 512) ((int*)xsbi)[i] = 0;
    if (t < 96) w1s[t] = g_w1p[t];
    if (t >= 128 && t < 160) bs1s[t - 128] = g_b1q[t - 128] * s1;
    __syncthreads();

    {   // quantize x into both byte tiles
        const int li = t >> 8, st = t & 255;
        float4 v = ((const float4*)(x + (b0img + li) * 1024))[st];
        int h = st >> 3, w0 = (st & 7) * 4;
        int c0 = qcode(v.x, sx, -127, 127) & 255;
        int c1 = qcode(v.y, sx, -127, 127) & 255;
        int c2 = qcode(v.z, sx, -127, 127) & 255;
        int c3 = qcode(v.w, sx, -127, 127) & 255;
        *(int*)((signed char*)xsbi[li] + (h + 1) * 40 + 4 + w0) =
            c0 | (c1 << 8) | (c2 << 16) | (c3 << 24);
    }
    __syncthreads();

    if (t < 128) {  // skip1: maxpool(5,4,2) of x codes
        int li = t >> 6, pos = t & 63;
        int oh = pos >> 3, ow = pos & 7;
        const signed char* xb = (const signed char*)xsbi[li];
        int m = -128;
        int h0 = max(0, 4 * oh - 2), h1 = min(31, 4 * oh + 2);
        int w0 = max(0, 4 * ow - 2), w1i = min(31, 4 * ow + 2);
        for (int ih = h0; ih <= h1; ih++)
            for (int iw = w0; iw <= w1i; iw++)
                m = max(m, (int)xb[(ih + 1) * 40 + 4 + iw]);
        skip1s[li][pos] = (float)m * invx;
    }

    {   // conv1 + fused quantize -> ap
        const int li = t >> 8, pix = t & 255;
        const int oh = pix >> 4, ow = pix & 15;
        const int* xw = (const int*)xsbi[li];
        #pragma unroll
        for (int half = 0; half < 2; half++) {
            int acc[16];
            #pragma unroll
            for (int o = 0; o < 16; o++) acc[o] = 0;
            #pragma unroll
            for (int r = 0; r < 3; r++) {
                int rowb = (2 * oh + r) * 40 + 4 + 2 * ow - 1;
                int wi = rowb >> 2, off = rowb & 3;
                int a = __byte_perm(xw[wi], xw[wi + 1], 0x3210 + off * 0x1111);
                const int4* wr = (const int4*)&w1s[r * 32 + half * 16];
                #pragma unroll
                for (int o4 = 0; o4 < 4; o4++) {
                    int4 wv = wr[o4];
                    acc[o4*4+0] = __dp4a(a, wv.x, acc[o4*4+0]);
                    acc[o4*4+1] = __dp4a(a, wv.y, acc[o4*4+1]);
                    acc[o4*4+2] = __dp4a(a, wv.z, acc[o4*4+2]);
                    acc[o4*4+3] = __dp4a(a, wv.w, acc[o4*4+3]);
                }
            }
            #pragma unroll
            for (int j = 0; j < 4; j++) {
                int cc[4];
                #pragma unroll
                for (int k = 0; k < 4; k++) {
                    float f = (float)acc[j*4+k] * ks + bs1s[half*16 + j*4+k];
                    cc[k] = max(0, min(127, __float2int_rn(f)));
                }
                ap[li][(oh + 1) * 145 + (ow + 1) * 8 + half * 4 + j] =
                    cc[0] | (cc[1] << 8) | (cc[2] << 16) | (cc[3] << 24);
            }
        }
    }
    __syncthreads();

    // conv2 mma phase: 16 warps, li2 = w>>3, mt = (w>>1)&3, nh = w&1
    const int w = t >> 5, lane = t & 31;
    const int li2 = w >> 3, mt = (w >> 1) & 3, nh = w & 1;
    const int b = b0img + li2;
    const int r = lane >> 2, c4 = lane & 3;
    const int pix = mt * 16 + r;
    const int oh = pix >> 3, ow = pix & 7;

    int acc[4][4];
    #pragma unroll
    for (int j = 0; j < 4; j++)
        #pragma unroll
        for (int k = 0; k < 4; k++) acc[j][k] = 0;

    #pragma unroll
    for (int kc = 0; kc < 9; kc++) {
        const int tr = kc / 3, tc = kc - tr * 3;
        const int abase = (2 * oh + tr) * 145 + (2 * ow + tc) * 8;
        int a0 = ap[li2][abase + c4];
        int a1 = ap[li2][abase + 290 + c4];
        int a2 = ap[li2][abase + c4 + 4];
        int a3 = ap[li2][abase + 290 + c4 + 4];
        #pragma unroll
        for (int j = 0; j < 4; j++) {
            int ntg = nh * 4 + j;
            int wb = (ntg * 8 + r) * 76 + kc * 8;
            mma_s8(acc[j], a0, a1, a2, a3, ws[wb + c4], ws[wb + c4 + 4]);
        }
    }

    const float sww = mkscale(2, 127.f);
    const float inv = (s1 > 0.f && sww > 0.f) ? 1.f / (s1 * sww) : 0.f;
    const float sk0 = skip1s[li2][pix];
    const float sk1 = skip1s[li2][pix + 8];
    float lm = 0.f;
    #pragma unroll
    for (int j = 0; j < 4; j++) {
        int oc = (nh * 4 + j) * 8 + 2 * c4;
        float y0 = fminf(fmaxf((float)acc[j][0] * inv + g_b2q[oc]     + sk0, 0.f), 10.f);
        float y1 = fminf(fmaxf((float)acc[j][1] * inv + g_b2q[oc + 1] + sk0, 0.f), 10.f);
        float y2 = fminf(fmaxf((float)acc[j][2] * inv + g_b2q[oc]     + sk1, 0.f), 10.f);
        float y3 = fminf(fmaxf((float)acc[j][3] * inv + g_b2q[oc + 1] + sk1, 0.f), 10.f);
        lm = fmaxf(lm, fmaxf(fmaxf(y0, y1), fmaxf(y2, y3)));
        *(float2*)(g_act2 + (b * 64 + pix)     * 64 + oc) = make_float2(y0, y1);
        *(float2*)(g_act2 + (b * 64 + pix + 8) * 64 + oc) = make_float2(y2, y3);
    }
    blockamax<16>(14, lm, redm, t);
}

// Stage 3: quant(act2) codes -> maxpool(3,2,1)=skip2 codes ; conv3(64->16,1x1) dp4a
__global__ void __launch_bounds__(256) k_stage3()
{
    __shared__ __align__(16) int cp[64 * 17];
    __shared__ __align__(16) int w3s[256];
    __shared__ __align__(16) float b3s[16];
    __shared__ float redm[8];
    const int b = blockIdx.x, t = threadIdx.x;
    const float m2 = ldmax(14);
    const float s2 = m2 > 0.f ? 127.f / m2 : 0.f;

    if (t < 64) ((int4*)w3s)[t] = ((const int4*)g_w3p)[t];
    if (t < 16) b3s[t] = g_b3q[t];

    const float4* a2 = (const float4*)(g_act2 + b * 4096);
    #pragma unroll
    for (int i = 0; i < 4; i++) {
        int idx4 = t + 256 * i;
        float4 v = a2[idx4];
        int pix = idx4 >> 4, ic4 = idx4 & 15;
        int c0 = min(127, __float2int_rn(v.x * s2));
        int c1 = min(127, __float2int_rn(v.y * s2));
        int c2 = min(127, __float2int_rn(v.z * s2));
        int c3 = min(127, __float2int_rn(v.w * s2));
        cp[pix * 17 + ic4] = c0 | (c1<<8) | (c2<<16) | (c3<<24);
    }
    __syncthreads();

    float lm;
    {
        int pos = t >> 2, ocq = t & 3;
        int4 acc = make_int4(0, 0, 0, 0);
        #pragma unroll
        for (int ic4 = 0; ic4 < 16; ic4++) {
            int a = cp[pos * 17 + ic4];
            int4 w = ((const int4*)w3s)[ic4 * 4 + ocq];
            acc.x = __dp4a(a, w.x, acc.x); acc.y = __dp4a(a, w.y, acc.y);
            acc.z = __dp4a(a, w.z, acc.z); acc.w = __dp4a(a, w.w, acc.w);
        }
        const float sw3 = mkscale(3, 127.f);
        const float inv3 = (s2 > 0.f && sw3 > 0.f) ? 1.f / (s2 * sw3) : 0.f;
        float4 c;
        c.x = fminf(fmaxf((float)acc.x * inv3 + b3s[ocq*4+0], 0.f), 10.f);
        c.y = fminf(fmaxf((float)acc.y * inv3 + b3s[ocq*4+1], 0.f), 10.f);
        c.z = fminf(fmaxf((float)acc.z * inv3 + b3s[ocq*4+2], 0.f), 10.f);
        c.w = fminf(fmaxf((float)acc.w * inv3 + b3s[ocq*4+3], 0.f), 10.f);
        *(float4*)(g_act3 + (b * 64 + pos) * 16 + ocq * 4) = c;
        lm = fmaxf(fmaxf(c.x, c.y), fmaxf(c.z, c.w));
    }

    {
        int opix = t >> 4, ic4 = t & 15;
        int oh = opix >> 2, ow = opix & 3;
        int m = 0;
        int h0 = max(0, 2*oh-1), h1 = min(7, 2*oh+1);
        int w0 = max(0, 2*ow-1), w1i = min(7, 2*ow+1);
        for (int ih = h0; ih <= h1; ih++)
            for (int iw = w0; iw <= w1i; iw++)
                m = __vmaxs4(m, cp[(ih * 8 + iw) * 17 + ic4]);
        g_skip2p[(b * 16 + opix) * 16 + ic4] = m;
    }
    blockamax<8>(15, lm, redm, t);
}

// Stage 4: conv4(16->16,3x3,s2) dp4a ; 4 images / block
__global__ void __launch_bounds__(256) k_stage4()
{
    __shared__ __align__(16) int a3p[4][64 * 5];
    __shared__ __align__(16) int w4s[576];
    __shared__ __align__(16) float b4s[16];
    __shared__ float redm[8];
    const int t = threadIdx.x;
    const int li = t >> 6, st = t & 63;
    const int img = blockIdx.x * 4 + li;
    const float m3 = ldmax(15);
    const float s3 = m3 > 0.f ? 127.f / m3 : 0.f;

    for (int i = t; i < 576; i += 256) w4s[i] = g_w4p[i];
    if (t < 16) b4s[t] = g_b4q[t];

    const float4* a3 = (const float4*)(g_act3 + img * 1024);
    #pragma unroll
    for (int i = 0; i < 4; i++) {
        int idx4 = st + 64 * i;
        float4 v = a3[idx4];
        int pin = idx4 >> 2, ic4 = idx4 & 3;
        int c0 = min(127, __float2int_rn(v.x * s3));
        int c1 = min(127, __float2int_rn(v.y * s3));
        int c2 = min(127, __float2int_rn(v.z * s3));
        int c3 = min(127, __float2int_rn(v.w * s3));
        a3p[li][pin * 5 + ic4] = c0 | (c1<<8) | (c2<<16) | (c3<<24);
    }
    __syncthreads();

    const int pix = st >> 2, ocq = st & 3;
    const int oh = pix >> 2, ow = pix & 3;
    int4 acc = make_int4(0, 0, 0, 0);
    for (int r = 0; r < 3; r++) {
        int ih = 2*oh - 1 + r;
        if ((unsigned)ih >= 8u) continue;
        for (int s = 0; s < 3; s++) {
            int iw = 2*ow - 1 + s;
            if ((unsigned)iw >= 8u) continue;
            int pin = ih * 8 + iw, tap = r * 3 + s;
            #pragma unroll
            for (int ic4 = 0; ic4 < 4; ic4++) {
                int a = a3p[li][pin * 5 + ic4];
                int4 w = ((const int4*)w4s)[tap * 16 + ic4 * 4 + ocq];
                acc.x = __dp4a(a, w.x, acc.x); acc.y = __dp4a(a, w.y, acc.y);
                acc.z = __dp4a(a, w.z, acc.z); acc.w = __dp4a(a, w.w, acc.w);
            }
        }
    }
    const float sw4 = mkscale(4, 127.f);
    const float inv4 = (s3 > 0.f && sw4 > 0.f) ? 1.f / (s3 * sw4) : 0.f;
    float4 c;
    c.x = fminf(fmaxf((float)acc.x * inv4 + b4s[ocq*4+0], 0.f), 10.f);
    c.y = fminf(fmaxf((float)acc.y * inv4 + b4s[ocq*4+1], 0.f), 10.f);
    c.z = fminf(fmaxf((float)acc.z * inv4 + b4s[ocq*4+2], 0.f), 10.f);
    c.w = fminf(fmaxf((float)acc.w * inv4 + b4s[ocq*4+3], 0.f), 10.f);
    *(float4*)(g_act4 + img * 256 + pix * 16 + ocq * 4) = c;
    float lm = fmaxf(fmaxf(c.x, c.y), fmaxf(c.z, c.w));
    blockamax<8>(16, lm, redm, t);
}

// Stage 5: conv5(16->64,1x1) dp4a + b5 + skip2 -> clip -> act5 ; 2 images / block
__global__ void __launch_bounds__(256) k_stage5()
{
    __shared__ __align__(16) int a4p[2][16 * 5];
    __shared__ __align__(16) int w5s[256];
    __shared__ __align__(16) float b5s[64];
    __shared__ float redm[8];
    const int t = threadIdx.x;
    const int li = t >> 7, st = t & 127;
    const int img = blockIdx.x * 2 + li;
    const float m4 = ldmax(16);
    const float s4 = m4 > 0.f ? 127.f / m4 : 0.f;

    if (t < 64) ((int4*)w5s)[t] = ((const int4*)g_w5p)[t];
    if (t >= 64 && t < 128) b5s[t - 64] = g_b5q[t - 64];

    const float4* a4 = (const float4*)(g_act4 + img * 256);
    if (st < 64) {
        float4 v = a4[st];
        int pin = st >> 2, ic4 = st & 3;
        int c0 = min(127, __float2int_rn(v.x * s4));
        int c1 = min(127, __float2int_rn(v.y * s4));
        int c2 = min(127, __float2int_rn(v.z * s4));
        int c3 = min(127, __float2int_rn(v.w * s4));
        a4p[li][pin * 5 + ic4] = c0 | (c1<<8) | (c2<<16) | (c3<<24);
    }
    __syncthreads();

    const int pix = st >> 3, ocg = st & 7;
    int acc[8];
    #pragma unroll
    for (int k = 0; k < 8; k++) acc[k] = 0;
    #pragma unroll
    for (int ic4 = 0; ic4 < 4; ic4++) {
        int a = a4p[li][pix * 5 + ic4];
        int4 w0 = ((const int4*)w5s)[ic4 * 16 + ocg * 2];
        int4 w1 = ((const int4*)w5s)[ic4 * 16 + ocg * 2 + 1];
        acc[0] = __dp4a(a, w0.x, acc[0]); acc[1] = __dp4a(a, w0.y, acc[1]);
        acc[2] = __dp4a(a, w0.z, acc[2]); acc[3] = __dp4a(a, w0.w, acc[3]);
        acc[4] = __dp4a(a, w1.x, acc[4]); acc[5] = __dp4a(a, w1.y, acc[5]);
        acc[6] = __dp4a(a, w1.z, acc[6]); acc[7] = __dp4a(a, w1.w, acc[7]);
    }
    const float sw5 = mkscale(5, 127.f);
    const float invw = (s4 > 0.f && sw5 > 0.f) ? 1.f / (s4 * sw5) : 0.f;
    const float m2 = ldmax(14);
    const float s2 = m2 > 0.f ? 127.f / m2 : 0.f;
    const float inv2 = s2 > 0.f ? 1.f / s2 : 0.f;

    const int* skp = g_skip2p + (img * 16 + pix) * 16 + ocg * 2;
    int sk0 = skp[0], sk1 = skp[1];
    float o[8], lm = 0.f;
    #pragma unroll
    for (int k = 0; k < 8; k++) {
        int code = (k < 4 ? (sk0 >> (8 * k)) : (sk1 >> (8 * (k - 4)))) & 255;
        float y = (float)acc[k] * invw + b5s[ocg*8+k] + (float)code * inv2;
        o[k] = fminf(fmaxf(y, 0.f), 10.f);
        lm = fmaxf(lm, o[k]);
    }
    float* dst = g_act5 + (img * 16 + pix) * 64 + ocg * 8;
    ((float4*)dst)[0] = make_float4(o[0], o[1], o[2], o[3]);
    ((float4*)dst)[1] = make_float4(o[4], o[5], o[6], o[7]);
    blockamax<8>(17, lm, redm, t);
}

// Final: quant(act5) -> mean(4x4) -> linear(64->10). 4 images / block.
__global__ void __launch_bounds__(256) k_final(float* __restrict__ out)
{
    __shared__ __align__(16) float sv[4][64];
    __shared__ __align__(16) float wls[640];
    const int t = threadIdx.x;
    const int li = t >> 6, sub = t & 63;
    const int img = blockIdx.x * 4 + li;
    const float m5 = ldmax(17);
    const float s5 = m5 > 0.f ? 127.f / m5 : 0.f;
    const float inv5 = s5 > 0.f ? 1.f / s5 : 0.f;
    for (int i = t; i < 640; i += 256) wls[i] = g_wlq[i];
    const float* a5 = g_act5 + img * 1024;
    int acc = 0;
    #pragma unroll
    for (int p = 0; p < 16; p++)
        acc += min(127, __float2int_rn(a5[p * 64 + sub] * s5));
    sv[li][sub] = (float)acc * inv5 * (1.f / 16.f);
    __syncthreads();
    if (t < 40) {
        int li3 = t / 10, o = t - li3 * 10;
        float r = g_blq[o];
        const float* svr = sv[li3];
        const float* wr = wls + o * 64;
        #pragma unroll 8
        for (int c = 0; c < 64; c++) r += svr[c] * wr[c];
        out[(blockIdx.x * 4 + li3) * 10 + o] = r;
    }
}

extern "C" void kernel_launch(void* const* d_in, const int* in_sizes, int n_in,
                              void* d_out, int out_size) {
    const float* x  = (const float*)d_in[0];
    const float* w1 = (const float*)d_in[1];  const float* b1 = (const float*)d_in[2];
    const float* w2 = (const float*)d_in[3];  const float* b2 = (const float*)d_in[4];
    const float* w3 = (const float*)d_in[5];  const float* b3 = (const float*)d_in[6];
    const float* w4 = (const float*)d_in[7];  const float* b4 = (const float*)d_in[8];
    const float* w5 = (const float*)d_in[9];  const float* b5 = (const float*)d_in[10];
    const float* wl = (const float*)d_in[11]; const float* bl = (const float*)d_in[12];

    k_reset<<<1, 32>>>();
    k_absmax<<<524, 256>>>((const float4*)x, w1, w2, w3, w4, w5, wl,
                           b1, b2, b3, b4, b5, bl);
    k_wprep<<<2, 256>>>(w1, w2, w3, w4, w5, wl, b1, b2, b3, b4, b5, bl);
    k_max1<<<B_IMG, 256>>>(x, w1, b1);
    k_stage12<<<B_IMG / 2, 512>>>(x);
    k_stage3<<<B_IMG, 256>>>();
    k_stage4<<<B_IMG / 4, 256>>>();
    k_stage5<<<B_IMG / 2, 256>>>();
    k_final<<<B_IMG / 4, 256>>>((float*)d_out);
}

// round 16
// speedup vs baseline: 3.7774x; 1.0099x over previous
#include <cuda_runtime.h>
#include <cstdint>
#include <climits>

#define B_IMG 4096

// slots: 0:x 1..5:w1..w5 6:wl 7..11:b1..b5 12:bl 13..17:act1..act5
__device__ unsigned g_maxbits[18];
__device__ __align__(16) float g_act2 [B_IMG * 4096];   // [b][64 pix][64 ch]
__device__ __align__(16) float g_act3 [B_IMG * 1024];   // [b][64 pix][16 ch]
__device__ __align__(16) int   g_skip2p[B_IMG * 256];   // [b][16 pix][16 ic4] packed codes
__device__ __align__(16) float g_act4 [B_IMG * 256];    // [b][16 pix][16 ch]
__device__ __align__(16) float g_act5 [B_IMG * 1024];   // [b][16 pix][64 ch]

// pre-quantized parameters
__device__ __align__(16) int   g_w2p[4608];   // [oc=64][tap*8+ic4=72] packed codes
__device__ __align__(16) int   g_w1p[96];     // [r=3][oc=32] bytes (w0,w1,w2,0)
__device__ __align__(16) int   g_w3p[256];    // [ic4=16][oc=16]
__device__ __align__(16) int   g_w4p[576];    // [tap=9][ic4=4][oc=16]
__device__ __align__(16) int   g_w5p[256];    // [ic4=4][oc=64]
__device__ __align__(16) float g_wlq[640];
__device__ __align__(16) float g_b1q[32];
__device__ __align__(16) float g_b2q[64];
__device__ __align__(16) float g_b3q[16];
__device__ __align__(16) float g_b4q[16];
__device__ __align__(16) float g_b5q[64];
__device__ __align__(16) float g_blq[12];

__device__ __forceinline__ float ldmax(int i) { return __uint_as_float(g_maxbits[i]); }
__device__ __forceinline__ void amaxf(int i, float v) {
    atomicMax(&g_maxbits[i], __float_as_uint(v));
}
__device__ __forceinline__ float warpmax(float v) {
    #pragma unroll
    for (int o = 16; o > 0; o >>= 1) v = fmaxf(v, __shfl_xor_sync(0xffffffffu, v, o));
    return v;
}
template<int NW>
__device__ __forceinline__ void blockamax(int slot, float lm, float* redm, int t) {
    lm = warpmax(lm);
    if ((t & 31) == 0) redm[t >> 5] = lm;
    __syncthreads();
    if (t == 0) {
        float mm = redm[0];
        #pragma unroll
        for (int i = 1; i < NW; i++) mm = fmaxf(mm, redm[i]);
        amaxf(slot, mm);
    }
}
__device__ __forceinline__ float mkscale(int slot, float maxv) {
    float m = ldmax(slot);
    return m > 0.f ? maxv / m : 0.f;
}
__device__ __forceinline__ int qcode(float x, float s, int lo, int hi) {
    return max(lo, min(hi, __float2int_rn(x * s)));
}
__device__ __forceinline__ float dequant1(float x, float s, float lo, float hi) {
    if (s <= 0.f) return 0.f;
    return fminf(fmaxf(rintf(x * s), lo), hi) / s;
}
// int8 mma: D(16x8) += A(16x32) * B(32x8)
__device__ __forceinline__ void mma_s8(int* c, int a0, int a1, int a2, int a3,
                                       int b0, int b1) {
    asm volatile(
        "mma.sync.aligned.m16n8k32.row.col.s32.s8.s8.s32 "
        "{%0,%1,%2,%3}, {%4,%5,%6,%7}, {%8,%9}, {%0,%1,%2,%3};"
        : "+r"(c[0]), "+r"(c[1]), "+r"(c[2]), "+r"(c[3])
        : "r"(a0), "r"(a1), "r"(a2), "r"(a3), "r"(b0), "r"(b1));
}
// int8 mma k16, zero accumulator: D = A(16x16) * B(16x8)
__device__ __forceinline__ void mma_s8_k16z(int* d, int a0, int a1, int b0) {
    asm volatile(
        "mma.sync.aligned.m16n8k16.row.col.s32.s8.s8.s32 "
        "{%0,%1,%2,%3}, {%4,%5}, {%6}, {%7,%7,%7,%7};"
        : "=r"(d[0]), "=r"(d[1]), "=r"(d[2]), "=r"(d[3])
        : "r"(a0), "r"(a1), "r"(b0), "r"(0));
}

__global__ void k_reset() { if (threadIdx.x < 18) g_maxbits[threadIdx.x] = 0u; }

// blocks 0..511: max|x| ; blocks 512..523: per-param max
__global__ void __launch_bounds__(256) k_absmax(
    const float4* __restrict__ x,
    const float* w1, const float* w2, const float* w3, const float* w4, const float* w5,
    const float* wl, const float* b1, const float* b2, const float* b3, const float* b4,
    const float* b5, const float* bl)
{
    __shared__ float redm[8];
    if (blockIdx.x < 512) {
        const int n4 = B_IMG * 1024 / 4;
        float m = 0.f;
        for (int i = blockIdx.x * 256 + threadIdx.x; i < n4; i += 512 * 256) {
            float4 v = x[i];
            m = fmaxf(m, fmaxf(fmaxf(fabsf(v.x), fabsf(v.y)), fmaxf(fabsf(v.z), fabsf(v.w))));
        }
        blockamax<8>(0, m, redm, threadIdx.x);
    } else {
        const float* ptrs[12] = {w1, w2, w3, w4, w5, wl, b1, b2, b3, b4, b5, bl};
        const int sizes[12]   = {288, 18432, 1024, 2304, 1024, 640, 32, 64, 16, 16, 64, 10};
        int blk = blockIdx.x - 512;
        const float* p = ptrs[blk];
        int n = sizes[blk];
        float m = 0.f;
        for (int i = threadIdx.x; i < n; i += 256) m = fmaxf(m, fabsf(p[i]));
        blockamax<8>(blk + 1, m, redm, threadIdx.x);
    }
}

// k_max1: blocks 0..511 -> conv1 max via m16n8k16 mma (8 images/block, 1 warp/image);
// blocks 512..513 -> parameter quantization/packing (former k_wprep).
__global__ void __launch_bounds__(256) k_max1(
    const float* __restrict__ x,
    const float* __restrict__ w1g, const float* __restrict__ b1g,
    const float* __restrict__ w2, const float* __restrict__ w3, const float* __restrict__ w4,
    const float* __restrict__ w5, const float* __restrict__ wl,
    const float* __restrict__ b2, const float* __restrict__ b3, const float* __restrict__ b4,
    const float* __restrict__ b5, const float* __restrict__ bl)
{
    const int t = threadIdx.x;
    if (blockIdx.x >= 512) {        // ---- wprep path ----
        if (blockIdx.x == 512) {
            const float sw = mkscale(2, 127.f);
            for (int i = t; i < 4608; i += 256) {
                int oc = i / 72, k = i - oc * 72, tap = k >> 3, ic4 = k & 7;
                int p = 0;
                #pragma unroll
                for (int j = 0; j < 4; j++)
                    p |= (qcode(w2[oc * 288 + (ic4 * 4 + j) * 9 + tap], sw, -127, 127) & 255) << (8 * j);
                g_w2p[i] = p;
            }
        } else {
            {   const float s = mkscale(1, 127.f);
                if (t < 96) {
                    int r = t >> 5, oc = t & 31, p = 0;
                    #pragma unroll
                    for (int j = 0; j < 3; j++)
                        p |= (qcode(w1g[oc * 9 + r * 3 + j], s, -127, 127) & 255) << (8 * j);
                    g_w1p[t] = p;
                }
            }
            {   const float s = mkscale(3, 127.f);
                for (int i = t; i < 256; i += 256) {
                    int ic4 = i >> 4, oc = i & 15, p = 0;
                    #pragma unroll
                    for (int j = 0; j < 4; j++)
                        p |= (qcode(w3[oc * 64 + ic4 * 4 + j], s, -127, 127) & 255) << (8 * j);
                    g_w3p[i] = p;
                }
            }
            {   const float s = mkscale(4, 127.f);
                for (int i = t; i < 576; i += 256) {
                    int oc = i & 15, ic4 = (i >> 4) & 3, tap = i >> 6, p = 0;
                    #pragma unroll
                    for (int j = 0; j < 4; j++)
                        p |= (qcode(w4[oc * 144 + (ic4 * 4 + j) * 9 + tap], s, -127, 127) & 255) << (8 * j);
                    g_w4p[i] = p;
                }
            }
            {   const float s = mkscale(5, 127.f);
                for (int i = t; i < 256; i += 256) {
                    int ic4 = i >> 6, oc = i & 63, p = 0;
                    #pragma unroll
                    for (int j = 0; j < 4; j++)
                        p |= (qcode(w5[oc * 16 + ic4 * 4 + j], s, -127, 127) & 255) << (8 * j);
                    g_w5p[i] = p;
                }
            }
            {   const float s = mkscale(6, 127.f);
                for (int i = t; i < 640; i += 256) g_wlq[i] = dequant1(wl[i], s, -127.f, 127.f); }
            {   const float s = mkscale(7, 32767.f);
                if (t < 32) g_b1q[t] = dequant1(b1g[t], s, -32767.f, 32767.f); }
            {   const float s = mkscale(8, 32767.f);
                if (t < 64) g_b2q[t] = dequant1(b2[t], s, -32767.f, 32767.f); }
            {   const float s = mkscale(9, 32767.f);
                if (t < 16) g_b3q[t] = dequant1(b3[t], s, -32767.f, 32767.f); }
            {   const float s = mkscale(10, 32767.f);
                if (t < 16) g_b4q[t] = dequant1(b4[t], s, -32767.f, 32767.f); }
            {   const float s = mkscale(11, 32767.f);
                if (t < 64) g_b5q[t] = dequant1(b5[t], s, -32767.f, 32767.f); }
            {   const float s = mkscale(12, 32767.f);
                if (t < 10) g_blq[t] = dequant1(bl[t], s, -32767.f, 32767.f); }
        }
        return;
    }

    // ---- max1 path: 8 warps, 1 image each ----
    __shared__ __align__(16) int xsb[8][330];   // 33 rows x 40B, guarded
    __shared__ __align__(16) int w1s[96];
    __shared__ __align__(16) float b1s[32];
    __shared__ float redm[8];
    const int wid = t >> 5, lane = t & 31;
    const int img = blockIdx.x * 8 + wid;
    const float sx = mkscale(0, 127.f);
    const float sw = mkscale(1, 127.f);
    const float inv = (sx > 0.f && sw > 0.f) ? 1.f / (sx * sw) : 0.f;

    if (t < 96) {
        int r = t >> 5, oc = t & 31, p = 0;
        #pragma unroll
        for (int j = 0; j < 3; j++)
            p |= (qcode(w1g[oc * 9 + r * 3 + j], sw, -127, 127) & 255) << (8 * j);
        w1s[t] = p;
    }
    if (t >= 128 && t < 160) b1s[t - 128] = dequant1(b1g[t - 128], mkscale(7, 32767.f), -32767.f, 32767.f);
    __syncthreads();

    int* xs = xsb[wid];
    for (int i = lane; i < 330; i += 32) xs[i] = 0;
    __syncwarp();
    {
        const float4* xg = (const float4*)(x + img * 1024);
        #pragma unroll
        for (int i = 0; i < 8; i++) {
            int idx = i * 32 + lane;
            float4 v = xg[idx];
            int h = idx >> 3, w0 = (idx & 7);
            int c0 = qcode(v.x, sx, -127, 127) & 255;
            int c1 = qcode(v.y, sx, -127, 127) & 255;
            int c2 = qcode(v.z, sx, -127, 127) & 255;
            int c3 = qcode(v.w, sx, -127, 127) & 255;
            xs[(h + 1) * 10 + 1 + w0] = c0 | (c1 << 8) | (c2 << 16) | (c3 << 24);
        }
    }
    __syncwarp();

    const int r = lane >> 2, c4 = lane & 3;
    int bfr[4];
    #pragma unroll
    for (int nt = 0; nt < 4; nt++) bfr[nt] = (c4 < 3) ? w1s[c4 * 32 + nt * 8 + r] : 0;

    int m0[4], m1[4];
    #pragma unroll
    for (int nt = 0; nt < 4; nt++) { m0[nt] = INT_MIN; m1[nt] = INT_MIN; }

    #pragma unroll
    for (int mt = 0; mt < 16; mt++) {
        int a0 = 0, a1 = 0;
        if (c4 < 3) {
            int rowb = (2 * mt + c4) * 40 + 4 + 2 * r - 1;   // pixel (mt, r), patch row c4
            int wi = rowb >> 2, off = rowb & 3;
            int sel = 0x3210 + off * 0x1111;
            a0 = __byte_perm(xs[wi], xs[wi + 1], sel);
            a1 = __byte_perm(xs[wi + 4], xs[wi + 5], sel);   // pixel (mt, r+8): +16 bytes
        }
        #pragma unroll
        for (int nt = 0; nt < 4; nt++) {
            int d[4];
            mma_s8_k16z(d, a0, a1, bfr[nt]);
            m0[nt] = max(m0[nt], max(d[0], d[2]));
            m1[nt] = max(m1[nt], max(d[1], d[3]));
        }
    }
    float lm = 0.f;
    #pragma unroll
    for (int nt = 0; nt < 4; nt++) {
        int ch = nt * 8 + 2 * c4;
        lm = fmaxf(lm, fminf(fmaxf((float)m0[nt] * inv + b1s[ch],     0.f), 10.f));
        lm = fmaxf(lm, fminf(fmaxf((float)m1[nt] * inv + b1s[ch + 1], 0.f), 10.f));
    }
    blockamax<8>(13, lm, redm, t);
}

// Fused stage1+2: conv1 -> act1 codes in smem halo tile -> conv2 int8 mma.
__global__ void __launch_bounds__(512) k_stage12(const float* __restrict__ x)
{
    __shared__ __align__(16) int xsbi[2][336];
    __shared__ __align__(16) int ap[2][18 * 145];
    __shared__ __align__(16) int ws[64 * 76];
    __shared__ __align__(16) int w1s[96];
    __shared__ __align__(16) float bs1s[32];
    __shared__ __align__(16) float skip1s[2][64];
    __shared__ float redm[16];
    const int t = threadIdx.x;
    const int b0img = blockIdx.x * 2;
    const float sx = mkscale(0, 127.f);
    const float sw1 = mkscale(1, 127.f);
    const float invx = sx > 0.f ? 1.f / sx : 0.f;
    const float m1 = ldmax(13);
    const float s1 = m1 > 0.f ? 127.f / m1 : 0.f;
    const float ks = (sx > 0.f && sw1 > 0.f) ? s1 / (sx * sw1) : 0.f;

    for (int i = t; i < 4608; i += 512) {
        int oc = i / 72, k = i - oc * 72;
        ws[oc * 76 + k] = g_w2p[i];
    }
    for (int i = t; i < 2 * 2610; i += 512) ((int*)ap)[i] = 0;
    for (int i = t; i < 672; i += 512) ((int*)xsbi)[i] = 0;
    if (t < 96) w1s[t] = g_w1p[t];
    if (t >= 128 && t < 160) bs1s[t - 128] = g_b1q[t - 128] * s1;
    __syncthreads();

    {
        const int li = t >> 8, st = t & 255;
        float4 v = ((const float4*)(x + (b0img + li) * 1024))[st];
        int h = st >> 3, w0 = (st & 7) * 4;
        int c0 = qcode(v.x, sx, -127, 127) & 255;
        int c1 = qcode(v.y, sx, -127, 127) & 255;
        int c2 = qcode(v.z, sx, -127, 127) & 255;
        int c3 = qcode(v.w, sx, -127, 127) & 255;
        *(int*)((signed char*)xsbi[li] + (h + 1) * 40 + 4 + w0) =
            c0 | (c1 << 8) | (c2 << 16) | (c3 << 24);
    }
    __syncthreads();

    if (t < 128) {
        int li = t >> 6, pos = t & 63;
        int oh = pos >> 3, ow = pos & 7;
        const signed char* xb = (const signed char*)xsbi[li];
        int m = -128;
        int h0 = max(0, 4 * oh - 2), h1 = min(31, 4 * oh + 2);
        int w0 = max(0, 4 * ow - 2), w1i = min(31, 4 * ow + 2);
        for (int ih = h0; ih <= h1; ih++)
            for (int iw = w0; iw <= w1i; iw++)
                m = max(m, (int)xb[(ih + 1) * 40 + 4 + iw]);
        skip1s[li][pos] = (float)m * invx;
    }

    {
        const int li = t >> 8, pix = t & 255;
        const int oh = pix >> 4, ow = pix & 15;
        const int* xw = (const int*)xsbi[li];
        #pragma unroll
        for (int half = 0; half < 2; half++) {
            int acc[16];
            #pragma unroll
            for (int o = 0; o < 16; o++) acc[o] = 0;
            #pragma unroll
            for (int r = 0; r < 3; r++) {
                int rowb = (2 * oh + r) * 40 + 4 + 2 * ow - 1;
                int wi = rowb >> 2, off = rowb & 3;
                int a = __byte_perm(xw[wi], xw[wi + 1], 0x3210 + off * 0x1111);
                const int4* wr = (const int4*)&w1s[r * 32 + half * 16];
                #pragma unroll
                for (int o4 = 0; o4 < 4; o4++) {
                    int4 wv = wr[o4];
                    acc[o4*4+0] = __dp4a(a, wv.x, acc[o4*4+0]);
                    acc[o4*4+1] = __dp4a(a, wv.y, acc[o4*4+1]);
                    acc[o4*4+2] = __dp4a(a, wv.z, acc[o4*4+2]);
                    acc[o4*4+3] = __dp4a(a, wv.w, acc[o4*4+3]);
                }
            }
            #pragma unroll
            for (int j = 0; j < 4; j++) {
                int cc[4];
                #pragma unroll
                for (int k = 0; k < 4; k++) {
                    float f = (float)acc[j*4+k] * ks + bs1s[half*16 + j*4+k];
                    cc[k] = max(0, min(127, __float2int_rn(f)));
                }
                ap[li][(oh + 1) * 145 + (ow + 1) * 8 + half * 4 + j] =
                    cc[0] | (cc[1] << 8) | (cc[2] << 16) | (cc[3] << 24);
            }
        }
    }
    __syncthreads();

    const int w = t >> 5, lane = t & 31;
    const int li2 = w >> 3, mt = (w >> 1) & 3, nh = w & 1;
    const int b = b0img + li2;
    const int r = lane >> 2, c4 = lane & 3;
    const int pix = mt * 16 + r;
    const int oh = pix >> 3, ow = pix & 7;

    int acc[4][4];
    #pragma unroll
    for (int j = 0; j < 4; j++)
        #pragma unroll
        for (int k = 0; k < 4; k++) acc[j][k] = 0;

    #pragma unroll
    for (int kc = 0; kc < 9; kc++) {
        const int tr = kc / 3, tc = kc - tr * 3;
        const int abase = (2 * oh + tr) * 145 + (2 * ow + tc) * 8;
        int a0 = ap[li2][abase + c4];
        int a1 = ap[li2][abase + 290 + c4];
        int a2 = ap[li2][abase + c4 + 4];
        int a3 = ap[li2][abase + 290 + c4 + 4];
        #pragma unroll
        for (int j = 0; j < 4; j++) {
            int ntg = nh * 4 + j;
            int wb = (ntg * 8 + r) * 76 + kc * 8;
            mma_s8(acc[j], a0, a1, a2, a3, ws[wb + c4], ws[wb + c4 + 4]);
        }
    }

    const float sww = mkscale(2, 127.f);
    const float inv = (s1 > 0.f && sww > 0.f) ? 1.f / (s1 * sww) : 0.f;
    const float sk0 = skip1s[li2][pix];
    const float sk1 = skip1s[li2][pix + 8];
    float lm = 0.f;
    #pragma unroll
    for (int j = 0; j < 4; j++) {
        int oc = (nh * 4 + j) * 8 + 2 * c4;
        float y0 = fminf(fmaxf((float)acc[j][0] * inv + g_b2q[oc]     + sk0, 0.f), 10.f);
        float y1 = fminf(fmaxf((float)acc[j][1] * inv + g_b2q[oc + 1] + sk0, 0.f), 10.f);
        float y2 = fminf(fmaxf((float)acc[j][2] * inv + g_b2q[oc]     + sk1, 0.f), 10.f);
        float y3 = fminf(fmaxf((float)acc[j][3] * inv + g_b2q[oc + 1] + sk1, 0.f), 10.f);
        lm = fmaxf(lm, fmaxf(fmaxf(y0, y1), fmaxf(y2, y3)));
        *(float2*)(g_act2 + (b * 64 + pix)     * 64 + oc) = make_float2(y0, y1);
        *(float2*)(g_act2 + (b * 64 + pix + 8) * 64 + oc) = make_float2(y2, y3);
    }
    blockamax<16>(14, lm, redm, t);
}

// Stage 3: quant(act2) codes -> maxpool(3,2,1)=skip2 codes ; conv3(64->16,1x1) dp4a
__global__ void __launch_bounds__(256) k_stage3()
{
    __shared__ __align__(16) int cp[64 * 17];
    __shared__ __align__(16) int w3s[256];
    __shared__ __align__(16) float b3s[16];
    __shared__ float redm[8];
    const int b = blockIdx.x, t = threadIdx.x;
    const float m2 = ldmax(14);
    const float s2 = m2 > 0.f ? 127.f / m2 : 0.f;

    if (t < 64) ((int4*)w3s)[t] = ((const int4*)g_w3p)[t];
    if (t < 16) b3s[t] = g_b3q[t];

    const float4* a2 = (const float4*)(g_act2 + b * 4096);
    #pragma unroll
    for (int i = 0; i < 4; i++) {
        int idx4 = t + 256 * i;
        float4 v = a2[idx4];
        int pix = idx4 >> 4, ic4 = idx4 & 15;
        int c0 = min(127, __float2int_rn(v.x * s2));
        int c1 = min(127, __float2int_rn(v.y * s2));
        int c2 = min(127, __float2int_rn(v.z * s2));
        int c3 = min(127, __float2int_rn(v.w * s2));
        cp[pix * 17 + ic4] = c0 | (c1<<8) | (c2<<16) | (c3<<24);
    }
    __syncthreads();

    float lm;
    {
        int pos = t >> 2, ocq = t & 3;
        int4 acc = make_int4(0, 0, 0, 0);
        #pragma unroll
        for (int ic4 = 0; ic4 < 16; ic4++) {
            int a = cp[pos * 17 + ic4];
            int4 w = ((const int4*)w3s)[ic4 * 4 + ocq];
            acc.x = __dp4a(a, w.x, acc.x); acc.y = __dp4a(a, w.y, acc.y);
            acc.z = __dp4a(a, w.z, acc.z); acc.w = __dp4a(a, w.w, acc.w);
        }
        const float sw3 = mkscale(3, 127.f);
        const float inv3 = (s2 > 0.f && sw3 > 0.f) ? 1.f / (s2 * sw3) : 0.f;
        float4 c;
        c.x = fminf(fmaxf((float)acc.x * inv3 + b3s[ocq*4+0], 0.f), 10.f);
        c.y = fminf(fmaxf((float)acc.y * inv3 + b3s[ocq*4+1], 0.f), 10.f);
        c.z = fminf(fmaxf((float)acc.z * inv3 + b3s[ocq*4+2], 0.f), 10.f);
        c.w = fminf(fmaxf((float)acc.w * inv3 + b3s[ocq*4+3], 0.f), 10.f);
        *(float4*)(g_act3 + (b * 64 + pos) * 16 + ocq * 4) = c;
        lm = fmaxf(fmaxf(c.x, c.y), fmaxf(c.z, c.w));
    }

    {
        int opix = t >> 4, ic4 = t & 15;
        int oh = opix >> 2, ow = opix & 3;
        int m = 0;
        int h0 = max(0, 2*oh-1), h1 = min(7, 2*oh+1);
        int w0 = max(0, 2*ow-1), w1i = min(7, 2*ow+1);
        for (int ih = h0; ih <= h1; ih++)
            for (int iw = w0; iw <= w1i; iw++)
                m = __vmaxs4(m, cp[(ih * 8 + iw) * 17 + ic4]);
        g_skip2p[(b * 16 + opix) * 16 + ic4] = m;
    }
    blockamax<8>(15, lm, redm, t);
}

// Stage 4: conv4(16->16,3x3,s2) dp4a ; 4 images / block
__global__ void __launch_bounds__(256) k_stage4()
{
    __shared__ __align__(16) int a3p[4][64 * 5];
    __shared__ __align__(16) int w4s[576];
    __shared__ __align__(16) float b4s[16];
    __shared__ float redm[8];
    const int t = threadIdx.x;
    const int li = t >> 6, st = t & 63;
    const int img = blockIdx.x * 4 + li;
    const float m3 = ldmax(15);
    const float s3 = m3 > 0.f ? 127.f / m3 : 0.f;

    for (int i = t; i < 576; i += 256) w4s[i] = g_w4p[i];
    if (t < 16) b4s[t] = g_b4q[t];

    const float4* a3 = (const float4*)(g_act3 + img * 1024);
    #pragma unroll
    for (int i = 0; i < 4; i++) {
        int idx4 = st + 64 * i;
        float4 v = a3[idx4];
        int pin = idx4 >> 2, ic4 = idx4 & 3;
        int c0 = min(127, __float2int_rn(v.x * s3));
        int c1 = min(127, __float2int_rn(v.y * s3));
        int c2 = min(127, __float2int_rn(v.z * s3));
        int c3 = min(127, __float2int_rn(v.w * s3));
        a3p[li][pin * 5 + ic4] = c0 | (c1<<8) | (c2<<16) | (c3<<24);
    }
    __syncthreads();

    const int pix = st >> 2, ocq = st & 3;
    const int oh = pix >> 2, ow = pix & 3;
    int4 acc = make_int4(0, 0, 0, 0);
    for (int r = 0; r < 3; r++) {
        int ih = 2*oh - 1 + r;
        if ((unsigned)ih >= 8u) continue;
        for (int s = 0; s < 3; s++) {
            int iw = 2*ow - 1 + s;
            if ((unsigned)iw >= 8u) continue;
            int pin = ih * 8 + iw, tap = r * 3 + s;
            #pragma unroll
            for (int ic4 = 0; ic4 < 4; ic4++) {
                int a = a3p[li][pin * 5 + ic4];
                int4 w = ((const int4*)w4s)[tap * 16 + ic4 * 4 + ocq];
                acc.x = __dp4a(a, w.x, acc.x); acc.y = __dp4a(a, w.y, acc.y);
                acc.z = __dp4a(a, w.z, acc.z); acc.w = __dp4a(a, w.w, acc.w);
            }
        }
    }
    const float sw4 = mkscale(4, 127.f);
    const float inv4 = (s3 > 0.f && sw4 > 0.f) ? 1.f / (s3 * sw4) : 0.f;
    float4 c;
    c.x = fminf(fmaxf((float)acc.x * inv4 + b4s[ocq*4+0], 0.f), 10.f);
    c.y = fminf(fmaxf((float)acc.y * inv4 + b4s[ocq*4+1], 0.f), 10.f);
    c.z = fminf(fmaxf((float)acc.z * inv4 + b4s[ocq*4+2], 0.f), 10.f);
    c.w = fminf(fmaxf((float)acc.w * inv4 + b4s[ocq*4+3], 0.f), 10.f);
    *(float4*)(g_act4 + img * 256 + pix * 16 + ocq * 4) = c;
    float lm = fmaxf(fmaxf(c.x, c.y), fmaxf(c.z, c.w));
    blockamax<8>(16, lm, redm, t);
}

// Stage 5: conv5(16->64,1x1) dp4a + b5 + skip2 -> clip -> act5 ; 2 images / block
__global__ void __launch_bounds__(256) k_stage5()
{
    __shared__ __align__(16) int a4p[2][16 * 5];
    __shared__ __align__(16) int w5s[256];
    __shared__ __align__(16) float b5s[64];
    __shared__ float redm[8];
    const int t = threadIdx.x;
    const int li = t >> 7, st = t & 127;
    const int img = blockIdx.x * 2 + li;
    const float m4 = ldmax(16);
    const float s4 = m4 > 0.f ? 127.f / m4 : 0.f;

    if (t < 64) ((int4*)w5s)[t] = ((const int4*)g_w5p)[t];
    if (t >= 64 && t < 128) b5s[t - 64] = g_b5q[t - 64];

    const float4* a4 = (const float4*)(g_act4 + img * 256);
    if (st < 64) {
        float4 v = a4[st];
        int pin = st >> 2, ic4 = st & 3;
        int c0 = min(127, __float2int_rn(v.x * s4));
        int c1 = min(127, __float2int_rn(v.y * s4));
        int c2 = min(127, __float2int_rn(v.z * s4));
        int c3 = min(127, __float2int_rn(v.w * s4));
        a4p[li][pin * 5 + ic4] = c0 | (c1<<8) | (c2<<16) | (c3<<24);
    }
    __syncthreads();

    const int pix = st >> 3, ocg = st & 7;
    int acc[8];
    #pragma unroll
    for (int k = 0; k < 8; k++) acc[k] = 0;
    #pragma unroll
    for (int ic4 = 0; ic4 < 4; ic4++) {
        int a = a4p[li][pix * 5 + ic4];
        int4 w0 = ((const int4*)w5s)[ic4 * 16 + ocg * 2];
        int4 w1 = ((const int4*)w5s)[ic4 * 16 + ocg * 2 + 1];
        acc[0] = __dp4a(a, w0.x, acc[0]); acc[1] = __dp4a(a, w0.y, acc[1]);
        acc[2] = __dp4a(a, w0.z, acc[2]); acc[3] = __dp4a(a, w0.w, acc[3]);
        acc[4] = __dp4a(a, w1.x, acc[4]); acc[5] = __dp4a(a, w1.y, acc[5]);
        acc[6] = __dp4a(a, w1.z, acc[6]); acc[7] = __dp4a(a, w1.w, acc[7]);
    }
    const float sw5 = mkscale(5, 127.f);
    const float invw = (s4 > 0.f && sw5 > 0.f) ? 1.f / (s4 * sw5) : 0.f;
    const float m2 = ldmax(14);
    const float s2 = m2 > 0.f ? 127.f / m2 : 0.f;
    const float inv2 = s2 > 0.f ? 1.f / s2 : 0.f;

    const int* skp = g_skip2p + (img * 16 + pix) * 16 + ocg * 2;
    int sk0 = skp[0], sk1 = skp[1];
    float o[8], lm = 0.f;
    #pragma unroll
    for (int k = 0; k < 8; k++) {
        int code = (k < 4 ? (sk0 >> (8 * k)) : (sk1 >> (8 * (k - 4)))) & 255;
        float y = (float)acc[k] * invw + b5s[ocg*8+k] + (float)code * inv2;
        o[k] = fminf(fmaxf(y, 0.f), 10.f);
        lm = fmaxf(lm, o[k]);
    }
    float* dst = g_act5 + (img * 16 + pix) * 64 + ocg * 8;
    ((float4*)dst)[0] = make_float4(o[0], o[1], o[2], o[3]);
    ((float4*)dst)[1] = make_float4(o[4], o[5], o[6], o[7]);
    blockamax<8>(17, lm, redm, t);
}

// Final: quant(act5) -> mean(4x4) -> linear(64->10). 4 images / block.
__global__ void __launch_bounds__(256) k_final(float* __restrict__ out)
{
    __shared__ __align__(16) float sv[4][64];
    __shared__ __align__(16) float wls[640];
    const int t = threadIdx.x;
    const int li = t >> 6, sub = t & 63;
    const int img = blockIdx.x * 4 + li;
    const float m5 = ldmax(17);
    const float s5 = m5 > 0.f ? 127.f / m5 : 0.f;
    const float inv5 = s5 > 0.f ? 1.f / s5 : 0.f;
    for (int i = t; i < 640; i += 256) wls[i] = g_wlq[i];
    const float* a5 = g_act5 + img * 1024;
    int acc = 0;
    #pragma unroll
    for (int p = 0; p < 16; p++)
        acc += min(127, __float2int_rn(a5[p * 64 + sub] * s5));
    sv[li][sub] = (float)acc * inv5 * (1.f / 16.f);
    __syncthreads();
    if (t < 40) {
        int li3 = t / 10, o = t - li3 * 10;
        float r = g_blq[o];
        const float* svr = sv[li3];
        const float* wr = wls + o * 64;
        #pragma unroll 8
        for (int c = 0; c < 64; c++) r += svr[c] * wr[c];
        out[(blockIdx.x * 4 + li3) * 10 + o] = r;
    }
}

extern "C" void kernel_launch(void* const* d_in, const int* in_sizes, int n_in,
                              void* d_out, int out_size) {
    const float* x  = (const float*)d_in[0];
    const float* w1 = (const float*)d_in[1];  const float* b1 = (const float*)d_in[2];
    const float* w2 = (const float*)d_in[3];  const float* b2 = (const float*)d_in[4];
    const float* w3 = (const float*)d_in[5];  const float* b3 = (const float*)d_in[6];
    const float* w4 = (const float*)d_in[7];  const float* b4 = (const float*)d_in[8];
    const float* w5 = (const float*)d_in[9];  const float* b5 = (const float*)d_in[10];
    const float* wl = (const float*)d_in[11]; const float* bl = (const float*)d_in[12];

    k_reset<<<1, 32>>>();
    k_absmax<<<524, 256>>>((const float4*)x, w1, w2, w3, w4, w5, wl,
                           b1, b2, b3, b4, b5, bl);
    k_max1<<<514, 256>>>(x, w1, b1, w2, w3, w4, w5, wl, b2, b3, b4, b5, bl);
    k_stage12<<<B_IMG / 2, 512>>>(x);
    k_stage3<<<B_IMG, 256>>>();
    k_stage4<<<B_IMG / 4, 256>>>();
    k_stage5<<<B_IMG / 2, 256>>>();
    k_final<<<B_IMG / 4, 256>>>((float*)d_out);
}